// round 12
// baseline (speedup 1.0000x reference)
#include <cuda_runtime.h>
#include <cuda_bf16.h>
#include <cstdint>
#include <cstddef>

#define B_    4
#define S_    512
#define D_    768
#define H_    12
#define HD_   64
#define NRELV 101
#define EROWS 112
#define XN    (B_*S_*D_)
#define WN    (D_*D_)

#define BM    128
#define BN    128
#define BK    32
#define LDSB  40           // bf16 stride (80B) -> ldmatrix conflict-free
#define GSTAGE 40960       // bytes per oproj gemm stage

// qkv gemm (128x256 CTA tile, 3 stages)
#define QSTAGE 61440       // Xhi 10240 | Xlo 10240 | Whi 20480 | Wlo 20480
#define QSMEM  (3*QSTAGE)  // 184320

// ---------------- scratch ------------------------------------------------------
__device__ __nv_bfloat16 g_qkhi[(size_t)B_*H_*S_*128], g_qklo[(size_t)B_*H_*S_*128];
__device__ __nv_bfloat16 g_vhi[XN], g_vlo[XN];
__device__ __nv_bfloat16 g_xhi[3*XN], g_xlo[3*XN];
__device__ __nv_bfloat16 g_whi[4*WN], g_wlo[4*WN];
__device__ __nv_bfloat16 g_chi[XN], g_clo[XN];
__device__ __nv_bfloat16 g_ehi[EROWS*128], g_elo[EROWS*128];
__device__ float   g_bias[(size_t)B_*H_*S_*NRELV];
__device__ uint8_t g_rel8[(size_t)B_*S_*S_];
__device__ int     g_arc_is64;

// ---------------- helpers ------------------------------------------------------
__device__ __forceinline__ void split2(float a, float b, uint32_t& hi, uint32_t& lo)
{
    __nv_bfloat16 h0 = __float2bfloat16(a);
    __nv_bfloat16 h1 = __float2bfloat16(b);
    __nv_bfloat16 l0 = __float2bfloat16(a - __bfloat162float(h0));
    __nv_bfloat16 l1 = __float2bfloat16(b - __bfloat162float(h1));
    hi = (uint32_t)*(unsigned short*)&h0 | ((uint32_t)*(unsigned short*)&h1 << 16);
    lo = (uint32_t)*(unsigned short*)&l0 | ((uint32_t)*(unsigned short*)&l1 << 16);
}

__device__ __forceinline__ void ldsm_x4(uint32_t addr, uint32_t& r0, uint32_t& r1,
                                        uint32_t& r2, uint32_t& r3)
{
    asm volatile("ldmatrix.sync.aligned.m8n8.x4.shared.b16 {%0,%1,%2,%3}, [%4];"
                 : "=r"(r0), "=r"(r1), "=r"(r2), "=r"(r3) : "r"(addr));
}

__device__ __forceinline__ void ldsm_x2_trans(uint32_t addr, uint32_t& r0, uint32_t& r1)
{
    asm volatile("ldmatrix.sync.aligned.m8n8.x2.trans.shared.b16 {%0,%1}, [%2];"
                 : "=r"(r0), "=r"(r1) : "r"(addr));
}

__device__ __forceinline__ void mma16816(float* c, const uint32_t* a,
                                         uint32_t b0, uint32_t b1)
{
    asm volatile(
        "mma.sync.aligned.m16n8k16.row.col.f32.bf16.bf16.f32 "
        "{%0,%1,%2,%3}, {%4,%5,%6,%7}, {%8,%9}, {%0,%1,%2,%3};"
        : "+f"(c[0]), "+f"(c[1]), "+f"(c[2]), "+f"(c[3])
        : "r"(a[0]), "r"(a[1]), "r"(a[2]), "r"(a[3]), "r"(b0), "r"(b1));
}

__device__ __forceinline__ void cp16(uint32_t dst, const void* src)
{
    asm volatile("cp.async.ca.shared.global [%0], [%1], 16;" :: "r"(dst), "l"(src));
}

// ---------------- graph_arc dtype detection ------------------------------------
__global__ void detect_kernel(const int* __restrict__ arc32)
{
    __shared__ int cnt;
    if (threadIdx.x == 0) cnt = 0;
    __syncthreads();
    int local = 0;
    for (int i = threadIdx.x; i < 1024; i += blockDim.x)
        if (arc32[2*i + 1] != 0) local++;
    if (local) atomicAdd(&cnt, local);
    __syncthreads();
    if (threadIdx.x == 0) g_arc_is64 = (cnt == 0) ? 1 : 0;
}

// arc (int32 or int64) -> uint8 relation table
__global__ void __launch_bounds__(256)
rel8_kernel(const void* __restrict__ arc)
{
    const int is64 = g_arc_is64;
    const size_t i = ((size_t)blockIdx.x * 256 + threadIdx.x) * 4;
    if (i >= (size_t)B_*S_*S_) return;
    uchar4 r;
    if (is64) {
        const long long* a = (const long long*)arc + i;
        r = make_uchar4((uint8_t)a[0], (uint8_t)a[1], (uint8_t)a[2], (uint8_t)a[3]);
    } else {
        const int* a = (const int*)arc + i;
        r = make_uchar4((uint8_t)a[0], (uint8_t)a[1], (uint8_t)a[2], (uint8_t)a[3]);
    }
    *(uchar4*)&g_rel8[i] = r;
}

// ---------------- prepass: fp32 -> bf16 hi/lo split -----------------------------
struct SplitArgs {
    const float*   src[7];
    __nv_bfloat16* hi[7];
    __nv_bfloat16* lo[7];
    int            n[7];
};

__global__ void __launch_bounds__(256)
split_kernel(SplitArgs a)
{
    const int w = blockIdx.y;
    const int n = a.n[w];
    const int i = (blockIdx.x * 256 + threadIdx.x) * 4;
    if (i >= n) return;
    float4 v = *(const float4*)(a.src[w] + i);
    uint32_t h0, l0, h1, l1;
    split2(v.x, v.y, h0, l0);
    split2(v.z, v.w, h1, l1);
    *(uint2*)(a.hi[w] + i) = make_uint2(h0, h1);
    *(uint2*)(a.lo[w] + i) = make_uint2(l0, l1);
}

__global__ void __launch_bounds__(256)
ebuild_kernel(const float* __restrict__ Ek, const float* __restrict__ Eq)
{
    int idx = blockIdx.x * 256 + threadIdx.x;
    if (idx >= EROWS*128) return;
    int row = idx >> 7, col = idx & 127;
    float v = 0.f;
    if (row < NRELV) v = (col < 64) ? Ek[row*64 + col] : Eq[row*64 + col - 64];
    __nv_bfloat16 hv = __float2bfloat16(v);
    __nv_bfloat16 lv = __float2bfloat16(v - __bfloat162float(hv));
    g_ehi[idx] = hv;
    g_elo[idx] = lv;
}

// ---------------- QKV GEMM: 128x256 CTA, (64,64) warp tiles, 3-stage ------------
__global__ void __launch_bounds__(256, 1)
qkv_gemm_kernel(const float* __restrict__ bias0, const float* __restrict__ bias1,
                const float* __restrict__ bias2)
{
    extern __shared__ char gsm[];
    const uint32_t smemBase = (uint32_t)__cvta_generic_to_shared(gsm);

    const int z = blockIdx.z;
    const __nv_bfloat16* Xhi = g_xhi + (size_t)z*XN;
    const __nv_bfloat16* Xlo = g_xlo + (size_t)z*XN;
    const __nv_bfloat16* Whi = g_whi + (size_t)z*WN;
    const __nv_bfloat16* Wlo = g_wlo + (size_t)z*WN;
    const float* bias = (z == 0) ? bias0 : (z == 1) ? bias1 : bias2;

    const int tid  = threadIdx.x;
    const int lane = tid & 31;
    const int warp = tid >> 5;
    const int wm   = warp & 1;      // 2 m-warps (64 rows each)
    const int wn   = warp >> 1;     // 4 n-warps (64 cols each)
    const int m0   = blockIdx.y * 128;
    const int n0   = blockIdx.x * 256;

    float acc[4][8][4];
    #pragma unroll
    for (int mt = 0; mt < 4; mt++)
        #pragma unroll
        for (int nt = 0; nt < 8; nt++)
            #pragma unroll
            for (int j = 0; j < 4; j++) acc[mt][nt][j] = 0.f;

    const int mat = lane >> 3, mr = lane & 7;
    const uint32_t aOff = (uint32_t)((wm*64 + (mat & 1)*8 + mr)*80 + ((mat >> 1)*8)*2);
    const uint32_t bOff = 20480u + (uint32_t)((wn*64 + (mat >> 1)*8 + mr)*80 + ((mat & 1)*8)*2);

    // copy mapping: X 2 thr/row, W 1 thr/row
    const int xrow = tid >> 1;
    const int xq   = (tid & 1) * 2;
    const uint32_t xDst = (uint32_t)(xrow*80 + xq*16);
    const uint32_t wDst = 20480u + (uint32_t)(tid*80);

    #define QLOAD(stage, k0)                                                     \
    {                                                                            \
        const uint32_t sbl = smemBase + (uint32_t)((stage) * QSTAGE);            \
        const size_t xo = (size_t)(m0 + xrow)*D_ + (k0) + xq*8;                  \
        cp16(sbl + xDst,              Xhi + xo);                                 \
        cp16(sbl + xDst + 16,         Xhi + xo + 8);                             \
        cp16(sbl + 10240 + xDst,      Xlo + xo);                                 \
        cp16(sbl + 10240 + xDst + 16, Xlo + xo + 8);                             \
        const size_t wo = (size_t)(n0 + tid)*D_ + (k0);                          \
        _Pragma("unroll")                                                        \
        for (int u = 0; u < 4; u++) {                                            \
            cp16(sbl + wDst + u*16,         Whi + wo + u*8);                     \
            cp16(sbl + 20480 + wDst + u*16, Wlo + wo + u*8);                     \
        }                                                                        \
    }

    QLOAD(0, 0);
    asm volatile("cp.async.commit_group;");
    QLOAD(1, 32);
    asm volatile("cp.async.commit_group;");

    const int NK = D_ / BK;   // 24
    for (int kt = 0; kt < NK; kt++) {
        asm volatile("cp.async.wait_group 1;");
        __syncthreads();

        if (kt + 2 < NK) {
            QLOAD((kt + 2) % 3, (kt + 2) * BK);
        }
        asm volatile("cp.async.commit_group;");

        const uint32_t sb = smemBase + (uint32_t)((kt % 3) * QSTAGE);
        #pragma unroll
        for (int ks = 0; ks < 2; ks++) {
            const uint32_t ko = ks * 32;
            uint32_t ah[4][4], al[4][4];
            #pragma unroll
            for (int mt = 0; mt < 4; mt++) {
                const uint32_t mo = mt * 1280;
                ldsm_x4(sb + aOff + mo + ko,          ah[mt][0], ah[mt][1], ah[mt][2], ah[mt][3]);
                ldsm_x4(sb + aOff + 10240 + mo + ko,  al[mt][0], al[mt][1], al[mt][2], al[mt][3]);
            }
            #pragma unroll
            for (int pr = 0; pr < 4; pr++) {
                const uint32_t po = pr * 1280;
                uint32_t bh[4], bl[4];
                ldsm_x4(sb + bOff + po + ko,          bh[0], bh[1], bh[2], bh[3]);
                ldsm_x4(sb + bOff + 20480 + po + ko,  bl[0], bl[1], bl[2], bl[3]);
                #pragma unroll
                for (int h2 = 0; h2 < 2; h2++) {
                    const int nt = pr*2 + h2;
                    #pragma unroll
                    for (int mt = 0; mt < 4; mt++) {
                        mma16816(acc[mt][nt], ah[mt], bh[h2*2], bh[h2*2+1]);
                        mma16816(acc[mt][nt], ah[mt], bl[h2*2], bl[h2*2+1]);
                        mma16816(acc[mt][nt], al[mt], bh[h2*2], bh[h2*2+1]);
                    }
                }
            }
        }
    }
    #undef QLOAD

    // ---- epilogue: scatter to g_qk / g_v (split bf16) ----
    const int gid = lane >> 2, tig = lane & 3;
    #pragma unroll
    for (int mt = 0; mt < 4; mt++) {
        const int rbase = m0 + wm*64 + mt*16 + gid;
        #pragma unroll
        for (int nt = 0; nt < 8; nt++) {
            const int col = n0 + wn*64 + nt*8 + tig*2;
            const float b0v = bias[col], b1v = bias[col+1];
            float v00 = acc[mt][nt][0] + b0v;
            float v01 = acc[mt][nt][1] + b1v;
            float v10 = acc[mt][nt][2] + b0v;
            float v11 = acc[mt][nt][3] + b1v;
            const int hh = col >> 6, e = col & 63;
            #pragma unroll
            for (int half = 0; half < 2; half++) {
                const int r = rbase + half*8;
                const int b = r >> 9, s = r & (S_-1);
                const size_t rowb = (size_t)(b*H_ + hh)*S_ + s;
                const float va = half ? v10 : v00;
                const float vb = half ? v11 : v01;
                uint32_t hi, lo; split2(va, vb, hi, lo);
                if (z == 0) {
                    *(uint32_t*)&g_qkhi[rowb*128 + e] = hi;
                    *(uint32_t*)&g_qklo[rowb*128 + e] = lo;
                } else if (z == 1) {
                    *(uint32_t*)&g_qkhi[rowb*128 + 64 + e] = hi;
                    *(uint32_t*)&g_qklo[rowb*128 + 64 + e] = lo;
                } else {
                    *(uint32_t*)&g_vhi[rowb*64 + e] = hi;
                    *(uint32_t*)&g_vlo[rowb*64 + e] = lo;
                }
            }
        }
    }
}

// ---------------- out-proj GEMM (proven 2-stage, MODE 1 only) -------------------
__global__ void __launch_bounds__(256, 2)
oproj_gemm_kernel(const float* __restrict__ bias, float* __restrict__ out1)
{
    extern __shared__ char gsm[];
    const uint32_t smemBase = (uint32_t)__cvta_generic_to_shared(gsm);

    const __nv_bfloat16* Xhi = g_chi;
    const __nv_bfloat16* Xlo = g_clo;
    const __nv_bfloat16* Whi = g_whi + (size_t)3*WN;
    const __nv_bfloat16* Wlo = g_wlo + (size_t)3*WN;

    const int tid  = threadIdx.x;
    const int lane = tid & 31;
    const int warp = tid >> 5;
    const int wm   = warp & 3;
    const int wn   = warp >> 2;
    const int m0   = blockIdx.y * BM;
    const int n0   = blockIdx.x * BN;

    float acc[2][8][4];
    #pragma unroll
    for (int mt = 0; mt < 2; mt++)
        #pragma unroll
        for (int nt = 0; nt < 8; nt++)
            #pragma unroll
            for (int j = 0; j < 4; j++) acc[mt][nt][j] = 0.f;

    const int mat = lane >> 3, mr = lane & 7;
    const uint32_t aOffHi = (uint32_t)((wm*32 + (mat & 1)*8 + mr)*80 + ((mat >> 1)*8)*2);
    const uint32_t bOffHi = 20480u + (uint32_t)((wn*64 + (mat >> 1)*8 + mr)*80 + ((mat & 1)*8)*2);

    const int ldrow = tid >> 1;
    const int ldq   = (tid & 1) * 2;
    const uint32_t xDst = (uint32_t)(ldrow*80 + ldq*16);
    const uint32_t wDst = 20480u + xDst;

    #pragma unroll
    for (int u = 0; u < 2; u++) {
        const size_t xo = (size_t)(m0 + ldrow)*D_ + (ldq + u)*8;
        const size_t wo = (size_t)(n0 + ldrow)*D_ + (ldq + u)*8;
        cp16(smemBase + xDst + u*16,          Xhi + xo);
        cp16(smemBase + 10240 + xDst + u*16,  Xlo + xo);
        cp16(smemBase + wDst + u*16,          Whi + wo);
        cp16(smemBase + 10240 + wDst + u*16,  Wlo + wo);
    }
    asm volatile("cp.async.commit_group;");

    const int NK = D_ / BK;
    for (int kt = 0; kt < NK; kt++) {
        asm volatile("cp.async.wait_group 0;");
        __syncthreads();

        if (kt + 1 < NK) {
            const uint32_t sb2 = smemBase + (uint32_t)(((kt + 1) & 1) * GSTAGE);
            const int k0 = (kt + 1) * BK;
            #pragma unroll
            for (int u = 0; u < 2; u++) {
                const size_t xo = (size_t)(m0 + ldrow)*D_ + k0 + (ldq + u)*8;
                const size_t wo = (size_t)(n0 + ldrow)*D_ + k0 + (ldq + u)*8;
                cp16(sb2 + xDst + u*16,          Xhi + xo);
                cp16(sb2 + 10240 + xDst + u*16,  Xlo + xo);
                cp16(sb2 + wDst + u*16,          Whi + wo);
                cp16(sb2 + 10240 + wDst + u*16,  Wlo + wo);
            }
        }
        asm volatile("cp.async.commit_group;");

        const uint32_t sb = smemBase + (uint32_t)((kt & 1) * GSTAGE);
        #pragma unroll
        for (int ks = 0; ks < 2; ks++) {
            const uint32_t ko = ks * 32;
            uint32_t ah[2][4], al[2][4];
            #pragma unroll
            for (int mt = 0; mt < 2; mt++) {
                const uint32_t mo = mt * 1280;
                ldsm_x4(sb + aOffHi + mo + ko,          ah[mt][0], ah[mt][1], ah[mt][2], ah[mt][3]);
                ldsm_x4(sb + aOffHi + 10240 + mo + ko,  al[mt][0], al[mt][1], al[mt][2], al[mt][3]);
            }
            #pragma unroll
            for (int pr = 0; pr < 4; pr++) {
                const uint32_t po = pr * 1280;
                uint32_t bh[4], bl[4];
                ldsm_x4(sb + bOffHi + po + ko,          bh[0], bh[1], bh[2], bh[3]);
                ldsm_x4(sb + bOffHi + 10240 + po + ko,  bl[0], bl[1], bl[2], bl[3]);
                #pragma unroll
                for (int h2 = 0; h2 < 2; h2++) {
                    const int nt = pr*2 + h2;
                    #pragma unroll
                    for (int mt = 0; mt < 2; mt++) {
                        mma16816(acc[mt][nt], ah[mt], bh[h2*2], bh[h2*2+1]);
                        mma16816(acc[mt][nt], ah[mt], bl[h2*2], bl[h2*2+1]);
                        mma16816(acc[mt][nt], al[mt], bh[h2*2], bh[h2*2+1]);
                    }
                }
            }
        }
    }

    const int gid = lane >> 2, tig = lane & 3;
    #pragma unroll
    for (int mt = 0; mt < 2; mt++) {
        const int rbase = m0 + wm*32 + mt*16 + gid;
        #pragma unroll
        for (int nt = 0; nt < 8; nt++) {
            const int col = n0 + wn*64 + nt*8 + tig*2;
            const float b0v = bias[col], b1v = bias[col+1];
            out1[(size_t)rbase*D_ + col]       = acc[mt][nt][0] + b0v;
            out1[(size_t)rbase*D_ + col + 1]   = acc[mt][nt][1] + b1v;
            out1[(size_t)(rbase+8)*D_ + col]   = acc[mt][nt][2] + b0v;
            out1[(size_t)(rbase+8)*D_ + col+1] = acc[mt][nt][3] + b1v;
        }
    }
}

// ---------------- bias table via tensor cores -----------------------------------
__global__ void __launch_bounds__(256, 1)
bias_mma_kernel()
{
    __shared__ __nv_bfloat16 sAhi[128][LDSB], sAlo[128][LDSB];
    __shared__ __nv_bfloat16 sBhi[EROWS][LDSB], sBlo[EROWS][LDSB];

    const int rt = blockIdx.x;
    const int h  = blockIdx.y, b = blockIdx.z;
    const size_t bh = (size_t)b*H_ + h;
    const size_t abase = (bh*S_ + rt*128) * 128;

    const int tid  = threadIdx.x;
    const int lane = tid & 31;
    const int warp = tid >> 5;

    float acc[14][4];
    #pragma unroll
    for (int nt = 0; nt < 14; nt++)
        #pragma unroll
        for (int j = 0; j < 4; j++) acc[nt][j] = 0.f;

    const int mat = lane >> 3, mr = lane & 7;
    const int a_row = (mat & 1) * 8 + mr;
    const int a_k   = (mat >> 1) * 8;
    const uint32_t aHi = (uint32_t)__cvta_generic_to_shared(&sAhi[warp*16 + a_row][a_k]);
    const uint32_t aLo = (uint32_t)__cvta_generic_to_shared(&sAlo[warp*16 + a_row][a_k]);
    const int b_row = (mat >> 1) * 8 + mr;
    const int b_k   = (mat & 1) * 8;
    const uint32_t bHi = (uint32_t)__cvta_generic_to_shared(&sBhi[b_row][b_k]);
    const uint32_t bLo = (uint32_t)__cvta_generic_to_shared(&sBlo[b_row][b_k]);

    for (int k0 = 0; k0 < 128; k0 += BK) {
        {
            const int arow = tid >> 1;
            const int acol = (tid & 1) * 16;
            const size_t src = abase + (size_t)arow*128 + k0 + acol;
            uint4 h0 = *(const uint4*)(g_qkhi + src);
            uint4 h1 = *(const uint4*)(g_qkhi + src + 8);
            uint4 l0 = *(const uint4*)(g_qklo + src);
            uint4 l1 = *(const uint4*)(g_qklo + src + 8);
            __syncthreads();
            *(uint4*)&sAhi[arow][acol]     = h0;
            *(uint4*)&sAhi[arow][acol + 8] = h1;
            *(uint4*)&sAlo[arow][acol]     = l0;
            *(uint4*)&sAlo[arow][acol + 8] = l1;
        }
        if (tid < EROWS*2) {
            const int brow = tid >> 1;
            const int bcol = (tid & 1) * 16;
            const size_t src = (size_t)brow*128 + k0 + bcol;
            *(uint4*)&sBhi[brow][bcol]     = *(const uint4*)(g_ehi + src);
            *(uint4*)&sBhi[brow][bcol + 8] = *(const uint4*)(g_ehi + src + 8);
            *(uint4*)&sBlo[brow][bcol]     = *(const uint4*)(g_elo + src);
            *(uint4*)&sBlo[brow][bcol + 8] = *(const uint4*)(g_elo + src + 8);
        }
        __syncthreads();

        #pragma unroll
        for (int ks = 0; ks < 2; ks++) {
            const uint32_t ko = ks * 32;
            uint32_t ah[4], al[4];
            ldsm_x4(aHi + ko, ah[0], ah[1], ah[2], ah[3]);
            ldsm_x4(aLo + ko, al[0], al[1], al[2], al[3]);
            #pragma unroll
            for (int pr = 0; pr < 7; pr++) {
                const uint32_t po = pr * (16 * LDSB * 2);
                uint32_t bhf[4], blf[4];
                ldsm_x4(bHi + po + ko, bhf[0], bhf[1], bhf[2], bhf[3]);
                ldsm_x4(bLo + po + ko, blf[0], blf[1], blf[2], blf[3]);
                #pragma unroll
                for (int h2 = 0; h2 < 2; h2++) {
                    const int nt = pr*2 + h2;
                    mma16816(acc[nt], ah, bhf[h2*2], bhf[h2*2+1]);
                    mma16816(acc[nt], ah, blf[h2*2], blf[h2*2+1]);
                    mma16816(acc[nt], al, bhf[h2*2], bhf[h2*2+1]);
                }
            }
        }
        __syncthreads();
    }

    const int gid = lane >> 2, tig = lane & 3;
    const int row0 = rt*128 + warp*16 + gid;
    #pragma unroll
    for (int nt = 0; nt < 14; nt++) {
        const int col = nt*8 + tig*2;
        #pragma unroll
        for (int half = 0; half < 2; half++) {
            const int row = row0 + half*8;
            const size_t o = (bh*S_ + row)*NRELV;
            const float v0 = acc[nt][half*2];
            const float v1 = acc[nt][half*2+1];
            if (col < NRELV)     g_bias[o + col]     = v0;
            if (col + 1 < NRELV) g_bias[o + col + 1] = v1;
        }
    }
}

// ---------------- fused attention: QT=32, cp.async KV, fused scalar phases ------
#define QT    32
#define SSTR  520
#define OFF_SS    0
#define KVHI(bf)  (66560u + (uint32_t)(bf)*36864u)
#define KVLO(bf)  (84992u + (uint32_t)(bf)*36864u)
#define OFF_SB    140288
#define OFF_SW    153216
#define OFF_SZ    166144
#define OFF_MASK  166272
#define OFF_EV    168320
#define SMEM_ATTN 194176

__global__ void __launch_bounds__(512, 1)
attn_kernel(const int* __restrict__ mask, const float* __restrict__ Ev)
{
    extern __shared__ char smraw[];
    const uint32_t sbase = (uint32_t)__cvta_generic_to_shared(smraw);
    float* sS    = (float*)(smraw + OFF_SS);
    float* sEv   = (float*)(smraw + OFF_EV);
    float* sB    = (float*)(smraw + OFF_SB);
    float* sW    = (float*)(smraw + OFF_SW);
    float* sZ    = (float*)(smraw + OFF_SZ);
    int*   sMask = (int*)  (smraw + OFF_MASK);

    const int qt = blockIdx.x, h = blockIdx.y, b = blockIdx.z;
    const int i0 = qt * QT;
    const int tid  = threadIdx.x;
    const int lane = tid & 31;
    const int warp = tid >> 5;
    const int mt   = warp >> 3;
    const int wj   = warp & 7;
    const size_t bh    = (size_t)b*H_ + h;
    const size_t qrow0 = bh*S_ + i0;
    const size_t krow0 = bh*S_;
    const size_t vbase = bh*S_*HD_;

    const int copyrow = tid >> 2;
    const int cq      = (tid & 3) * 16;
    const uint32_t dOff = (uint32_t)(copyrow*144 + cq*2);

    {
        const size_t src = (krow0 + copyrow)*128 + 64 + cq;
        cp16(sbase + KVHI(0) + dOff,      g_qkhi + src);
        cp16(sbase + KVHI(0) + dOff + 16, g_qkhi + src + 8);
        cp16(sbase + KVLO(0) + dOff,      g_qklo + src);
        cp16(sbase + KVLO(0) + dOff + 16, g_qklo + src + 8);
    }
    asm volatile("cp.async.commit_group;");

    for (int i = tid; i < QT*NRELV; i += 512) {
        sB[i] = g_bias[qrow0*NRELV + i];
        sW[i] = 0.f;
    }
    for (int i = tid; i < S_; i += 512) sMask[i] = mask[b*S_ + i];

    uint32_t qah[4][4], qal[4][4];
    {
        const int qr = lane >> 2;
        const int qc = (lane & 3) * 2;
        const size_t qm = qrow0 + mt*16;
        #pragma unroll
        for (int kk = 0; kk < 4; kk++) {
            const size_t r0o = (qm + qr)*128     + kk*16 + qc;
            const size_t r1o = (qm + qr + 8)*128 + kk*16 + qc;
            qah[kk][0] = *(const uint32_t*)&g_qkhi[r0o];
            qah[kk][1] = *(const uint32_t*)&g_qkhi[r1o];
            qah[kk][2] = *(const uint32_t*)&g_qkhi[r0o + 8];
            qah[kk][3] = *(const uint32_t*)&g_qkhi[r1o + 8];
            qal[kk][0] = *(const uint32_t*)&g_qklo[r0o];
            qal[kk][1] = *(const uint32_t*)&g_qklo[r1o];
            qal[kk][2] = *(const uint32_t*)&g_qklo[r0o + 8];
            qal[kk][3] = *(const uint32_t*)&g_qklo[r1o + 8];
        }
    }
    __syncthreads();

    const uint32_t bfragOff =
        (uint32_t)((wj*16 + ((lane >> 4) & 1)*8 + (lane & 7))*144 + ((lane >> 3) & 1)*16);

    for (int jt = 0; jt < 4; jt++) {
        if (jt < 3) {
            const int nb = (jt + 1) & 1;
            const size_t src = (krow0 + (jt+1)*128 + copyrow)*128 + 64 + cq;
            cp16(sbase + KVHI(nb) + dOff,      g_qkhi + src);
            cp16(sbase + KVHI(nb) + dOff + 16, g_qkhi + src + 8);
            cp16(sbase + KVLO(nb) + dOff,      g_qklo + src);
            cp16(sbase + KVLO(nb) + dOff + 16, g_qklo + src + 8);
        } else {
            const size_t src = vbase + (size_t)copyrow*HD_ + cq;
            cp16(sbase + KVHI(0) + dOff,      g_vhi + src);
            cp16(sbase + KVHI(0) + dOff + 16, g_vhi + src + 8);
            cp16(sbase + KVLO(0) + dOff,      g_vlo + src);
            cp16(sbase + KVLO(0) + dOff + 16, g_vlo + src + 8);
        }
        asm volatile("cp.async.commit_group;");
        asm volatile("cp.async.wait_group 1;");
        __syncthreads();

        const uint32_t khA = sbase + KVHI(jt & 1) + bfragOff;
        const uint32_t klA = sbase + KVLO(jt & 1) + bfragOff;
        const int j0 = jt * 128;

        float c[2][4] = {{0,0,0,0},{0,0,0,0}};
        #pragma unroll
        for (int kk = 0; kk < 4; kk++) {
            uint32_t bhf[4], blf[4];
            ldsm_x4(khA + kk*32, bhf[0], bhf[1], bhf[2], bhf[3]);
            ldsm_x4(klA + kk*32, blf[0], blf[1], blf[2], blf[3]);
            mma16816(c[0], qah[kk], bhf[0], bhf[1]);
            mma16816(c[0], qah[kk], blf[0], blf[1]);
            mma16816(c[0], qal[kk], bhf[0], bhf[1]);
            mma16816(c[1], qah[kk], bhf[2], bhf[3]);
            mma16816(c[1], qah[kk], blf[2], blf[3]);
            mma16816(c[1], qal[kk], bhf[2], bhf[3]);
        }
        #pragma unroll
        for (int nt = 0; nt < 2; nt++) {
            const int col = j0 + wj*16 + nt*8 + 2*(lane & 3);
            const int r   = mt*16 + (lane >> 2);
            *(float2*)&sS[r*SSTR + col]     = make_float2(c[nt][0], c[nt][1]);
            *(float2*)&sS[(r+8)*SSTR + col] = make_float2(c[nt][2], c[nt][3]);
        }
        __syncthreads();
    }

    {
        const size_t src = vbase + (size_t)(128 + copyrow)*HD_ + cq;
        cp16(sbase + KVHI(1) + dOff,      g_vhi + src);
        cp16(sbase + KVHI(1) + dOff + 16, g_vhi + src + 8);
        cp16(sbase + KVLO(1) + dOff,      g_vlo + src);
        cp16(sbase + KVLO(1) + dOff + 16, g_vlo + src + 8);
    }
    asm volatile("cp.async.commit_group;");

    for (int i = tid; i < NRELV*HD_; i += 512) sEv[i] = Ev[i];

    const size_t arcbase = ((size_t)b*S_ + i0)*S_;
    {
        uchar4 relreg[2][4];
        #pragma unroll
        for (int rr = 0; rr < 2; rr++) {
            const int row = warp*2 + rr;
            const float* brow = &sB[row*NRELV];
            float m = -3.4e38f;
            #pragma unroll
            for (int it = 0; it < 4; it++) {
                const int j = it*128 + lane*4;
                uchar4 r4 = *(const uchar4*)&g_rel8[arcbase + (size_t)row*S_ + j];
                relreg[rr][it] = r4;
                float4 s4 = *(float4*)&sS[row*SSTR + j];
                s4.x = (s4.x + brow[r4.x]) * 0.125f; if (sMask[j]     == 0) s4.x = -1e30f;
                s4.y = (s4.y + brow[r4.y]) * 0.125f; if (sMask[j + 1] == 0) s4.y = -1e30f;
                s4.z = (s4.z + brow[r4.z]) * 0.125f; if (sMask[j + 2] == 0) s4.z = -1e30f;
                s4.w = (s4.w + brow[r4.w]) * 0.125f; if (sMask[j + 3] == 0) s4.w = -1e30f;
                *(float4*)&sS[row*SSTR + j] = s4;
                m = fmaxf(m, fmaxf(fmaxf(s4.x, s4.y), fmaxf(s4.z, s4.w)));
            }
            #pragma unroll
            for (int o = 16; o; o >>= 1) m = fmaxf(m, __shfl_xor_sync(0xffffffffu, m, o));

            float z = 0.f;
            float* wrow = &sW[row*NRELV];
            #pragma unroll
            for (int it = 0; it < 4; it++) {
                const int j = it*128 + lane*4;
                float4 s4 = *(float4*)&sS[row*SSTR + j];
                float4 p4;
                p4.x = __expf(s4.x - m);
                p4.y = __expf(s4.y - m);
                p4.z = __expf(s4.z - m);
                p4.w = __expf(s4.w - m);
                *(float4*)&sS[row*SSTR + j] = p4;
                z += p4.x + p4.y + p4.z + p4.w;
                uchar4 r4 = relreg[rr][it];
                atomicAdd(&wrow[r4.x], p4.x);
                atomicAdd(&wrow[r4.y], p4.y);
                atomicAdd(&wrow[r4.z], p4.z);
                atomicAdd(&wrow[r4.w], p4.w);
            }
            #pragma unroll
            for (int o = 16; o; o >>= 1) z += __shfl_xor_sync(0xffffffffu, z, o);
            if (lane == 0) sZ[row] = z;
        }
    }
    __syncthreads();

    float c2[8][4];
    #pragma unroll
    for (int nt = 0; nt < 8; nt++)
        #pragma unroll
        for (int j = 0; j < 4; j++) c2[nt][j] = 0.f;

    for (int jt = 0; jt < 4; jt++) {
        if (jt < 3) { asm volatile("cp.async.wait_group 1;"); }
        else        { asm volatile("cp.async.wait_group 0;"); }
        __syncthreads();

        const uint32_t vh = sbase + KVHI(jt & 1);
        const uint32_t vl = sbase + KVLO(jt & 1);
        const int jb = jt*128 + wj*16;
        uint32_t pah[4], pal[4];
        {
            const int pr = mt*16 + (lane >> 2);
            const int pc = (lane & 3) * 2;
            float2 x0 = *(float2*)&sS[pr*SSTR     + jb + pc];
            float2 x1 = *(float2*)&sS[(pr+8)*SSTR + jb + pc];
            float2 x2 = *(float2*)&sS[pr*SSTR     + jb + pc + 8];
            float2 x3 = *(float2*)&sS[(pr+8)*SSTR + jb + pc + 8];
            split2(x0.x, x0.y, pah[0], pal[0]);
            split2(x1.x, x1.y, pah[1], pal[1]);
            split2(x2.x, x2.y, pah[2], pal[2]);
            split2(x3.x, x3.y, pah[3], pal[3]);
        }
        const uint32_t rowoff = (uint32_t)(wj*16 + (lane & 15)) * 144;
        #pragma unroll
        for (int nt = 0; nt < 8; nt++) {
            uint32_t bh0, bh1, bl0, bl1;
            ldsm_x2_trans(vh + rowoff + nt*16, bh0, bh1);
            ldsm_x2_trans(vl + rowoff + nt*16, bl0, bl1);
            mma16816(c2[nt], pah, bh0, bh1);
            mma16816(c2[nt], pah, bl0, bl1);
            mma16816(c2[nt], pal, bh0, bh1);
        }
        __syncthreads();

        if (jt + 2 < 4) {
            const int nb = jt & 1;
            const size_t src = vbase + (size_t)((jt+2)*128 + copyrow)*HD_ + cq;
            cp16(sbase + KVHI(nb) + dOff,      g_vhi + src);
            cp16(sbase + KVHI(nb) + dOff + 16, g_vhi + src + 8);
            cp16(sbase + KVLO(nb) + dOff,      g_vlo + src);
            cp16(sbase + KVLO(nb) + dOff + 16, g_vlo + src + 8);
            asm volatile("cp.async.commit_group;");
        }
    }

    {
        float* red = sS;
        const int r = lane >> 2;
        #pragma unroll
        for (int nt = 0; nt < 8; nt++) {
            const int col = nt*8 + 2*(lane & 3);
            red[warp*1024 + r*64 + col]       = c2[nt][0];
            red[warp*1024 + r*64 + col + 1]   = c2[nt][1];
            red[warp*1024 + (r+8)*64 + col]   = c2[nt][2];
            red[warp*1024 + (r+8)*64 + col+1] = c2[nt][3];
        }
    }
    __syncthreads();

    {
        const int row = tid >> 4;
        const int e0  = (tid & 15) * 4;
        const int rmt = row >> 4, rl = row & 15;
        float4 acc = make_float4(0,0,0,0);
        #pragma unroll
        for (int w = 0; w < 8; w++) {
            float4 p = *(float4*)&sS[(rmt*8 + w)*1024 + rl*64 + e0];
            acc.x += p.x; acc.y += p.y; acc.z += p.z; acc.w += p.w;
        }
        const float* wrow = &sW[row*NRELV];
        for (int rel = 0; rel < NRELV; rel++) {
            float wv = wrow[rel];
            float4 ev = *(float4*)&sEv[rel*64 + e0];
            acc.x += wv*ev.x; acc.y += wv*ev.y; acc.z += wv*ev.z; acc.w += wv*ev.w;
        }
        const float rz = 1.f / sZ[row];
        acc.x *= rz; acc.y *= rz; acc.z *= rz; acc.w *= rz;

        uint32_t h0, l0, h1, l1;
        split2(acc.x, acc.y, h0, l0);
        split2(acc.z, acc.w, h1, l1);
        const size_t o = ((size_t)(b*S_ + i0 + row))*D_ + h*HD_ + e0;
        *(uint2*)&g_chi[o] = make_uint2(h0, h1);
        *(uint2*)&g_clo[o] = make_uint2(l0, l1);
    }
}

// ---------------- launch --------------------------------------------------------
extern "C" void kernel_launch(void* const* d_in, const int* in_sizes, int n_in,
                              void* d_out, int out_size)
{
    (void)in_sizes; (void)n_in; (void)out_size;
    const float* query = (const float*)d_in[0];
    const float* key_  = (const float*)d_in[1];
    const float* value = (const float*)d_in[2];
    const int*   mask  = (const int*)d_in[3];
    const void*  arc   = d_in[4];
    const float* bq = (const float*)d_in[6];
    const float* bk = (const float*)d_in[8];
    const float* bv = (const float*)d_in[10];
    const float* bo = (const float*)d_in[12];
    const float* Ek = (const float*)d_in[13];
    const float* Eq = (const float*)d_in[14];
    const float* Ev = (const float*)d_in[15];
    float* out = (float*)d_out;

    cudaFuncSetAttribute(attn_kernel, cudaFuncAttributeMaxDynamicSharedMemorySize, SMEM_ATTN);
    cudaFuncSetAttribute(qkv_gemm_kernel, cudaFuncAttributeMaxDynamicSharedMemorySize, QSMEM);
    cudaFuncSetAttribute(oproj_gemm_kernel, cudaFuncAttributeMaxDynamicSharedMemorySize, 2*GSTAGE);

    __nv_bfloat16 *xhi, *xlo, *whi, *wlo;
    cudaGetSymbolAddress((void**)&xhi, g_xhi);
    cudaGetSymbolAddress((void**)&xlo, g_xlo);
    cudaGetSymbolAddress((void**)&whi, g_whi);
    cudaGetSymbolAddress((void**)&wlo, g_wlo);

    detect_kernel<<<1, 256>>>((const int*)arc);
    rel8_kernel<<<((B_*S_*S_/4) + 255)/256, 256>>>(arc);

    SplitArgs sa;
    const float* srcs[7] = {query, key_, value,
                            (const float*)d_in[5], (const float*)d_in[7],
                            (const float*)d_in[9], (const float*)d_in[11]};
    for (int i = 0; i < 7; i++) {
        sa.src[i] = srcs[i];
        if (i < 3) {
            sa.hi[i] = xhi + (size_t)i*XN;
            sa.lo[i] = xlo + (size_t)i*XN;
            sa.n[i]  = XN;
        } else {
            sa.hi[i] = whi + (size_t)(i-3)*WN;
            sa.lo[i] = wlo + (size_t)(i-3)*WN;
            sa.n[i]  = WN;
        }
    }
    split_kernel<<<dim3((XN/4 + 255)/256, 7), 256>>>(sa);
    ebuild_kernel<<<(EROWS*128 + 255)/256, 256>>>(Ek, Eq);

    dim3 qkvGrid(D_/256, (B_*S_)/128, 3);   // (3, 16, 3) = 144 CTAs
    qkv_gemm_kernel<<<qkvGrid, 256, QSMEM>>>(bq, bk, bv);

    bias_mma_kernel<<<dim3(4, H_, B_), 256>>>();
    attn_kernel<<<dim3(S_/QT, H_, B_), 512, SMEM_ATTN>>>(mask, Ev);

    dim3 oGrid(D_/BN, (B_*S_)/BM, 1);       // (6, 16)
    oproj_gemm_kernel<<<oGrid, 256, 2*GSTAGE>>>(bo, out);
}

// round 13
// speedup vs baseline: 1.0410x; 1.0410x over previous
#include <cuda_runtime.h>
#include <cuda_bf16.h>
#include <cstdint>
#include <cstddef>

#define B_    4
#define S_    512
#define D_    768
#define H_    12
#define HD_   64
#define NRELV 101
#define EROWS 112
#define XN    (B_*S_*D_)
#define WN    (D_*D_)

#define BM    128
#define BN    128
#define BK    32
#define LDSB  40           // bf16 stride (80B) -> ldmatrix conflict-free
#define GSTAGE 40960       // bytes per gemm pipeline stage

// ---------------- scratch ------------------------------------------------------
__device__ __nv_bfloat16 g_qkhi[(size_t)B_*H_*S_*128], g_qklo[(size_t)B_*H_*S_*128];
__device__ __nv_bfloat16 g_vhi[XN], g_vlo[XN];
__device__ __nv_bfloat16 g_xhi[3*XN], g_xlo[3*XN];
__device__ __nv_bfloat16 g_whi[4*WN], g_wlo[4*WN];
__device__ __nv_bfloat16 g_chi[XN], g_clo[XN];
__device__ __nv_bfloat16 g_ehi[EROWS*128], g_elo[EROWS*128];
__device__ float   g_bias[(size_t)B_*H_*S_*NRELV];
__device__ uint8_t g_rel8[(size_t)B_*S_*S_];
__device__ int     g_arc_is64;

// ---------------- helpers ------------------------------------------------------
__device__ __forceinline__ void split2(float a, float b, uint32_t& hi, uint32_t& lo)
{
    __nv_bfloat16 h0 = __float2bfloat16(a);
    __nv_bfloat16 h1 = __float2bfloat16(b);
    __nv_bfloat16 l0 = __float2bfloat16(a - __bfloat162float(h0));
    __nv_bfloat16 l1 = __float2bfloat16(b - __bfloat162float(h1));
    hi = (uint32_t)*(unsigned short*)&h0 | ((uint32_t)*(unsigned short*)&h1 << 16);
    lo = (uint32_t)*(unsigned short*)&l0 | ((uint32_t)*(unsigned short*)&l1 << 16);
}

__device__ __forceinline__ void ldsm_x4(uint32_t addr, uint32_t& r0, uint32_t& r1,
                                        uint32_t& r2, uint32_t& r3)
{
    asm volatile("ldmatrix.sync.aligned.m8n8.x4.shared.b16 {%0,%1,%2,%3}, [%4];"
                 : "=r"(r0), "=r"(r1), "=r"(r2), "=r"(r3) : "r"(addr));
}

__device__ __forceinline__ void ldsm_x2_trans(uint32_t addr, uint32_t& r0, uint32_t& r1)
{
    asm volatile("ldmatrix.sync.aligned.m8n8.x2.trans.shared.b16 {%0,%1}, [%2];"
                 : "=r"(r0), "=r"(r1) : "r"(addr));
}

__device__ __forceinline__ void mma16816(float* c, const uint32_t* a,
                                         uint32_t b0, uint32_t b1)
{
    asm volatile(
        "mma.sync.aligned.m16n8k16.row.col.f32.bf16.bf16.f32 "
        "{%0,%1,%2,%3}, {%4,%5,%6,%7}, {%8,%9}, {%0,%1,%2,%3};"
        : "+f"(c[0]), "+f"(c[1]), "+f"(c[2]), "+f"(c[3])
        : "r"(a[0]), "r"(a[1]), "r"(a[2]), "r"(a[3]), "r"(b0), "r"(b1));
}

__device__ __forceinline__ void cp16(uint32_t dst, const void* src)
{
    asm volatile("cp.async.ca.shared.global [%0], [%1], 16;" :: "r"(dst), "l"(src));
}

// ---------------- graph_arc dtype detection ------------------------------------
__global__ void detect_kernel(const int* __restrict__ arc32)
{
    __shared__ int cnt;
    if (threadIdx.x == 0) cnt = 0;
    __syncthreads();
    int local = 0;
    for (int i = threadIdx.x; i < 1024; i += blockDim.x)
        if (arc32[2*i + 1] != 0) local++;
    if (local) atomicAdd(&cnt, local);
    __syncthreads();
    if (threadIdx.x == 0) g_arc_is64 = (cnt == 0) ? 1 : 0;
}

// ---------------- merged prepass: splits (y=0..6), ebuild (y=7), rel8 (y=8) -----
struct PrepArgs {
    const float*   src[7];
    __nv_bfloat16* hi[7];
    __nv_bfloat16* lo[7];
    int            n[7];
    const float*   Ek;
    const float*   Eq;
    const void*    arc;
};

__global__ void __launch_bounds__(256)
prep_kernel(PrepArgs a)
{
    const int w = blockIdx.y;
    const int t = blockIdx.x * 256 + threadIdx.x;

    if (w < 7) {
        const int i = t * 4;
        if (i >= a.n[w]) return;
        float4 v = *(const float4*)(a.src[w] + i);
        uint32_t h0, l0, h1, l1;
        split2(v.x, v.y, h0, l0);
        split2(v.z, v.w, h1, l1);
        *(uint2*)(a.hi[w] + i) = make_uint2(h0, h1);
        *(uint2*)(a.lo[w] + i) = make_uint2(l0, l1);
    } else if (w == 7) {
        if (t >= EROWS*128) return;
        int row = t >> 7, col = t & 127;
        float v = 0.f;
        if (row < NRELV) v = (col < 64) ? a.Ek[row*64 + col] : a.Eq[row*64 + col - 64];
        __nv_bfloat16 hv = __float2bfloat16(v);
        __nv_bfloat16 lv = __float2bfloat16(v - __bfloat162float(hv));
        g_ehi[t] = hv;
        g_elo[t] = lv;
    } else {
        const size_t i = (size_t)t * 4;
        if (i >= (size_t)B_*S_*S_) return;
        uchar4 r;
        if (g_arc_is64) {
            const long long* p = (const long long*)a.arc + i;
            r = make_uchar4((uint8_t)p[0], (uint8_t)p[1], (uint8_t)p[2], (uint8_t)p[3]);
        } else {
            const int* p = (const int*)a.arc + i;
            r = make_uchar4((uint8_t)p[0], (uint8_t)p[1], (uint8_t)p[2], (uint8_t)p[3]);
        }
        *(uchar4*)&g_rel8[i] = r;
    }
}

// ---------------- tensor-core GEMM, cp.async 2-stage pipeline -------------------
template<int MODE>
__global__ void __launch_bounds__(256, 2)
mma_gemm_kernel(const float* __restrict__ bias0, const float* __restrict__ bias1,
                const float* __restrict__ bias2, float* __restrict__ out1)
{
    extern __shared__ char gsm[];
    const uint32_t smemBase = (uint32_t)__cvta_generic_to_shared(gsm);

    const int z = (MODE == 0) ? blockIdx.z : 0;
    const __nv_bfloat16 *Xhi, *Xlo, *Whi, *Wlo;
    const float* bias;
    if (MODE == 0) {
        Xhi = g_xhi + (size_t)z*XN;  Xlo = g_xlo + (size_t)z*XN;
        Whi = g_whi + (size_t)z*WN;  Wlo = g_wlo + (size_t)z*WN;
        bias = (z == 0) ? bias0 : (z == 1) ? bias1 : bias2;
    } else {
        Xhi = g_chi;  Xlo = g_clo;
        Whi = g_whi + (size_t)3*WN;  Wlo = g_wlo + (size_t)3*WN;
        bias = bias0;
    }

    const int tid  = threadIdx.x;
    const int lane = tid & 31;
    const int warp = tid >> 5;
    const int wm   = warp & 3;
    const int wn   = warp >> 2;
    const int m0   = blockIdx.y * BM;
    const int n0   = blockIdx.x * BN;

    float acc[2][8][4];
    #pragma unroll
    for (int mt = 0; mt < 2; mt++)
        #pragma unroll
        for (int nt = 0; nt < 8; nt++)
            #pragma unroll
            for (int j = 0; j < 4; j++) acc[mt][nt][j] = 0.f;

    const int mat = lane >> 3, mr = lane & 7;
    const uint32_t aOffHi = (uint32_t)((wm*32 + (mat & 1)*8 + mr)*80 + ((mat >> 1)*8)*2);
    const uint32_t bOffHi = 20480u + (uint32_t)((wn*64 + (mat >> 1)*8 + mr)*80 + ((mat & 1)*8)*2);

    const int ldrow = tid >> 1;
    const int ldq   = (tid & 1) * 2;
    const uint32_t xDst = (uint32_t)(ldrow*80 + ldq*16);
    const uint32_t wDst = 20480u + xDst;

    #pragma unroll
    for (int u = 0; u < 2; u++) {
        const size_t xo = (size_t)(m0 + ldrow)*D_ + (ldq + u)*8;
        const size_t wo = (size_t)(n0 + ldrow)*D_ + (ldq + u)*8;
        cp16(smemBase + xDst + u*16,          Xhi + xo);
        cp16(smemBase + 10240 + xDst + u*16,  Xlo + xo);
        cp16(smemBase + wDst + u*16,          Whi + wo);
        cp16(smemBase + 10240 + wDst + u*16,  Wlo + wo);
    }
    asm volatile("cp.async.commit_group;");

    const int NK = D_ / BK;
    for (int kt = 0; kt < NK; kt++) {
        asm volatile("cp.async.wait_group 0;");
        __syncthreads();

        if (kt + 1 < NK) {
            const uint32_t sb2 = smemBase + (uint32_t)(((kt + 1) & 1) * GSTAGE);
            const int k0 = (kt + 1) * BK;
            #pragma unroll
            for (int u = 0; u < 2; u++) {
                const size_t xo = (size_t)(m0 + ldrow)*D_ + k0 + (ldq + u)*8;
                const size_t wo = (size_t)(n0 + ldrow)*D_ + k0 + (ldq + u)*8;
                cp16(sb2 + xDst + u*16,          Xhi + xo);
                cp16(sb2 + 10240 + xDst + u*16,  Xlo + xo);
                cp16(sb2 + wDst + u*16,          Whi + wo);
                cp16(sb2 + 10240 + wDst + u*16,  Wlo + wo);
            }
        }
        asm volatile("cp.async.commit_group;");

        const uint32_t sb = smemBase + (uint32_t)((kt & 1) * GSTAGE);
        #pragma unroll
        for (int ks = 0; ks < 2; ks++) {
            const uint32_t ko = ks * 32;
            uint32_t ah[2][4], al[2][4];
            #pragma unroll
            for (int mt = 0; mt < 2; mt++) {
                const uint32_t mo = mt * 1280;
                ldsm_x4(sb + aOffHi + mo + ko,          ah[mt][0], ah[mt][1], ah[mt][2], ah[mt][3]);
                ldsm_x4(sb + aOffHi + 10240 + mo + ko,  al[mt][0], al[mt][1], al[mt][2], al[mt][3]);
            }
            #pragma unroll
            for (int pr = 0; pr < 4; pr++) {
                const uint32_t po = pr * 1280;
                uint32_t bh[4], bl[4];
                ldsm_x4(sb + bOffHi + po + ko,          bh[0], bh[1], bh[2], bh[3]);
                ldsm_x4(sb + bOffHi + 10240 + po + ko,  bl[0], bl[1], bl[2], bl[3]);
                #pragma unroll
                for (int h2 = 0; h2 < 2; h2++) {
                    const int nt = pr*2 + h2;
                    #pragma unroll
                    for (int mt = 0; mt < 2; mt++) {
                        mma16816(acc[mt][nt], ah[mt], bh[h2*2], bh[h2*2+1]);
                        mma16816(acc[mt][nt], ah[mt], bl[h2*2], bl[h2*2+1]);
                        mma16816(acc[mt][nt], al[mt], bh[h2*2], bh[h2*2+1]);
                    }
                }
            }
        }
    }

    const int gid = lane >> 2, tig = lane & 3;
    #pragma unroll
    for (int mt = 0; mt < 2; mt++) {
        const int rbase = m0 + wm*32 + mt*16 + gid;
        #pragma unroll
        for (int nt = 0; nt < 8; nt++) {
            const int col = n0 + wn*64 + nt*8 + tig*2;
            const float b0v = bias[col], b1v = bias[col+1];
            float v00 = acc[mt][nt][0] + b0v;
            float v01 = acc[mt][nt][1] + b1v;
            float v10 = acc[mt][nt][2] + b0v;
            float v11 = acc[mt][nt][3] + b1v;
            if (MODE == 0) {
                const int hh = col >> 6, e = col & 63;
                #pragma unroll
                for (int half = 0; half < 2; half++) {
                    const int r = rbase + half*8;
                    const int b = r >> 9, s = r & (S_-1);
                    const size_t rowb = (size_t)(b*H_ + hh)*S_ + s;
                    const float va = half ? v10 : v00;
                    const float vb = half ? v11 : v01;
                    uint32_t hi, lo; split2(va, vb, hi, lo);
                    if (z == 0) {
                        *(uint32_t*)&g_qkhi[rowb*128 + e] = hi;
                        *(uint32_t*)&g_qklo[rowb*128 + e] = lo;
                    } else if (z == 1) {
                        *(uint32_t*)&g_qkhi[rowb*128 + 64 + e] = hi;
                        *(uint32_t*)&g_qklo[rowb*128 + 64 + e] = lo;
                    } else {
                        *(uint32_t*)&g_vhi[rowb*64 + e] = hi;
                        *(uint32_t*)&g_vlo[rowb*64 + e] = lo;
                    }
                }
            } else {
                out1[(size_t)rbase*D_ + col]       = v00;
                out1[(size_t)rbase*D_ + col + 1]   = v01;
                out1[(size_t)(rbase+8)*D_ + col]   = v10;
                out1[(size_t)(rbase+8)*D_ + col+1] = v11;
            }
        }
    }
}

// ---------------- bias table via tensor cores -----------------------------------
__global__ void __launch_bounds__(256, 1)
bias_mma_kernel()
{
    __shared__ __nv_bfloat16 sAhi[128][LDSB], sAlo[128][LDSB];
    __shared__ __nv_bfloat16 sBhi[EROWS][LDSB], sBlo[EROWS][LDSB];

    const int rt = blockIdx.x;
    const int h  = blockIdx.y, b = blockIdx.z;
    const size_t bh = (size_t)b*H_ + h;
    const size_t abase = (bh*S_ + rt*128) * 128;

    const int tid  = threadIdx.x;
    const int lane = tid & 31;
    const int warp = tid >> 5;

    float acc[14][4];
    #pragma unroll
    for (int nt = 0; nt < 14; nt++)
        #pragma unroll
        for (int j = 0; j < 4; j++) acc[nt][j] = 0.f;

    const int mat = lane >> 3, mr = lane & 7;
    const int a_row = (mat & 1) * 8 + mr;
    const int a_k   = (mat >> 1) * 8;
    const uint32_t aHi = (uint32_t)__cvta_generic_to_shared(&sAhi[warp*16 + a_row][a_k]);
    const uint32_t aLo = (uint32_t)__cvta_generic_to_shared(&sAlo[warp*16 + a_row][a_k]);
    const int b_row = (mat >> 1) * 8 + mr;
    const int b_k   = (mat & 1) * 8;
    const uint32_t bHi = (uint32_t)__cvta_generic_to_shared(&sBhi[b_row][b_k]);
    const uint32_t bLo = (uint32_t)__cvta_generic_to_shared(&sBlo[b_row][b_k]);

    for (int k0 = 0; k0 < 128; k0 += BK) {
        {
            const int arow = tid >> 1;
            const int acol = (tid & 1) * 16;
            const size_t src = abase + (size_t)arow*128 + k0 + acol;
            uint4 h0 = *(const uint4*)(g_qkhi + src);
            uint4 h1 = *(const uint4*)(g_qkhi + src + 8);
            uint4 l0 = *(const uint4*)(g_qklo + src);
            uint4 l1 = *(const uint4*)(g_qklo + src + 8);
            __syncthreads();
            *(uint4*)&sAhi[arow][acol]     = h0;
            *(uint4*)&sAhi[arow][acol + 8] = h1;
            *(uint4*)&sAlo[arow][acol]     = l0;
            *(uint4*)&sAlo[arow][acol + 8] = l1;
        }
        if (tid < EROWS*2) {
            const int brow = tid >> 1;
            const int bcol = (tid & 1) * 16;
            const size_t src = (size_t)brow*128 + k0 + bcol;
            *(uint4*)&sBhi[brow][bcol]     = *(const uint4*)(g_ehi + src);
            *(uint4*)&sBhi[brow][bcol + 8] = *(const uint4*)(g_ehi + src + 8);
            *(uint4*)&sBlo[brow][bcol]     = *(const uint4*)(g_elo + src);
            *(uint4*)&sBlo[brow][bcol + 8] = *(const uint4*)(g_elo + src + 8);
        }
        __syncthreads();

        #pragma unroll
        for (int ks = 0; ks < 2; ks++) {
            const uint32_t ko = ks * 32;
            uint32_t ah[4], al[4];
            ldsm_x4(aHi + ko, ah[0], ah[1], ah[2], ah[3]);
            ldsm_x4(aLo + ko, al[0], al[1], al[2], al[3]);
            #pragma unroll
            for (int pr = 0; pr < 7; pr++) {
                const uint32_t po = pr * (16 * LDSB * 2);
                uint32_t bhf[4], blf[4];
                ldsm_x4(bHi + po + ko, bhf[0], bhf[1], bhf[2], bhf[3]);
                ldsm_x4(bLo + po + ko, blf[0], blf[1], blf[2], blf[3]);
                #pragma unroll
                for (int h2 = 0; h2 < 2; h2++) {
                    const int nt = pr*2 + h2;
                    mma16816(acc[nt], ah, bhf[h2*2], bhf[h2*2+1]);
                    mma16816(acc[nt], ah, blf[h2*2], blf[h2*2+1]);
                    mma16816(acc[nt], al, bhf[h2*2], bhf[h2*2+1]);
                }
            }
        }
        __syncthreads();
    }

    const int gid = lane >> 2, tig = lane & 3;
    const int row0 = rt*128 + warp*16 + gid;
    #pragma unroll
    for (int nt = 0; nt < 14; nt++) {
        const int col = nt*8 + tig*2;
        #pragma unroll
        for (int half = 0; half < 2; half++) {
            const int row = row0 + half*8;
            const size_t o = (bh*S_ + row)*NRELV;
            const float v0 = acc[nt][half*2];
            const float v1 = acc[nt][half*2+1];
            if (col < NRELV)     g_bias[o + col]     = v0;
            if (col + 1 < NRELV) g_bias[o + col + 1] = v1;
        }
    }
}

// ---------------- fused attention: QT=32, cp.async KV, fused scalar phases ------
#define QT    32
#define SSTR  520
#define OFF_SS    0
#define KVHI(bf)  (66560u + (uint32_t)(bf)*36864u)
#define KVLO(bf)  (84992u + (uint32_t)(bf)*36864u)
#define OFF_SB    140288
#define OFF_SW    153216
#define OFF_SZ    166144
#define OFF_MASK  166272
#define OFF_EV    168320
#define SMEM_ATTN 194176

__global__ void __launch_bounds__(512, 1)
attn_kernel(const int* __restrict__ mask, const float* __restrict__ Ev)
{
    extern __shared__ char smraw[];
    const uint32_t sbase = (uint32_t)__cvta_generic_to_shared(smraw);
    float* sS    = (float*)(smraw + OFF_SS);
    float* sEv   = (float*)(smraw + OFF_EV);
    float* sB    = (float*)(smraw + OFF_SB);
    float* sW    = (float*)(smraw + OFF_SW);
    float* sZ    = (float*)(smraw + OFF_SZ);
    int*   sMask = (int*)  (smraw + OFF_MASK);

    const int qt = blockIdx.x, h = blockIdx.y, b = blockIdx.z;
    const int i0 = qt * QT;
    const int tid  = threadIdx.x;
    const int lane = tid & 31;
    const int warp = tid >> 5;
    const int mt   = warp >> 3;
    const int wj   = warp & 7;
    const size_t bh    = (size_t)b*H_ + h;
    const size_t qrow0 = bh*S_ + i0;
    const size_t krow0 = bh*S_;
    const size_t vbase = bh*S_*HD_;

    const int copyrow = tid >> 2;
    const int cq      = (tid & 3) * 16;
    const uint32_t dOff = (uint32_t)(copyrow*144 + cq*2);

    {
        const size_t src = (krow0 + copyrow)*128 + 64 + cq;
        cp16(sbase + KVHI(0) + dOff,      g_qkhi + src);
        cp16(sbase + KVHI(0) + dOff + 16, g_qkhi + src + 8);
        cp16(sbase + KVLO(0) + dOff,      g_qklo + src);
        cp16(sbase + KVLO(0) + dOff + 16, g_qklo + src + 8);
    }
    asm volatile("cp.async.commit_group;");

    for (int i = tid; i < QT*NRELV; i += 512) {
        sB[i] = g_bias[qrow0*NRELV + i];
        sW[i] = 0.f;
    }
    for (int i = tid; i < S_; i += 512) sMask[i] = mask[b*S_ + i];

    uint32_t qah[4][4], qal[4][4];
    {
        const int qr = lane >> 2;
        const int qc = (lane & 3) * 2;
        const size_t qm = qrow0 + mt*16;
        #pragma unroll
        for (int kk = 0; kk < 4; kk++) {
            const size_t r0o = (qm + qr)*128     + kk*16 + qc;
            const size_t r1o = (qm + qr + 8)*128 + kk*16 + qc;
            qah[kk][0] = *(const uint32_t*)&g_qkhi[r0o];
            qah[kk][1] = *(const uint32_t*)&g_qkhi[r1o];
            qah[kk][2] = *(const uint32_t*)&g_qkhi[r0o + 8];
            qah[kk][3] = *(const uint32_t*)&g_qkhi[r1o + 8];
            qal[kk][0] = *(const uint32_t*)&g_qklo[r0o];
            qal[kk][1] = *(const uint32_t*)&g_qklo[r1o];
            qal[kk][2] = *(const uint32_t*)&g_qklo[r0o + 8];
            qal[kk][3] = *(const uint32_t*)&g_qklo[r1o + 8];
        }
    }
    __syncthreads();

    const uint32_t bfragOff =
        (uint32_t)((wj*16 + ((lane >> 4) & 1)*8 + (lane & 7))*144 + ((lane >> 3) & 1)*16);

    for (int jt = 0; jt < 4; jt++) {
        if (jt < 3) {
            const int nb = (jt + 1) & 1;
            const size_t src = (krow0 + (jt+1)*128 + copyrow)*128 + 64 + cq;
            cp16(sbase + KVHI(nb) + dOff,      g_qkhi + src);
            cp16(sbase + KVHI(nb) + dOff + 16, g_qkhi + src + 8);
            cp16(sbase + KVLO(nb) + dOff,      g_qklo + src);
            cp16(sbase + KVLO(nb) + dOff + 16, g_qklo + src + 8);
        } else {
            const size_t src = vbase + (size_t)copyrow*HD_ + cq;
            cp16(sbase + KVHI(0) + dOff,      g_vhi + src);
            cp16(sbase + KVHI(0) + dOff + 16, g_vhi + src + 8);
            cp16(sbase + KVLO(0) + dOff,      g_vlo + src);
            cp16(sbase + KVLO(0) + dOff + 16, g_vlo + src + 8);
        }
        asm volatile("cp.async.commit_group;");
        asm volatile("cp.async.wait_group 1;");
        __syncthreads();

        const uint32_t khA = sbase + KVHI(jt & 1) + bfragOff;
        const uint32_t klA = sbase + KVLO(jt & 1) + bfragOff;
        const int j0 = jt * 128;

        float c[2][4] = {{0,0,0,0},{0,0,0,0}};
        #pragma unroll
        for (int kk = 0; kk < 4; kk++) {
            uint32_t bhf[4], blf[4];
            ldsm_x4(khA + kk*32, bhf[0], bhf[1], bhf[2], bhf[3]);
            ldsm_x4(klA + kk*32, blf[0], blf[1], blf[2], blf[3]);
            mma16816(c[0], qah[kk], bhf[0], bhf[1]);
            mma16816(c[0], qah[kk], blf[0], blf[1]);
            mma16816(c[0], qal[kk], bhf[0], bhf[1]);
            mma16816(c[1], qah[kk], bhf[2], bhf[3]);
            mma16816(c[1], qah[kk], blf[2], blf[3]);
            mma16816(c[1], qal[kk], bhf[2], bhf[3]);
        }
        #pragma unroll
        for (int nt = 0; nt < 2; nt++) {
            const int col = j0 + wj*16 + nt*8 + 2*(lane & 3);
            const int r   = mt*16 + (lane >> 2);
            *(float2*)&sS[r*SSTR + col]     = make_float2(c[nt][0], c[nt][1]);
            *(float2*)&sS[(r+8)*SSTR + col] = make_float2(c[nt][2], c[nt][3]);
        }
        __syncthreads();
    }

    {
        const size_t src = vbase + (size_t)(128 + copyrow)*HD_ + cq;
        cp16(sbase + KVHI(1) + dOff,      g_vhi + src);
        cp16(sbase + KVHI(1) + dOff + 16, g_vhi + src + 8);
        cp16(sbase + KVLO(1) + dOff,      g_vlo + src);
        cp16(sbase + KVLO(1) + dOff + 16, g_vlo + src + 8);
    }
    asm volatile("cp.async.commit_group;");

    for (int i = tid; i < NRELV*HD_; i += 512) sEv[i] = Ev[i];

    const size_t arcbase = ((size_t)b*S_ + i0)*S_;
    {
        uchar4 relreg[2][4];
        #pragma unroll
        for (int rr = 0; rr < 2; rr++) {
            const int row = warp*2 + rr;
            const float* brow = &sB[row*NRELV];
            float m = -3.4e38f;
            #pragma unroll
            for (int it = 0; it < 4; it++) {
                const int j = it*128 + lane*4;
                uchar4 r4 = *(const uchar4*)&g_rel8[arcbase + (size_t)row*S_ + j];
                relreg[rr][it] = r4;
                float4 s4 = *(float4*)&sS[row*SSTR + j];
                s4.x = (s4.x + brow[r4.x]) * 0.125f; if (sMask[j]     == 0) s4.x = -1e30f;
                s4.y = (s4.y + brow[r4.y]) * 0.125f; if (sMask[j + 1] == 0) s4.y = -1e30f;
                s4.z = (s4.z + brow[r4.z]) * 0.125f; if (sMask[j + 2] == 0) s4.z = -1e30f;
                s4.w = (s4.w + brow[r4.w]) * 0.125f; if (sMask[j + 3] == 0) s4.w = -1e30f;
                *(float4*)&sS[row*SSTR + j] = s4;
                m = fmaxf(m, fmaxf(fmaxf(s4.x, s4.y), fmaxf(s4.z, s4.w)));
            }
            #pragma unroll
            for (int o = 16; o; o >>= 1) m = fmaxf(m, __shfl_xor_sync(0xffffffffu, m, o));

            float z = 0.f;
            float* wrow = &sW[row*NRELV];
            #pragma unroll
            for (int it = 0; it < 4; it++) {
                const int j = it*128 + lane*4;
                float4 s4 = *(float4*)&sS[row*SSTR + j];
                float4 p4;
                p4.x = __expf(s4.x - m);
                p4.y = __expf(s4.y - m);
                p4.z = __expf(s4.z - m);
                p4.w = __expf(s4.w - m);
                *(float4*)&sS[row*SSTR + j] = p4;
                z += p4.x + p4.y + p4.z + p4.w;
                uchar4 r4 = relreg[rr][it];
                atomicAdd(&wrow[r4.x], p4.x);
                atomicAdd(&wrow[r4.y], p4.y);
                atomicAdd(&wrow[r4.z], p4.z);
                atomicAdd(&wrow[r4.w], p4.w);
            }
            #pragma unroll
            for (int o = 16; o; o >>= 1) z += __shfl_xor_sync(0xffffffffu, z, o);
            if (lane == 0) sZ[row] = z;
        }
    }
    __syncthreads();

    float c2[8][4];
    #pragma unroll
    for (int nt = 0; nt < 8; nt++)
        #pragma unroll
        for (int j = 0; j < 4; j++) c2[nt][j] = 0.f;

    for (int jt = 0; jt < 4; jt++) {
        if (jt < 3) { asm volatile("cp.async.wait_group 1;"); }
        else        { asm volatile("cp.async.wait_group 0;"); }
        __syncthreads();

        const uint32_t vh = sbase + KVHI(jt & 1);
        const uint32_t vl = sbase + KVLO(jt & 1);
        const int jb = jt*128 + wj*16;
        uint32_t pah[4], pal[4];
        {
            const int pr = mt*16 + (lane >> 2);
            const int pc = (lane & 3) * 2;
            float2 x0 = *(float2*)&sS[pr*SSTR     + jb + pc];
            float2 x1 = *(float2*)&sS[(pr+8)*SSTR + jb + pc];
            float2 x2 = *(float2*)&sS[pr*SSTR     + jb + pc + 8];
            float2 x3 = *(float2*)&sS[(pr+8)*SSTR + jb + pc + 8];
            split2(x0.x, x0.y, pah[0], pal[0]);
            split2(x1.x, x1.y, pah[1], pal[1]);
            split2(x2.x, x2.y, pah[2], pal[2]);
            split2(x3.x, x3.y, pah[3], pal[3]);
        }
        const uint32_t rowoff = (uint32_t)(wj*16 + (lane & 15)) * 144;
        #pragma unroll
        for (int nt = 0; nt < 8; nt++) {
            uint32_t bh0, bh1, bl0, bl1;
            ldsm_x2_trans(vh + rowoff + nt*16, bh0, bh1);
            ldsm_x2_trans(vl + rowoff + nt*16, bl0, bl1);
            mma16816(c2[nt], pah, bh0, bh1);
            mma16816(c2[nt], pah, bl0, bl1);
            mma16816(c2[nt], pal, bh0, bh1);
        }
        __syncthreads();

        if (jt + 2 < 4) {
            const int nb = jt & 1;
            const size_t src = vbase + (size_t)((jt+2)*128 + copyrow)*HD_ + cq;
            cp16(sbase + KVHI(nb) + dOff,      g_vhi + src);
            cp16(sbase + KVHI(nb) + dOff + 16, g_vhi + src + 8);
            cp16(sbase + KVLO(nb) + dOff,      g_vlo + src);
            cp16(sbase + KVLO(nb) + dOff + 16, g_vlo + src + 8);
            asm volatile("cp.async.commit_group;");
        }
    }

    {
        float* red = sS;
        const int r = lane >> 2;
        #pragma unroll
        for (int nt = 0; nt < 8; nt++) {
            const int col = nt*8 + 2*(lane & 3);
            red[warp*1024 + r*64 + col]       = c2[nt][0];
            red[warp*1024 + r*64 + col + 1]   = c2[nt][1];
            red[warp*1024 + (r+8)*64 + col]   = c2[nt][2];
            red[warp*1024 + (r+8)*64 + col+1] = c2[nt][3];
        }
    }
    __syncthreads();

    {
        const int row = tid >> 4;
        const int e0  = (tid & 15) * 4;
        const int rmt = row >> 4, rl = row & 15;
        float4 acc = make_float4(0,0,0,0);
        #pragma unroll
        for (int w = 0; w < 8; w++) {
            float4 p = *(float4*)&sS[(rmt*8 + w)*1024 + rl*64 + e0];
            acc.x += p.x; acc.y += p.y; acc.z += p.z; acc.w += p.w;
        }
        const float* wrow = &sW[row*NRELV];
        for (int rel = 0; rel < NRELV; rel++) {
            float wv = wrow[rel];
            float4 ev = *(float4*)&sEv[rel*64 + e0];
            acc.x += wv*ev.x; acc.y += wv*ev.y; acc.z += wv*ev.z; acc.w += wv*ev.w;
        }
        const float rz = 1.f / sZ[row];
        acc.x *= rz; acc.y *= rz; acc.z *= rz; acc.w *= rz;

        uint32_t h0, l0, h1, l1;
        split2(acc.x, acc.y, h0, l0);
        split2(acc.z, acc.w, h1, l1);
        const size_t o = ((size_t)(b*S_ + i0 + row))*D_ + h*HD_ + e0;
        *(uint2*)&g_chi[o] = make_uint2(h0, h1);
        *(uint2*)&g_clo[o] = make_uint2(l0, l1);
    }
}

// ---------------- launch --------------------------------------------------------
extern "C" void kernel_launch(void* const* d_in, const int* in_sizes, int n_in,
                              void* d_out, int out_size)
{
    (void)in_sizes; (void)n_in; (void)out_size;
    const float* query = (const float*)d_in[0];
    const float* key_  = (const float*)d_in[1];
    const float* value = (const float*)d_in[2];
    const int*   mask  = (const int*)d_in[3];
    const void*  arc   = d_in[4];
    const float* bq = (const float*)d_in[6];
    const float* bk = (const float*)d_in[8];
    const float* bv = (const float*)d_in[10];
    const float* bo = (const float*)d_in[12];
    const float* Ek = (const float*)d_in[13];
    const float* Eq = (const float*)d_in[14];
    const float* Ev = (const float*)d_in[15];
    float* out = (float*)d_out;

    cudaFuncSetAttribute(attn_kernel, cudaFuncAttributeMaxDynamicSharedMemorySize, SMEM_ATTN);
    cudaFuncSetAttribute(mma_gemm_kernel<0>, cudaFuncAttributeMaxDynamicSharedMemorySize, 2*GSTAGE);
    cudaFuncSetAttribute(mma_gemm_kernel<1>, cudaFuncAttributeMaxDynamicSharedMemorySize, 2*GSTAGE);

    __nv_bfloat16 *xhi, *xlo, *whi, *wlo;
    cudaGetSymbolAddress((void**)&xhi, g_xhi);
    cudaGetSymbolAddress((void**)&xlo, g_xlo);
    cudaGetSymbolAddress((void**)&whi, g_whi);
    cudaGetSymbolAddress((void**)&wlo, g_wlo);

    detect_kernel<<<1, 256>>>((const int*)arc);

    PrepArgs pa;
    const float* srcs[7] = {query, key_, value,
                            (const float*)d_in[5], (const float*)d_in[7],
                            (const float*)d_in[9], (const float*)d_in[11]};
    for (int i = 0; i < 7; i++) {
        pa.src[i] = srcs[i];
        if (i < 3) {
            pa.hi[i] = xhi + (size_t)i*XN;
            pa.lo[i] = xlo + (size_t)i*XN;
            pa.n[i]  = XN;
        } else {
            pa.hi[i] = whi + (size_t)(i-3)*WN;
            pa.lo[i] = wlo + (size_t)(i-3)*WN;
            pa.n[i]  = WN;
        }
    }
    pa.Ek = Ek; pa.Eq = Eq; pa.arc = arc;
    prep_kernel<<<dim3((XN/4 + 255)/256, 9), 256>>>(pa);

    dim3 qkvGrid(D_/BN, (B_*S_)/BM, 3);
    mma_gemm_kernel<0><<<qkvGrid, 256, 2*GSTAGE>>>(bq, bk, bv, nullptr);

    bias_mma_kernel<<<dim3(4, H_, B_), 256>>>();
    attn_kernel<<<dim3(S_/QT, H_, B_), 512, SMEM_ATTN>>>(mask, Ev);

    dim3 oGrid(D_/BN, (B_*S_)/BM, 1);
    mma_gemm_kernel<1><<<oGrid, 256, 2*GSTAGE>>>(bo, nullptr, nullptr, out);
}

// round 14
// speedup vs baseline: 1.0556x; 1.0140x over previous
#include <cuda_runtime.h>
#include <cuda_bf16.h>
#include <cstdint>
#include <cstddef>

#define B_    4
#define S_    512
#define D_    768
#define H_    12
#define HD_   64
#define NRELV 101
#define EROWS 112
#define XN    (B_*S_*D_)
#define WN    (D_*D_)

#define BM    128
#define BN    128
#define BK    32
#define GSTAGE 40960       // bytes per gemm pipeline stage

// ---------------- scratch ------------------------------------------------------
__device__ __nv_bfloat16 g_qkhi[(size_t)B_*H_*S_*128], g_qklo[(size_t)B_*H_*S_*128];
__device__ __nv_bfloat16 g_vhi[XN], g_vlo[XN];
__device__ __nv_bfloat16 g_xhi[3*XN], g_xlo[3*XN];
__device__ __nv_bfloat16 g_whi[4*WN], g_wlo[4*WN];
__device__ __nv_bfloat16 g_chi[XN], g_clo[XN];
__device__ __nv_bfloat16 g_ehi[EROWS*128], g_elo[EROWS*128];
__device__ float   g_bias[(size_t)B_*H_*S_*NRELV];
__device__ uint8_t g_rel8[(size_t)B_*S_*S_];
__device__ int     g_arc_is64;

// ---------------- helpers ------------------------------------------------------
__device__ __forceinline__ void split2(float a, float b, uint32_t& hi, uint32_t& lo)
{
    __nv_bfloat16 h0 = __float2bfloat16(a);
    __nv_bfloat16 h1 = __float2bfloat16(b);
    __nv_bfloat16 l0 = __float2bfloat16(a - __bfloat162float(h0));
    __nv_bfloat16 l1 = __float2bfloat16(b - __bfloat162float(h1));
    hi = (uint32_t)*(unsigned short*)&h0 | ((uint32_t)*(unsigned short*)&h1 << 16);
    lo = (uint32_t)*(unsigned short*)&l0 | ((uint32_t)*(unsigned short*)&l1 << 16);
}

__device__ __forceinline__ void ldsm_x4(uint32_t addr, uint32_t& r0, uint32_t& r1,
                                        uint32_t& r2, uint32_t& r3)
{
    asm volatile("ldmatrix.sync.aligned.m8n8.x4.shared.b16 {%0,%1,%2,%3}, [%4];"
                 : "=r"(r0), "=r"(r1), "=r"(r2), "=r"(r3) : "r"(addr));
}

__device__ __forceinline__ void ldsm_x2_trans(uint32_t addr, uint32_t& r0, uint32_t& r1)
{
    asm volatile("ldmatrix.sync.aligned.m8n8.x2.trans.shared.b16 {%0,%1}, [%2];"
                 : "=r"(r0), "=r"(r1) : "r"(addr));
}

__device__ __forceinline__ void mma16816(float* c, const uint32_t* a,
                                         uint32_t b0, uint32_t b1)
{
    asm volatile(
        "mma.sync.aligned.m16n8k16.row.col.f32.bf16.bf16.f32 "
        "{%0,%1,%2,%3}, {%4,%5,%6,%7}, {%8,%9}, {%0,%1,%2,%3};"
        : "+f"(c[0]), "+f"(c[1]), "+f"(c[2]), "+f"(c[3])
        : "r"(a[0]), "r"(a[1]), "r"(a[2]), "r"(a[3]), "r"(b0), "r"(b1));
}

__device__ __forceinline__ void cp16(uint32_t dst, const void* src)
{
    asm volatile("cp.async.ca.shared.global [%0], [%1], 16;" :: "r"(dst), "l"(src));
}

// ---------------- graph_arc dtype detection ------------------------------------
__global__ void detect_kernel(const int* __restrict__ arc32)
{
    __shared__ int cnt;
    if (threadIdx.x == 0) cnt = 0;
    __syncthreads();
    int local = 0;
    for (int i = threadIdx.x; i < 1024; i += blockDim.x)
        if (arc32[2*i + 1] != 0) local++;
    if (local) atomicAdd(&cnt, local);
    __syncthreads();
    if (threadIdx.x == 0) g_arc_is64 = (cnt == 0) ? 1 : 0;
}

// ---------------- merged prepass: splits (y=0..6), ebuild (y=7), rel8 (y=8) -----
struct PrepArgs {
    const float*   src[7];
    __nv_bfloat16* hi[7];
    __nv_bfloat16* lo[7];
    int            n[7];
    const float*   Ek;
    const float*   Eq;
    const void*    arc;
};

__global__ void __launch_bounds__(256)
prep_kernel(PrepArgs a)
{
    const int w = blockIdx.y;
    const int t = blockIdx.x * 256 + threadIdx.x;

    if (w < 7) {
        const int i = t * 4;
        if (i >= a.n[w]) return;
        float4 v = *(const float4*)(a.src[w] + i);
        uint32_t h0, l0, h1, l1;
        split2(v.x, v.y, h0, l0);
        split2(v.z, v.w, h1, l1);
        *(uint2*)(a.hi[w] + i) = make_uint2(h0, h1);
        *(uint2*)(a.lo[w] + i) = make_uint2(l0, l1);
    } else if (w == 7) {
        if (t >= EROWS*128) return;
        int row = t >> 7, col = t & 127;
        float v = 0.f;
        if (row < NRELV) v = (col < 64) ? a.Ek[row*64 + col] : a.Eq[row*64 + col - 64];
        __nv_bfloat16 hv = __float2bfloat16(v);
        __nv_bfloat16 lv = __float2bfloat16(v - __bfloat162float(hv));
        g_ehi[t] = hv;
        g_elo[t] = lv;
    } else {
        const size_t i = (size_t)t * 4;
        if (i >= (size_t)B_*S_*S_) return;
        uchar4 r;
        if (g_arc_is64) {
            const long long* p = (const long long*)a.arc + i;
            r = make_uchar4((uint8_t)p[0], (uint8_t)p[1], (uint8_t)p[2], (uint8_t)p[3]);
        } else {
            const int* p = (const int*)a.arc + i;
            r = make_uchar4((uint8_t)p[0], (uint8_t)p[1], (uint8_t)p[2], (uint8_t)p[3]);
        }
        *(uchar4*)&g_rel8[i] = r;
    }
}

// ---------------- tensor-core GEMM, cp.async 2-stage pipeline -------------------
template<int MODE>
__global__ void __launch_bounds__(256, 2)
mma_gemm_kernel(const float* __restrict__ bias0, const float* __restrict__ bias1,
                const float* __restrict__ bias2, float* __restrict__ out1)
{
    extern __shared__ char gsm[];
    const uint32_t smemBase = (uint32_t)__cvta_generic_to_shared(gsm);

    const int z = (MODE == 0) ? blockIdx.z : 0;
    const __nv_bfloat16 *Xhi, *Xlo, *Whi, *Wlo;
    const float* bias;
    if (MODE == 0) {
        Xhi = g_xhi + (size_t)z*XN;  Xlo = g_xlo + (size_t)z*XN;
        Whi = g_whi + (size_t)z*WN;  Wlo = g_wlo + (size_t)z*WN;
        bias = (z == 0) ? bias0 : (z == 1) ? bias1 : bias2;
    } else {
        Xhi = g_chi;  Xlo = g_clo;
        Whi = g_whi + (size_t)3*WN;  Wlo = g_wlo + (size_t)3*WN;
        bias = bias0;
    }

    const int tid  = threadIdx.x;
    const int lane = tid & 31;
    const int warp = tid >> 5;
    const int wm   = warp & 3;
    const int wn   = warp >> 2;
    const int m0   = blockIdx.y * BM;
    const int n0   = blockIdx.x * BN;

    float acc[2][8][4];
    #pragma unroll
    for (int mt = 0; mt < 2; mt++)
        #pragma unroll
        for (int nt = 0; nt < 8; nt++)
            #pragma unroll
            for (int j = 0; j < 4; j++) acc[mt][nt][j] = 0.f;

    const int mat = lane >> 3, mr = lane & 7;
    const uint32_t aOffHi = (uint32_t)((wm*32 + (mat & 1)*8 + mr)*80 + ((mat >> 1)*8)*2);
    const uint32_t bOffHi = 20480u + (uint32_t)((wn*64 + (mat >> 1)*8 + mr)*80 + ((mat & 1)*8)*2);

    const int ldrow = tid >> 1;
    const int ldq   = (tid & 1) * 2;
    const uint32_t xDst = (uint32_t)(ldrow*80 + ldq*16);
    const uint32_t wDst = 20480u + xDst;

    #pragma unroll
    for (int u = 0; u < 2; u++) {
        const size_t xo = (size_t)(m0 + ldrow)*D_ + (ldq + u)*8;
        const size_t wo = (size_t)(n0 + ldrow)*D_ + (ldq + u)*8;
        cp16(smemBase + xDst + u*16,          Xhi + xo);
        cp16(smemBase + 10240 + xDst + u*16,  Xlo + xo);
        cp16(smemBase + wDst + u*16,          Whi + wo);
        cp16(smemBase + 10240 + wDst + u*16,  Wlo + wo);
    }
    asm volatile("cp.async.commit_group;");

    const int NK = D_ / BK;
    for (int kt = 0; kt < NK; kt++) {
        asm volatile("cp.async.wait_group 0;");
        __syncthreads();

        if (kt + 1 < NK) {
            const uint32_t sb2 = smemBase + (uint32_t)(((kt + 1) & 1) * GSTAGE);
            const int k0 = (kt + 1) * BK;
            #pragma unroll
            for (int u = 0; u < 2; u++) {
                const size_t xo = (size_t)(m0 + ldrow)*D_ + k0 + (ldq + u)*8;
                const size_t wo = (size_t)(n0 + ldrow)*D_ + k0 + (ldq + u)*8;
                cp16(sb2 + xDst + u*16,          Xhi + xo);
                cp16(sb2 + 10240 + xDst + u*16,  Xlo + xo);
                cp16(sb2 + wDst + u*16,          Whi + wo);
                cp16(sb2 + 10240 + wDst + u*16,  Wlo + wo);
            }
        }
        asm volatile("cp.async.commit_group;");

        const uint32_t sb = smemBase + (uint32_t)((kt & 1) * GSTAGE);
        #pragma unroll
        for (int ks = 0; ks < 2; ks++) {
            const uint32_t ko = ks * 32;
            uint32_t ah[2][4], al[2][4];
            #pragma unroll
            for (int mt = 0; mt < 2; mt++) {
                const uint32_t mo = mt * 1280;
                ldsm_x4(sb + aOffHi + mo + ko,          ah[mt][0], ah[mt][1], ah[mt][2], ah[mt][3]);
                ldsm_x4(sb + aOffHi + 10240 + mo + ko,  al[mt][0], al[mt][1], al[mt][2], al[mt][3]);
            }
            #pragma unroll
            for (int pr = 0; pr < 4; pr++) {
                const uint32_t po = pr * 1280;
                uint32_t bh[4], bl[4];
                ldsm_x4(sb + bOffHi + po + ko,          bh[0], bh[1], bh[2], bh[3]);
                ldsm_x4(sb + bOffHi + 10240 + po + ko,  bl[0], bl[1], bl[2], bl[3]);
                #pragma unroll
                for (int h2 = 0; h2 < 2; h2++) {
                    const int nt = pr*2 + h2;
                    #pragma unroll
                    for (int mt = 0; mt < 2; mt++) {
                        mma16816(acc[mt][nt], ah[mt], bh[h2*2], bh[h2*2+1]);
                        mma16816(acc[mt][nt], ah[mt], bl[h2*2], bl[h2*2+1]);
                        mma16816(acc[mt][nt], al[mt], bh[h2*2], bh[h2*2+1]);
                    }
                }
            }
        }
    }

    const int gid = lane >> 2, tig = lane & 3;
    #pragma unroll
    for (int mt = 0; mt < 2; mt++) {
        const int rbase = m0 + wm*32 + mt*16 + gid;
        #pragma unroll
        for (int nt = 0; nt < 8; nt++) {
            const int col = n0 + wn*64 + nt*8 + tig*2;
            const float b0v = bias[col], b1v = bias[col+1];
            float v00 = acc[mt][nt][0] + b0v;
            float v01 = acc[mt][nt][1] + b1v;
            float v10 = acc[mt][nt][2] + b0v;
            float v11 = acc[mt][nt][3] + b1v;
            if (MODE == 0) {
                const int hh = col >> 6, e = col & 63;
                #pragma unroll
                for (int half = 0; half < 2; half++) {
                    const int r = rbase + half*8;
                    const int b = r >> 9, s = r & (S_-1);
                    const size_t rowb = (size_t)(b*H_ + hh)*S_ + s;
                    const float va = half ? v10 : v00;
                    const float vb = half ? v11 : v01;
                    uint32_t hi, lo; split2(va, vb, hi, lo);
                    if (z == 0) {
                        *(uint32_t*)&g_qkhi[rowb*128 + e] = hi;
                        *(uint32_t*)&g_qklo[rowb*128 + e] = lo;
                    } else if (z == 1) {
                        *(uint32_t*)&g_qkhi[rowb*128 + 64 + e] = hi;
                        *(uint32_t*)&g_qklo[rowb*128 + 64 + e] = lo;
                    } else {
                        *(uint32_t*)&g_vhi[rowb*64 + e] = hi;
                        *(uint32_t*)&g_vlo[rowb*64 + e] = lo;
                    }
                }
            } else {
                out1[(size_t)rbase*D_ + col]       = v00;
                out1[(size_t)rbase*D_ + col + 1]   = v01;
                out1[(size_t)(rbase+8)*D_ + col]   = v10;
                out1[(size_t)(rbase+8)*D_ + col+1] = v11;
            }
        }
    }
}

// ---------------- bias table: single-load, zero-redundancy ----------------------
// smem (bytes): Ahi@0 (128x272), Alo@34816, Bhi@69632 (112x272), Blo@100096
#define BSM_AHI 0u
#define BSM_ALO 34816u
#define BSM_BHI 69632u
#define BSM_BLO 100096u
#define BSM_TOT 130560

__global__ void __launch_bounds__(256, 1)
bias_mma_kernel()
{
    extern __shared__ char bsm[];
    const uint32_t sb = (uint32_t)__cvta_generic_to_shared(bsm);

    const int rt = blockIdx.x;
    const int h  = blockIdx.y, b = blockIdx.z;
    const size_t bh = (size_t)b*H_ + h;
    const size_t abase = (bh*S_ + rt*128) * 128;

    const int tid  = threadIdx.x;
    const int lane = tid & 31;
    const int warp = tid >> 5;

    // ---- one-shot cp.async load of A (128x128) and B (112x128), hi+lo ----
    {
        const int row  = tid >> 1;            // 0..127
        const int half = (tid & 1) * 64;      // element offset
        const uint32_t dA = (uint32_t)(row*272 + half*2);
        const size_t  sA = abase + (size_t)row*128 + half;
        #pragma unroll
        for (int u = 0; u < 8; u++) {
            cp16(sb + BSM_AHI + dA + u*16, g_qkhi + sA + u*8);
            cp16(sb + BSM_ALO + dA + u*16, g_qklo + sA + u*8);
        }
        if (tid < EROWS*2) {
            const int brow  = tid >> 1;
            const int bhalf = (tid & 1) * 64;
            const uint32_t dB = (uint32_t)(brow*272 + bhalf*2);
            const size_t  sB = (size_t)brow*128 + bhalf;
            #pragma unroll
            for (int u = 0; u < 8; u++) {
                cp16(sb + BSM_BHI + dB + u*16, g_ehi + sB + u*8);
                cp16(sb + BSM_BLO + dB + u*16, g_elo + sB + u*8);
            }
        }
    }
    asm volatile("cp.async.commit_group;");
    asm volatile("cp.async.wait_group 0;");
    __syncthreads();

    float acc[14][4];
    #pragma unroll
    for (int nt = 0; nt < 14; nt++)
        #pragma unroll
        for (int j = 0; j < 4; j++) acc[nt][j] = 0.f;

    const int mat = lane >> 3, mr = lane & 7;
    const uint32_t aOff = (uint32_t)((warp*16 + (mat & 1)*8 + mr)*272 + ((mat >> 1)*8)*2);
    const uint32_t bOff = (uint32_t)(((mat >> 1)*8 + mr)*272 + ((mat & 1)*8)*2);

    // ---- all 8 K-steps, no barriers ----
    #pragma unroll
    for (int kk = 0; kk < 8; kk++) {
        const uint32_t ko = kk * 32;
        uint32_t ah[4], al[4];
        ldsm_x4(sb + BSM_AHI + aOff + ko, ah[0], ah[1], ah[2], ah[3]);
        ldsm_x4(sb + BSM_ALO + aOff + ko, al[0], al[1], al[2], al[3]);
        #pragma unroll
        for (int pr = 0; pr < 7; pr++) {
            const uint32_t po = pr * (16*272);
            uint32_t bhf[4], blf[4];
            ldsm_x4(sb + BSM_BHI + bOff + po + ko, bhf[0], bhf[1], bhf[2], bhf[3]);
            ldsm_x4(sb + BSM_BLO + bOff + po + ko, blf[0], blf[1], blf[2], blf[3]);
            #pragma unroll
            for (int h2 = 0; h2 < 2; h2++) {
                const int nt = pr*2 + h2;
                mma16816(acc[nt], ah, bhf[h2*2], bhf[h2*2+1]);
                mma16816(acc[nt], ah, blf[h2*2], blf[h2*2+1]);
                mma16816(acc[nt], al, bhf[h2*2], bhf[h2*2+1]);
            }
        }
    }

    const int gid = lane >> 2, tig = lane & 3;
    const int row0 = rt*128 + warp*16 + gid;
    #pragma unroll
    for (int nt = 0; nt < 14; nt++) {
        const int col = nt*8 + tig*2;
        #pragma unroll
        for (int half = 0; half < 2; half++) {
            const int row = row0 + half*8;
            const size_t o = (bh*S_ + row)*NRELV;
            const float v0 = acc[nt][half*2];
            const float v1 = acc[nt][half*2+1];
            if (col < NRELV)     g_bias[o + col]     = v0;
            if (col + 1 < NRELV) g_bias[o + col + 1] = v1;
        }
    }
}

// ---------------- fused attention: QT=32, cp.async KV, fused scalar phases ------
#define QT    32
#define SSTR  520
#define OFF_SS    0
#define KVHI(bf)  (66560u + (uint32_t)(bf)*36864u)
#define KVLO(bf)  (84992u + (uint32_t)(bf)*36864u)
#define OFF_SB    140288
#define OFF_SW    153216
#define OFF_SZ    166144
#define OFF_MASK  166272
#define OFF_EV    168320
#define SMEM_ATTN 194176

__global__ void __launch_bounds__(512, 1)
attn_kernel(const int* __restrict__ mask, const float* __restrict__ Ev)
{
    extern __shared__ char smraw[];
    const uint32_t sbase = (uint32_t)__cvta_generic_to_shared(smraw);
    float* sS    = (float*)(smraw + OFF_SS);
    float* sEv   = (float*)(smraw + OFF_EV);
    float* sB    = (float*)(smraw + OFF_SB);
    float* sW    = (float*)(smraw + OFF_SW);
    float* sZ    = (float*)(smraw + OFF_SZ);
    int*   sMask = (int*)  (smraw + OFF_MASK);

    const int qt = blockIdx.x, h = blockIdx.y, b = blockIdx.z;
    const int i0 = qt * QT;
    const int tid  = threadIdx.x;
    const int lane = tid & 31;
    const int warp = tid >> 5;
    const int mt   = warp >> 3;
    const int wj   = warp & 7;
    const size_t bh    = (size_t)b*H_ + h;
    const size_t qrow0 = bh*S_ + i0;
    const size_t krow0 = bh*S_;
    const size_t vbase = bh*S_*HD_;

    const int copyrow = tid >> 2;
    const int cq      = (tid & 3) * 16;
    const uint32_t dOff = (uint32_t)(copyrow*144 + cq*2);

    {
        const size_t src = (krow0 + copyrow)*128 + 64 + cq;
        cp16(sbase + KVHI(0) + dOff,      g_qkhi + src);
        cp16(sbase + KVHI(0) + dOff + 16, g_qkhi + src + 8);
        cp16(sbase + KVLO(0) + dOff,      g_qklo + src);
        cp16(sbase + KVLO(0) + dOff + 16, g_qklo + src + 8);
    }
    asm volatile("cp.async.commit_group;");

    for (int i = tid; i < QT*NRELV; i += 512) {
        sB[i] = g_bias[qrow0*NRELV + i];
        sW[i] = 0.f;
    }
    for (int i = tid; i < S_; i += 512) sMask[i] = mask[b*S_ + i];

    uint32_t qah[4][4], qal[4][4];
    {
        const int qr = lane >> 2;
        const int qc = (lane & 3) * 2;
        const size_t qm = qrow0 + mt*16;
        #pragma unroll
        for (int kk = 0; kk < 4; kk++) {
            const size_t r0o = (qm + qr)*128     + kk*16 + qc;
            const size_t r1o = (qm + qr + 8)*128 + kk*16 + qc;
            qah[kk][0] = *(const uint32_t*)&g_qkhi[r0o];
            qah[kk][1] = *(const uint32_t*)&g_qkhi[r1o];
            qah[kk][2] = *(const uint32_t*)&g_qkhi[r0o + 8];
            qah[kk][3] = *(const uint32_t*)&g_qkhi[r1o + 8];
            qal[kk][0] = *(const uint32_t*)&g_qklo[r0o];
            qal[kk][1] = *(const uint32_t*)&g_qklo[r1o];
            qal[kk][2] = *(const uint32_t*)&g_qklo[r0o + 8];
            qal[kk][3] = *(const uint32_t*)&g_qklo[r1o + 8];
        }
    }
    __syncthreads();

    const uint32_t bfragOff =
        (uint32_t)((wj*16 + ((lane >> 4) & 1)*8 + (lane & 7))*144 + ((lane >> 3) & 1)*16);

    for (int jt = 0; jt < 4; jt++) {
        if (jt < 3) {
            const int nb = (jt + 1) & 1;
            const size_t src = (krow0 + (jt+1)*128 + copyrow)*128 + 64 + cq;
            cp16(sbase + KVHI(nb) + dOff,      g_qkhi + src);
            cp16(sbase + KVHI(nb) + dOff + 16, g_qkhi + src + 8);
            cp16(sbase + KVLO(nb) + dOff,      g_qklo + src);
            cp16(sbase + KVLO(nb) + dOff + 16, g_qklo + src + 8);
        } else {
            const size_t src = vbase + (size_t)copyrow*HD_ + cq;
            cp16(sbase + KVHI(0) + dOff,      g_vhi + src);
            cp16(sbase + KVHI(0) + dOff + 16, g_vhi + src + 8);
            cp16(sbase + KVLO(0) + dOff,      g_vlo + src);
            cp16(sbase + KVLO(0) + dOff + 16, g_vlo + src + 8);
        }
        asm volatile("cp.async.commit_group;");
        asm volatile("cp.async.wait_group 1;");
        __syncthreads();

        const uint32_t khA = sbase + KVHI(jt & 1) + bfragOff;
        const uint32_t klA = sbase + KVLO(jt & 1) + bfragOff;
        const int j0 = jt * 128;

        float c[2][4] = {{0,0,0,0},{0,0,0,0}};
        #pragma unroll
        for (int kk = 0; kk < 4; kk++) {
            uint32_t bhf[4], blf[4];
            ldsm_x4(khA + kk*32, bhf[0], bhf[1], bhf[2], bhf[3]);
            ldsm_x4(klA + kk*32, blf[0], blf[1], blf[2], blf[3]);
            mma16816(c[0], qah[kk], bhf[0], bhf[1]);
            mma16816(c[0], qah[kk], blf[0], blf[1]);
            mma16816(c[0], qal[kk], bhf[0], bhf[1]);
            mma16816(c[1], qah[kk], bhf[2], bhf[3]);
            mma16816(c[1], qah[kk], blf[2], blf[3]);
            mma16816(c[1], qal[kk], bhf[2], bhf[3]);
        }
        #pragma unroll
        for (int nt = 0; nt < 2; nt++) {
            const int col = j0 + wj*16 + nt*8 + 2*(lane & 3);
            const int r   = mt*16 + (lane >> 2);
            *(float2*)&sS[r*SSTR + col]     = make_float2(c[nt][0], c[nt][1]);
            *(float2*)&sS[(r+8)*SSTR + col] = make_float2(c[nt][2], c[nt][3]);
        }
        __syncthreads();
    }

    {
        const size_t src = vbase + (size_t)(128 + copyrow)*HD_ + cq;
        cp16(sbase + KVHI(1) + dOff,      g_vhi + src);
        cp16(sbase + KVHI(1) + dOff + 16, g_vhi + src + 8);
        cp16(sbase + KVLO(1) + dOff,      g_vlo + src);
        cp16(sbase + KVLO(1) + dOff + 16, g_vlo + src + 8);
    }
    asm volatile("cp.async.commit_group;");

    for (int i = tid; i < NRELV*HD_; i += 512) sEv[i] = Ev[i];

    const size_t arcbase = ((size_t)b*S_ + i0)*S_;
    {
        uchar4 relreg[2][4];
        #pragma unroll
        for (int rr = 0; rr < 2; rr++) {
            const int row = warp*2 + rr;
            const float* brow = &sB[row*NRELV];
            float m = -3.4e38f;
            #pragma unroll
            for (int it = 0; it < 4; it++) {
                const int j = it*128 + lane*4;
                uchar4 r4 = *(const uchar4*)&g_rel8[arcbase + (size_t)row*S_ + j];
                relreg[rr][it] = r4;
                float4 s4 = *(float4*)&sS[row*SSTR + j];
                s4.x = (s4.x + brow[r4.x]) * 0.125f; if (sMask[j]     == 0) s4.x = -1e30f;
                s4.y = (s4.y + brow[r4.y]) * 0.125f; if (sMask[j + 1] == 0) s4.y = -1e30f;
                s4.z = (s4.z + brow[r4.z]) * 0.125f; if (sMask[j + 2] == 0) s4.z = -1e30f;
                s4.w = (s4.w + brow[r4.w]) * 0.125f; if (sMask[j + 3] == 0) s4.w = -1e30f;
                *(float4*)&sS[row*SSTR + j] = s4;
                m = fmaxf(m, fmaxf(fmaxf(s4.x, s4.y), fmaxf(s4.z, s4.w)));
            }
            #pragma unroll
            for (int o = 16; o; o >>= 1) m = fmaxf(m, __shfl_xor_sync(0xffffffffu, m, o));

            float z = 0.f;
            float* wrow = &sW[row*NRELV];
            #pragma unroll
            for (int it = 0; it < 4; it++) {
                const int j = it*128 + lane*4;
                float4 s4 = *(float4*)&sS[row*SSTR + j];
                float4 p4;
                p4.x = __expf(s4.x - m);
                p4.y = __expf(s4.y - m);
                p4.z = __expf(s4.z - m);
                p4.w = __expf(s4.w - m);
                *(float4*)&sS[row*SSTR + j] = p4;
                z += p4.x + p4.y + p4.z + p4.w;
                uchar4 r4 = relreg[rr][it];
                atomicAdd(&wrow[r4.x], p4.x);
                atomicAdd(&wrow[r4.y], p4.y);
                atomicAdd(&wrow[r4.z], p4.z);
                atomicAdd(&wrow[r4.w], p4.w);
            }
            #pragma unroll
            for (int o = 16; o; o >>= 1) z += __shfl_xor_sync(0xffffffffu, z, o);
            if (lane == 0) sZ[row] = z;
        }
    }
    __syncthreads();

    float c2[8][4];
    #pragma unroll
    for (int nt = 0; nt < 8; nt++)
        #pragma unroll
        for (int j = 0; j < 4; j++) c2[nt][j] = 0.f;

    for (int jt = 0; jt < 4; jt++) {
        if (jt < 3) { asm volatile("cp.async.wait_group 1;"); }
        else        { asm volatile("cp.async.wait_group 0;"); }
        __syncthreads();

        const uint32_t vh = sbase + KVHI(jt & 1);
        const uint32_t vl = sbase + KVLO(jt & 1);
        const int jb = jt*128 + wj*16;
        uint32_t pah[4], pal[4];
        {
            const int pr = mt*16 + (lane >> 2);
            const int pc = (lane & 3) * 2;
            float2 x0 = *(float2*)&sS[pr*SSTR     + jb + pc];
            float2 x1 = *(float2*)&sS[(pr+8)*SSTR + jb + pc];
            float2 x2 = *(float2*)&sS[pr*SSTR     + jb + pc + 8];
            float2 x3 = *(float2*)&sS[(pr+8)*SSTR + jb + pc + 8];
            split2(x0.x, x0.y, pah[0], pal[0]);
            split2(x1.x, x1.y, pah[1], pal[1]);
            split2(x2.x, x2.y, pah[2], pal[2]);
            split2(x3.x, x3.y, pah[3], pal[3]);
        }
        const uint32_t rowoff = (uint32_t)(wj*16 + (lane & 15)) * 144;
        #pragma unroll
        for (int nt = 0; nt < 8; nt++) {
            uint32_t bh0, bh1, bl0, bl1;
            ldsm_x2_trans(vh + rowoff + nt*16, bh0, bh1);
            ldsm_x2_trans(vl + rowoff + nt*16, bl0, bl1);
            mma16816(c2[nt], pah, bh0, bh1);
            mma16816(c2[nt], pah, bl0, bl1);
            mma16816(c2[nt], pal, bh0, bh1);
        }
        __syncthreads();

        if (jt + 2 < 4) {
            const int nb = jt & 1;
            const size_t src = vbase + (size_t)((jt+2)*128 + copyrow)*HD_ + cq;
            cp16(sbase + KVHI(nb) + dOff,      g_vhi + src);
            cp16(sbase + KVHI(nb) + dOff + 16, g_vhi + src + 8);
            cp16(sbase + KVLO(nb) + dOff,      g_vlo + src);
            cp16(sbase + KVLO(nb) + dOff + 16, g_vlo + src + 8);
            asm volatile("cp.async.commit_group;");
        }
    }

    {
        float* red = sS;
        const int r = lane >> 2;
        #pragma unroll
        for (int nt = 0; nt < 8; nt++) {
            const int col = nt*8 + 2*(lane & 3);
            red[warp*1024 + r*64 + col]       = c2[nt][0];
            red[warp*1024 + r*64 + col + 1]   = c2[nt][1];
            red[warp*1024 + (r+8)*64 + col]   = c2[nt][2];
            red[warp*1024 + (r+8)*64 + col+1] = c2[nt][3];
        }
    }
    __syncthreads();

    {
        const int row = tid >> 4;
        const int e0  = (tid & 15) * 4;
        const int rmt = row >> 4, rl = row & 15;
        float4 acc = make_float4(0,0,0,0);
        #pragma unroll
        for (int w = 0; w < 8; w++) {
            float4 p = *(float4*)&sS[(rmt*8 + w)*1024 + rl*64 + e0];
            acc.x += p.x; acc.y += p.y; acc.z += p.z; acc.w += p.w;
        }
        const float* wrow = &sW[row*NRELV];
        for (int rel = 0; rel < NRELV; rel++) {
            float wv = wrow[rel];
            float4 ev = *(float4*)&sEv[rel*64 + e0];
            acc.x += wv*ev.x; acc.y += wv*ev.y; acc.z += wv*ev.z; acc.w += wv*ev.w;
        }
        const float rz = 1.f / sZ[row];
        acc.x *= rz; acc.y *= rz; acc.z *= rz; acc.w *= rz;

        uint32_t h0, l0, h1, l1;
        split2(acc.x, acc.y, h0, l0);
        split2(acc.z, acc.w, h1, l1);
        const size_t o = ((size_t)(b*S_ + i0 + row))*D_ + h*HD_ + e0;
        *(uint2*)&g_chi[o] = make_uint2(h0, h1);
        *(uint2*)&g_clo[o] = make_uint2(l0, l1);
    }
}

// ---------------- launch --------------------------------------------------------
extern "C" void kernel_launch(void* const* d_in, const int* in_sizes, int n_in,
                              void* d_out, int out_size)
{
    (void)in_sizes; (void)n_in; (void)out_size;
    const float* query = (const float*)d_in[0];
    const float* key_  = (const float*)d_in[1];
    const float* value = (const float*)d_in[2];
    const int*   mask  = (const int*)d_in[3];
    const void*  arc   = d_in[4];
    const float* bq = (const float*)d_in[6];
    const float* bk = (const float*)d_in[8];
    const float* bv = (const float*)d_in[10];
    const float* bo = (const float*)d_in[12];
    const float* Ek = (const float*)d_in[13];
    const float* Eq = (const float*)d_in[14];
    const float* Ev = (const float*)d_in[15];
    float* out = (float*)d_out;

    cudaFuncSetAttribute(attn_kernel, cudaFuncAttributeMaxDynamicSharedMemorySize, SMEM_ATTN);
    cudaFuncSetAttribute(mma_gemm_kernel<0>, cudaFuncAttributeMaxDynamicSharedMemorySize, 2*GSTAGE);
    cudaFuncSetAttribute(mma_gemm_kernel<1>, cudaFuncAttributeMaxDynamicSharedMemorySize, 2*GSTAGE);
    cudaFuncSetAttribute(bias_mma_kernel, cudaFuncAttributeMaxDynamicSharedMemorySize, BSM_TOT);

    __nv_bfloat16 *xhi, *xlo, *whi, *wlo;
    cudaGetSymbolAddress((void**)&xhi, g_xhi);
    cudaGetSymbolAddress((void**)&xlo, g_xlo);
    cudaGetSymbolAddress((void**)&whi, g_whi);
    cudaGetSymbolAddress((void**)&wlo, g_wlo);

    detect_kernel<<<1, 256>>>((const int*)arc);

    PrepArgs pa;
    const float* srcs[7] = {query, key_, value,
                            (const float*)d_in[5], (const float*)d_in[7],
                            (const float*)d_in[9], (const float*)d_in[11]};
    for (int i = 0; i < 7; i++) {
        pa.src[i] = srcs[i];
        if (i < 3) {
            pa.hi[i] = xhi + (size_t)i*XN;
            pa.lo[i] = xlo + (size_t)i*XN;
            pa.n[i]  = XN;
        } else {
            pa.hi[i] = whi + (size_t)(i-3)*WN;
            pa.lo[i] = wlo + (size_t)(i-3)*WN;
            pa.n[i]  = WN;
        }
    }
    pa.Ek = Ek; pa.Eq = Eq; pa.arc = arc;
    prep_kernel<<<dim3((XN/4 + 255)/256, 9), 256>>>(pa);

    dim3 qkvGrid(D_/BN, (B_*S_)/BM, 3);
    mma_gemm_kernel<0><<<qkvGrid, 256, 2*GSTAGE>>>(bq, bk, bv, nullptr);

    bias_mma_kernel<<<dim3(4, H_, B_), 256, BSM_TOT>>>();
    attn_kernel<<<dim3(S_/QT, H_, B_), 512, SMEM_ATTN>>>(mask, Ev);

    dim3 oGrid(D_/BN, (B_*S_)/BM, 1);
    mma_gemm_kernel<1><<<oGrid, 256, 2*GSTAGE>>>(bo, nullptr, nullptr, out);
}

// round 15
// speedup vs baseline: 1.0570x; 1.0012x over previous
#include <cuda_runtime.h>
#include <cuda_bf16.h>
#include <cstdint>
#include <cstddef>

#define B_    4
#define S_    512
#define D_    768
#define H_    12
#define HD_   64
#define NRELV 101
#define EROWS 112
#define XN    (B_*S_*D_)
#define WN    (D_*D_)

#define BM    128
#define BN    128
#define BK    32
#define GSTAGE 40960       // bytes per gemm pipeline stage

// ---------------- scratch ------------------------------------------------------
__device__ __nv_bfloat16 g_qkhi[(size_t)B_*H_*S_*128], g_qklo[(size_t)B_*H_*S_*128];
__device__ __nv_bfloat16 g_vhi[XN], g_vlo[XN];
__device__ __nv_bfloat16 g_xhi[3*XN], g_xlo[3*XN];
__device__ __nv_bfloat16 g_whi[4*WN], g_wlo[4*WN];
__device__ __nv_bfloat16 g_chi[XN], g_clo[XN];
__device__ __nv_bfloat16 g_ehi[EROWS*128], g_elo[EROWS*128];
__device__ float   g_bias[(size_t)B_*H_*S_*NRELV];
__device__ uint8_t g_rel8[(size_t)B_*S_*S_];
__device__ int     g_arc_is64;

// ---------------- helpers ------------------------------------------------------
__device__ __forceinline__ void split2(float a, float b, uint32_t& hi, uint32_t& lo)
{
    __nv_bfloat16 h0 = __float2bfloat16(a);
    __nv_bfloat16 h1 = __float2bfloat16(b);
    __nv_bfloat16 l0 = __float2bfloat16(a - __bfloat162float(h0));
    __nv_bfloat16 l1 = __float2bfloat16(b - __bfloat162float(h1));
    hi = (uint32_t)*(unsigned short*)&h0 | ((uint32_t)*(unsigned short*)&h1 << 16);
    lo = (uint32_t)*(unsigned short*)&l0 | ((uint32_t)*(unsigned short*)&l1 << 16);
}

__device__ __forceinline__ void ldsm_x4(uint32_t addr, uint32_t& r0, uint32_t& r1,
                                        uint32_t& r2, uint32_t& r3)
{
    asm volatile("ldmatrix.sync.aligned.m8n8.x4.shared.b16 {%0,%1,%2,%3}, [%4];"
                 : "=r"(r0), "=r"(r1), "=r"(r2), "=r"(r3) : "r"(addr));
}

__device__ __forceinline__ void ldsm_x2_trans(uint32_t addr, uint32_t& r0, uint32_t& r1)
{
    asm volatile("ldmatrix.sync.aligned.m8n8.x2.trans.shared.b16 {%0,%1}, [%2];"
                 : "=r"(r0), "=r"(r1) : "r"(addr));
}

__device__ __forceinline__ void mma16816(float* c, const uint32_t* a,
                                         uint32_t b0, uint32_t b1)
{
    asm volatile(
        "mma.sync.aligned.m16n8k16.row.col.f32.bf16.bf16.f32 "
        "{%0,%1,%2,%3}, {%4,%5,%6,%7}, {%8,%9}, {%0,%1,%2,%3};"
        : "+f"(c[0]), "+f"(c[1]), "+f"(c[2]), "+f"(c[3])
        : "r"(a[0]), "r"(a[1]), "r"(a[2]), "r"(a[3]), "r"(b0), "r"(b1));
}

__device__ __forceinline__ void cp16(uint32_t dst, const void* src)
{
    asm volatile("cp.async.ca.shared.global [%0], [%1], 16;" :: "r"(dst), "l"(src));
}

// ---------------- graph_arc dtype detection ------------------------------------
__global__ void detect_kernel(const int* __restrict__ arc32)
{
    __shared__ int cnt;
    if (threadIdx.x == 0) cnt = 0;
    __syncthreads();
    int local = 0;
    for (int i = threadIdx.x; i < 1024; i += blockDim.x)
        if (arc32[2*i + 1] != 0) local++;
    if (local) atomicAdd(&cnt, local);
    __syncthreads();
    if (threadIdx.x == 0) g_arc_is64 = (cnt == 0) ? 1 : 0;
}

// ---------------- merged prepass: splits (y=0..6), ebuild (y=7), rel8 (y=8) -----
struct PrepArgs {
    const float*   src[7];
    __nv_bfloat16* hi[7];
    __nv_bfloat16* lo[7];
    int            n[7];
    const float*   Ek;
    const float*   Eq;
    const void*    arc;
};

__global__ void __launch_bounds__(256)
prep_kernel(PrepArgs a)
{
    const int w = blockIdx.y;
    const int t = blockIdx.x * 256 + threadIdx.x;

    if (w < 7) {
        const int i = t * 4;
        if (i >= a.n[w]) return;
        float4 v = *(const float4*)(a.src[w] + i);
        uint32_t h0, l0, h1, l1;
        split2(v.x, v.y, h0, l0);
        split2(v.z, v.w, h1, l1);
        *(uint2*)(a.hi[w] + i) = make_uint2(h0, h1);
        *(uint2*)(a.lo[w] + i) = make_uint2(l0, l1);
    } else if (w == 7) {
        if (t >= EROWS*128) return;
        int row = t >> 7, col = t & 127;
        float v = 0.f;
        if (row < NRELV) v = (col < 64) ? a.Ek[row*64 + col] : a.Eq[row*64 + col - 64];
        __nv_bfloat16 hv = __float2bfloat16(v);
        __nv_bfloat16 lv = __float2bfloat16(v - __bfloat162float(hv));
        g_ehi[t] = hv;
        g_elo[t] = lv;
    } else {
        const size_t i = (size_t)t * 4;
        if (i >= (size_t)B_*S_*S_) return;
        uchar4 r;
        if (g_arc_is64) {
            const long long* p = (const long long*)a.arc + i;
            r = make_uchar4((uint8_t)p[0], (uint8_t)p[1], (uint8_t)p[2], (uint8_t)p[3]);
        } else {
            const int* p = (const int*)a.arc + i;
            r = make_uchar4((uint8_t)p[0], (uint8_t)p[1], (uint8_t)p[2], (uint8_t)p[3]);
        }
        *(uchar4*)&g_rel8[i] = r;
    }
}

// ---------------- tensor-core GEMM, cp.async 2-stage pipeline -------------------
template<int MODE>
__global__ void __launch_bounds__(256, 2)
mma_gemm_kernel(const float* __restrict__ bias0, const float* __restrict__ bias1,
                const float* __restrict__ bias2, float* __restrict__ out1)
{
    extern __shared__ char gsm[];
    const uint32_t smemBase = (uint32_t)__cvta_generic_to_shared(gsm);

    const int z = (MODE == 0) ? blockIdx.z : 0;
    const __nv_bfloat16 *Xhi, *Xlo, *Whi, *Wlo;
    const float* bias;
    if (MODE == 0) {
        Xhi = g_xhi + (size_t)z*XN;  Xlo = g_xlo + (size_t)z*XN;
        Whi = g_whi + (size_t)z*WN;  Wlo = g_wlo + (size_t)z*WN;
        bias = (z == 0) ? bias0 : (z == 1) ? bias1 : bias2;
    } else {
        Xhi = g_chi;  Xlo = g_clo;
        Whi = g_whi + (size_t)3*WN;  Wlo = g_wlo + (size_t)3*WN;
        bias = bias0;
    }

    const int tid  = threadIdx.x;
    const int lane = tid & 31;
    const int warp = tid >> 5;
    const int wm   = warp & 3;
    const int wn   = warp >> 2;
    const int m0   = blockIdx.y * BM;
    const int n0   = blockIdx.x * BN;

    float acc[2][8][4];
    #pragma unroll
    for (int mt = 0; mt < 2; mt++)
        #pragma unroll
        for (int nt = 0; nt < 8; nt++)
            #pragma unroll
            for (int j = 0; j < 4; j++) acc[mt][nt][j] = 0.f;

    const int mat = lane >> 3, mr = lane & 7;
    const uint32_t aOffHi = (uint32_t)((wm*32 + (mat & 1)*8 + mr)*80 + ((mat >> 1)*8)*2);
    const uint32_t bOffHi = 20480u + (uint32_t)((wn*64 + (mat >> 1)*8 + mr)*80 + ((mat & 1)*8)*2);

    const int ldrow = tid >> 1;
    const int ldq   = (tid & 1) * 2;
    const uint32_t xDst = (uint32_t)(ldrow*80 + ldq*16);
    const uint32_t wDst = 20480u + xDst;

    #pragma unroll
    for (int u = 0; u < 2; u++) {
        const size_t xo = (size_t)(m0 + ldrow)*D_ + (ldq + u)*8;
        const size_t wo = (size_t)(n0 + ldrow)*D_ + (ldq + u)*8;
        cp16(smemBase + xDst + u*16,          Xhi + xo);
        cp16(smemBase + 10240 + xDst + u*16,  Xlo + xo);
        cp16(smemBase + wDst + u*16,          Whi + wo);
        cp16(smemBase + 10240 + wDst + u*16,  Wlo + wo);
    }
    asm volatile("cp.async.commit_group;");

    const int NK = D_ / BK;
    for (int kt = 0; kt < NK; kt++) {
        asm volatile("cp.async.wait_group 0;");
        __syncthreads();

        if (kt + 1 < NK) {
            const uint32_t sb2 = smemBase + (uint32_t)(((kt + 1) & 1) * GSTAGE);
            const int k0 = (kt + 1) * BK;
            #pragma unroll
            for (int u = 0; u < 2; u++) {
                const size_t xo = (size_t)(m0 + ldrow)*D_ + k0 + (ldq + u)*8;
                const size_t wo = (size_t)(n0 + ldrow)*D_ + k0 + (ldq + u)*8;
                cp16(sb2 + xDst + u*16,          Xhi + xo);
                cp16(sb2 + 10240 + xDst + u*16,  Xlo + xo);
                cp16(sb2 + wDst + u*16,          Whi + wo);
                cp16(sb2 + 10240 + wDst + u*16,  Wlo + wo);
            }
        }
        asm volatile("cp.async.commit_group;");

        const uint32_t sb = smemBase + (uint32_t)((kt & 1) * GSTAGE);
        #pragma unroll
        for (int ks = 0; ks < 2; ks++) {
            const uint32_t ko = ks * 32;
            uint32_t ah[2][4], al[2][4];
            #pragma unroll
            for (int mt = 0; mt < 2; mt++) {
                const uint32_t mo = mt * 1280;
                ldsm_x4(sb + aOffHi + mo + ko,          ah[mt][0], ah[mt][1], ah[mt][2], ah[mt][3]);
                ldsm_x4(sb + aOffHi + 10240 + mo + ko,  al[mt][0], al[mt][1], al[mt][2], al[mt][3]);
            }
            #pragma unroll
            for (int pr = 0; pr < 4; pr++) {
                const uint32_t po = pr * 1280;
                uint32_t bh[4], bl[4];
                ldsm_x4(sb + bOffHi + po + ko,          bh[0], bh[1], bh[2], bh[3]);
                ldsm_x4(sb + bOffHi + 10240 + po + ko,  bl[0], bl[1], bl[2], bl[3]);
                #pragma unroll
                for (int h2 = 0; h2 < 2; h2++) {
                    const int nt = pr*2 + h2;
                    #pragma unroll
                    for (int mt = 0; mt < 2; mt++) {
                        mma16816(acc[mt][nt], ah[mt], bh[h2*2], bh[h2*2+1]);
                        mma16816(acc[mt][nt], ah[mt], bl[h2*2], bl[h2*2+1]);
                        mma16816(acc[mt][nt], al[mt], bh[h2*2], bh[h2*2+1]);
                    }
                }
            }
        }
    }

    const int gid = lane >> 2, tig = lane & 3;
    #pragma unroll
    for (int mt = 0; mt < 2; mt++) {
        const int rbase = m0 + wm*32 + mt*16 + gid;
        #pragma unroll
        for (int nt = 0; nt < 8; nt++) {
            const int col = n0 + wn*64 + nt*8 + tig*2;
            const float b0v = bias[col], b1v = bias[col+1];
            float v00 = acc[mt][nt][0] + b0v;
            float v01 = acc[mt][nt][1] + b1v;
            float v10 = acc[mt][nt][2] + b0v;
            float v11 = acc[mt][nt][3] + b1v;
            if (MODE == 0) {
                const int hh = col >> 6, e = col & 63;
                #pragma unroll
                for (int half = 0; half < 2; half++) {
                    const int r = rbase + half*8;
                    const int b = r >> 9, s = r & (S_-1);
                    const size_t rowb = (size_t)(b*H_ + hh)*S_ + s;
                    const float va = half ? v10 : v00;
                    const float vb = half ? v11 : v01;
                    uint32_t hi, lo; split2(va, vb, hi, lo);
                    if (z == 0) {
                        *(uint32_t*)&g_qkhi[rowb*128 + e] = hi;
                        *(uint32_t*)&g_qklo[rowb*128 + e] = lo;
                    } else if (z == 1) {
                        *(uint32_t*)&g_qkhi[rowb*128 + 64 + e] = hi;
                        *(uint32_t*)&g_qklo[rowb*128 + 64 + e] = lo;
                    } else {
                        *(uint32_t*)&g_vhi[rowb*64 + e] = hi;
                        *(uint32_t*)&g_vlo[rowb*64 + e] = lo;
                    }
                }
            } else {
                out1[(size_t)rbase*D_ + col]       = v00;
                out1[(size_t)rbase*D_ + col + 1]   = v01;
                out1[(size_t)(rbase+8)*D_ + col]   = v10;
                out1[(size_t)(rbase+8)*D_ + col+1] = v11;
            }
        }
    }
}

// ---------------- bias table: 64-row CTAs, 128 thr, 2 CTAs/SM -------------------
// smem (bytes): Ahi@0 (64x272)=17408, Alo@17408, Bhi@34816 (112x272)=30464,
//               Blo@65280 ; total 95744
#define BSM_AHI 0u
#define BSM_ALO 17408u
#define BSM_BHI 34816u
#define BSM_BLO 65280u
#define BSM_TOT 95744

__global__ void __launch_bounds__(128, 2)
bias_mma_kernel()
{
    extern __shared__ char bsm[];
    const uint32_t sb = (uint32_t)__cvta_generic_to_shared(bsm);

    const int rt = blockIdx.x;            // 0..7 (64-row tile)
    const int h  = blockIdx.y, b = blockIdx.z;
    const size_t bh = (size_t)b*H_ + h;
    const size_t abase = (bh*S_ + rt*64) * 128;

    const int tid  = threadIdx.x;
    const int lane = tid & 31;
    const int warp = tid >> 5;            // 0..3, 16 rows each

    // ---- one-shot cp.async load: A (64x128) + B (112x128), hi+lo ----
    {
        const int row  = tid >> 1;            // 0..63
        const int half = (tid & 1) * 64;
        const uint32_t dA = (uint32_t)(row*272 + half*2);
        const size_t  sA = abase + (size_t)row*128 + half;
        #pragma unroll
        for (int u = 0; u < 8; u++) {
            cp16(sb + BSM_AHI + dA + u*16, g_qkhi + sA + u*8);
            cp16(sb + BSM_ALO + dA + u*16, g_qklo + sA + u*8);
        }
        for (int i = tid; i < EROWS*2; i += 128) {
            const int brow  = i >> 1;
            const int bhalf = (i & 1) * 64;
            const uint32_t dB = (uint32_t)(brow*272 + bhalf*2);
            const size_t  sB = (size_t)brow*128 + bhalf;
            #pragma unroll
            for (int u = 0; u < 8; u++) {
                cp16(sb + BSM_BHI + dB + u*16, g_ehi + sB + u*8);
                cp16(sb + BSM_BLO + dB + u*16, g_elo + sB + u*8);
            }
        }
    }
    asm volatile("cp.async.commit_group;");
    asm volatile("cp.async.wait_group 0;");
    __syncthreads();

    float acc[14][4];
    #pragma unroll
    for (int nt = 0; nt < 14; nt++)
        #pragma unroll
        for (int j = 0; j < 4; j++) acc[nt][j] = 0.f;

    const int mat = lane >> 3, mr = lane & 7;
    const uint32_t aOff = (uint32_t)((warp*16 + (mat & 1)*8 + mr)*272 + ((mat >> 1)*8)*2);
    const uint32_t bOff = (uint32_t)(((mat >> 1)*8 + mr)*272 + ((mat & 1)*8)*2);

    #pragma unroll
    for (int kk = 0; kk < 8; kk++) {
        const uint32_t ko = kk * 32;
        uint32_t ah[4], al[4];
        ldsm_x4(sb + BSM_AHI + aOff + ko, ah[0], ah[1], ah[2], ah[3]);
        ldsm_x4(sb + BSM_ALO + aOff + ko, al[0], al[1], al[2], al[3]);
        #pragma unroll
        for (int pr = 0; pr < 7; pr++) {
            const uint32_t po = pr * (16*272);
            uint32_t bhf[4], blf[4];
            ldsm_x4(sb + BSM_BHI + bOff + po + ko, bhf[0], bhf[1], bhf[2], bhf[3]);
            ldsm_x4(sb + BSM_BLO + bOff + po + ko, blf[0], blf[1], blf[2], blf[3]);
            #pragma unroll
            for (int h2 = 0; h2 < 2; h2++) {
                const int nt = pr*2 + h2;
                mma16816(acc[nt], ah, bhf[h2*2], bhf[h2*2+1]);
                mma16816(acc[nt], ah, blf[h2*2], blf[h2*2+1]);
                mma16816(acc[nt], al, bhf[h2*2], bhf[h2*2+1]);
            }
        }
    }

    const int gid = lane >> 2, tig = lane & 3;
    const int row0 = rt*64 + warp*16 + gid;
    #pragma unroll
    for (int nt = 0; nt < 14; nt++) {
        const int col = nt*8 + tig*2;
        #pragma unroll
        for (int half = 0; half < 2; half++) {
            const int row = row0 + half*8;
            const size_t o = (bh*S_ + row)*NRELV;
            const float v0 = acc[nt][half*2];
            const float v1 = acc[nt][half*2+1];
            if (col < NRELV)     g_bias[o + col]     = v0;
            if (col + 1 < NRELV) g_bias[o + col + 1] = v1;
        }
    }
}

// ---------------- fused attention: QT=32, cp.async KV, fused scalar phases ------
#define QT    32
#define SSTR  520
#define OFF_SS    0
#define KVHI(bf)  (66560u + (uint32_t)(bf)*36864u)
#define KVLO(bf)  (84992u + (uint32_t)(bf)*36864u)
#define OFF_SB    140288
#define OFF_SW    153216
#define OFF_SZ    166144
#define OFF_MASK  166272
#define OFF_EV    168320
#define SMEM_ATTN 194176

__global__ void __launch_bounds__(512, 1)
attn_kernel(const int* __restrict__ mask, const float* __restrict__ Ev)
{
    extern __shared__ char smraw[];
    const uint32_t sbase = (uint32_t)__cvta_generic_to_shared(smraw);
    float* sS    = (float*)(smraw + OFF_SS);
    float* sEv   = (float*)(smraw + OFF_EV);
    float* sB    = (float*)(smraw + OFF_SB);
    float* sW    = (float*)(smraw + OFF_SW);
    float* sZ    = (float*)(smraw + OFF_SZ);
    int*   sMask = (int*)  (smraw + OFF_MASK);

    const int qt = blockIdx.x, h = blockIdx.y, b = blockIdx.z;
    const int i0 = qt * QT;
    const int tid  = threadIdx.x;
    const int lane = tid & 31;
    const int warp = tid >> 5;
    const int mt   = warp >> 3;
    const int wj   = warp & 7;
    const size_t bh    = (size_t)b*H_ + h;
    const size_t qrow0 = bh*S_ + i0;
    const size_t krow0 = bh*S_;
    const size_t vbase = bh*S_*HD_;

    const int copyrow = tid >> 2;
    const int cq      = (tid & 3) * 16;
    const uint32_t dOff = (uint32_t)(copyrow*144 + cq*2);

    {
        const size_t src = (krow0 + copyrow)*128 + 64 + cq;
        cp16(sbase + KVHI(0) + dOff,      g_qkhi + src);
        cp16(sbase + KVHI(0) + dOff + 16, g_qkhi + src + 8);
        cp16(sbase + KVLO(0) + dOff,      g_qklo + src);
        cp16(sbase + KVLO(0) + dOff + 16, g_qklo + src + 8);
    }
    asm volatile("cp.async.commit_group;");

    for (int i = tid; i < QT*NRELV; i += 512) {
        sB[i] = g_bias[qrow0*NRELV + i];
        sW[i] = 0.f;
    }
    for (int i = tid; i < S_; i += 512) sMask[i] = mask[b*S_ + i];

    uint32_t qah[4][4], qal[4][4];
    {
        const int qr = lane >> 2;
        const int qc = (lane & 3) * 2;
        const size_t qm = qrow0 + mt*16;
        #pragma unroll
        for (int kk = 0; kk < 4; kk++) {
            const size_t r0o = (qm + qr)*128     + kk*16 + qc;
            const size_t r1o = (qm + qr + 8)*128 + kk*16 + qc;
            qah[kk][0] = *(const uint32_t*)&g_qkhi[r0o];
            qah[kk][1] = *(const uint32_t*)&g_qkhi[r1o];
            qah[kk][2] = *(const uint32_t*)&g_qkhi[r0o + 8];
            qah[kk][3] = *(const uint32_t*)&g_qkhi[r1o + 8];
            qal[kk][0] = *(const uint32_t*)&g_qklo[r0o];
            qal[kk][1] = *(const uint32_t*)&g_qklo[r1o];
            qal[kk][2] = *(const uint32_t*)&g_qklo[r0o + 8];
            qal[kk][3] = *(const uint32_t*)&g_qklo[r1o + 8];
        }
    }
    __syncthreads();

    const uint32_t bfragOff =
        (uint32_t)((wj*16 + ((lane >> 4) & 1)*8 + (lane & 7))*144 + ((lane >> 3) & 1)*16);

    for (int jt = 0; jt < 4; jt++) {
        if (jt < 3) {
            const int nb = (jt + 1) & 1;
            const size_t src = (krow0 + (jt+1)*128 + copyrow)*128 + 64 + cq;
            cp16(sbase + KVHI(nb) + dOff,      g_qkhi + src);
            cp16(sbase + KVHI(nb) + dOff + 16, g_qkhi + src + 8);
            cp16(sbase + KVLO(nb) + dOff,      g_qklo + src);
            cp16(sbase + KVLO(nb) + dOff + 16, g_qklo + src + 8);
        } else {
            const size_t src = vbase + (size_t)copyrow*HD_ + cq;
            cp16(sbase + KVHI(0) + dOff,      g_vhi + src);
            cp16(sbase + KVHI(0) + dOff + 16, g_vhi + src + 8);
            cp16(sbase + KVLO(0) + dOff,      g_vlo + src);
            cp16(sbase + KVLO(0) + dOff + 16, g_vlo + src + 8);
        }
        asm volatile("cp.async.commit_group;");
        asm volatile("cp.async.wait_group 1;");
        __syncthreads();

        const uint32_t khA = sbase + KVHI(jt & 1) + bfragOff;
        const uint32_t klA = sbase + KVLO(jt & 1) + bfragOff;
        const int j0 = jt * 128;

        float c[2][4] = {{0,0,0,0},{0,0,0,0}};
        #pragma unroll
        for (int kk = 0; kk < 4; kk++) {
            uint32_t bhf[4], blf[4];
            ldsm_x4(khA + kk*32, bhf[0], bhf[1], bhf[2], bhf[3]);
            ldsm_x4(klA + kk*32, blf[0], blf[1], blf[2], blf[3]);
            mma16816(c[0], qah[kk], bhf[0], bhf[1]);
            mma16816(c[0], qah[kk], blf[0], blf[1]);
            mma16816(c[0], qal[kk], bhf[0], bhf[1]);
            mma16816(c[1], qah[kk], bhf[2], bhf[3]);
            mma16816(c[1], qah[kk], blf[2], blf[3]);
            mma16816(c[1], qal[kk], bhf[2], bhf[3]);
        }
        #pragma unroll
        for (int nt = 0; nt < 2; nt++) {
            const int col = j0 + wj*16 + nt*8 + 2*(lane & 3);
            const int r   = mt*16 + (lane >> 2);
            *(float2*)&sS[r*SSTR + col]     = make_float2(c[nt][0], c[nt][1]);
            *(float2*)&sS[(r+8)*SSTR + col] = make_float2(c[nt][2], c[nt][3]);
        }
        __syncthreads();
    }

    {
        const size_t src = vbase + (size_t)(128 + copyrow)*HD_ + cq;
        cp16(sbase + KVHI(1) + dOff,      g_vhi + src);
        cp16(sbase + KVHI(1) + dOff + 16, g_vhi + src + 8);
        cp16(sbase + KVLO(1) + dOff,      g_vlo + src);
        cp16(sbase + KVLO(1) + dOff + 16, g_vlo + src + 8);
    }
    asm volatile("cp.async.commit_group;");

    for (int i = tid; i < NRELV*HD_; i += 512) sEv[i] = Ev[i];

    const size_t arcbase = ((size_t)b*S_ + i0)*S_;
    {
        uchar4 relreg[2][4];
        #pragma unroll
        for (int rr = 0; rr < 2; rr++) {
            const int row = warp*2 + rr;
            const float* brow = &sB[row*NRELV];
            float m = -3.4e38f;
            #pragma unroll
            for (int it = 0; it < 4; it++) {
                const int j = it*128 + lane*4;
                uchar4 r4 = *(const uchar4*)&g_rel8[arcbase + (size_t)row*S_ + j];
                relreg[rr][it] = r4;
                float4 s4 = *(float4*)&sS[row*SSTR + j];
                s4.x = (s4.x + brow[r4.x]) * 0.125f; if (sMask[j]     == 0) s4.x = -1e30f;
                s4.y = (s4.y + brow[r4.y]) * 0.125f; if (sMask[j + 1] == 0) s4.y = -1e30f;
                s4.z = (s4.z + brow[r4.z]) * 0.125f; if (sMask[j + 2] == 0) s4.z = -1e30f;
                s4.w = (s4.w + brow[r4.w]) * 0.125f; if (sMask[j + 3] == 0) s4.w = -1e30f;
                *(float4*)&sS[row*SSTR + j] = s4;
                m = fmaxf(m, fmaxf(fmaxf(s4.x, s4.y), fmaxf(s4.z, s4.w)));
            }
            #pragma unroll
            for (int o = 16; o; o >>= 1) m = fmaxf(m, __shfl_xor_sync(0xffffffffu, m, o));

            float z = 0.f;
            float* wrow = &sW[row*NRELV];
            #pragma unroll
            for (int it = 0; it < 4; it++) {
                const int j = it*128 + lane*4;
                float4 s4 = *(float4*)&sS[row*SSTR + j];
                float4 p4;
                p4.x = __expf(s4.x - m);
                p4.y = __expf(s4.y - m);
                p4.z = __expf(s4.z - m);
                p4.w = __expf(s4.w - m);
                *(float4*)&sS[row*SSTR + j] = p4;
                z += p4.x + p4.y + p4.z + p4.w;
                uchar4 r4 = relreg[rr][it];
                atomicAdd(&wrow[r4.x], p4.x);
                atomicAdd(&wrow[r4.y], p4.y);
                atomicAdd(&wrow[r4.z], p4.z);
                atomicAdd(&wrow[r4.w], p4.w);
            }
            #pragma unroll
            for (int o = 16; o; o >>= 1) z += __shfl_xor_sync(0xffffffffu, z, o);
            if (lane == 0) sZ[row] = z;
        }
    }
    __syncthreads();

    float c2[8][4];
    #pragma unroll
    for (int nt = 0; nt < 8; nt++)
        #pragma unroll
        for (int j = 0; j < 4; j++) c2[nt][j] = 0.f;

    for (int jt = 0; jt < 4; jt++) {
        if (jt < 3) { asm volatile("cp.async.wait_group 1;"); }
        else        { asm volatile("cp.async.wait_group 0;"); }
        __syncthreads();

        const uint32_t vh = sbase + KVHI(jt & 1);
        const uint32_t vl = sbase + KVLO(jt & 1);
        const int jb = jt*128 + wj*16;
        uint32_t pah[4], pal[4];
        {
            const int pr = mt*16 + (lane >> 2);
            const int pc = (lane & 3) * 2;
            float2 x0 = *(float2*)&sS[pr*SSTR     + jb + pc];
            float2 x1 = *(float2*)&sS[(pr+8)*SSTR + jb + pc];
            float2 x2 = *(float2*)&sS[pr*SSTR     + jb + pc + 8];
            float2 x3 = *(float2*)&sS[(pr+8)*SSTR + jb + pc + 8];
            split2(x0.x, x0.y, pah[0], pal[0]);
            split2(x1.x, x1.y, pah[1], pal[1]);
            split2(x2.x, x2.y, pah[2], pal[2]);
            split2(x3.x, x3.y, pah[3], pal[3]);
        }
        const uint32_t rowoff = (uint32_t)(wj*16 + (lane & 15)) * 144;
        #pragma unroll
        for (int nt = 0; nt < 8; nt++) {
            uint32_t bh0, bh1, bl0, bl1;
            ldsm_x2_trans(vh + rowoff + nt*16, bh0, bh1);
            ldsm_x2_trans(vl + rowoff + nt*16, bl0, bl1);
            mma16816(c2[nt], pah, bh0, bh1);
            mma16816(c2[nt], pah, bl0, bl1);
            mma16816(c2[nt], pal, bh0, bh1);
        }
        __syncthreads();

        if (jt + 2 < 4) {
            const int nb = jt & 1;
            const size_t src = vbase + (size_t)((jt+2)*128 + copyrow)*HD_ + cq;
            cp16(sbase + KVHI(nb) + dOff,      g_vhi + src);
            cp16(sbase + KVHI(nb) + dOff + 16, g_vhi + src + 8);
            cp16(sbase + KVLO(nb) + dOff,      g_vlo + src);
            cp16(sbase + KVLO(nb) + dOff + 16, g_vlo + src + 8);
            asm volatile("cp.async.commit_group;");
        }
    }

    {
        float* red = sS;
        const int r = lane >> 2;
        #pragma unroll
        for (int nt = 0; nt < 8; nt++) {
            const int col = nt*8 + 2*(lane & 3);
            red[warp*1024 + r*64 + col]       = c2[nt][0];
            red[warp*1024 + r*64 + col + 1]   = c2[nt][1];
            red[warp*1024 + (r+8)*64 + col]   = c2[nt][2];
            red[warp*1024 + (r+8)*64 + col+1] = c2[nt][3];
        }
    }
    __syncthreads();

    {
        const int row = tid >> 4;
        const int e0  = (tid & 15) * 4;
        const int rmt = row >> 4, rl = row & 15;
        float4 acc = make_float4(0,0,0,0);
        #pragma unroll
        for (int w = 0; w < 8; w++) {
            float4 p = *(float4*)&sS[(rmt*8 + w)*1024 + rl*64 + e0];
            acc.x += p.x; acc.y += p.y; acc.z += p.z; acc.w += p.w;
        }
        const float* wrow = &sW[row*NRELV];
        for (int rel = 0; rel < NRELV; rel++) {
            float wv = wrow[rel];
            float4 ev = *(float4*)&sEv[rel*64 + e0];
            acc.x += wv*ev.x; acc.y += wv*ev.y; acc.z += wv*ev.z; acc.w += wv*ev.w;
        }
        const float rz = 1.f / sZ[row];
        acc.x *= rz; acc.y *= rz; acc.z *= rz; acc.w *= rz;

        uint32_t h0, l0, h1, l1;
        split2(acc.x, acc.y, h0, l0);
        split2(acc.z, acc.w, h1, l1);
        const size_t o = ((size_t)(b*S_ + i0 + row))*D_ + h*HD_ + e0;
        *(uint2*)&g_chi[o] = make_uint2(h0, h1);
        *(uint2*)&g_clo[o] = make_uint2(l0, l1);
    }
}

// ---------------- launch --------------------------------------------------------
extern "C" void kernel_launch(void* const* d_in, const int* in_sizes, int n_in,
                              void* d_out, int out_size)
{
    (void)in_sizes; (void)n_in; (void)out_size;
    const float* query = (const float*)d_in[0];
    const float* key_  = (const float*)d_in[1];
    const float* value = (const float*)d_in[2];
    const int*   mask  = (const int*)d_in[3];
    const void*  arc   = d_in[4];
    const float* bq = (const float*)d_in[6];
    const float* bk = (const float*)d_in[8];
    const float* bv = (const float*)d_in[10];
    const float* bo = (const float*)d_in[12];
    const float* Ek = (const float*)d_in[13];
    const float* Eq = (const float*)d_in[14];
    const float* Ev = (const float*)d_in[15];
    float* out = (float*)d_out;

    cudaFuncSetAttribute(attn_kernel, cudaFuncAttributeMaxDynamicSharedMemorySize, SMEM_ATTN);
    cudaFuncSetAttribute(mma_gemm_kernel<0>, cudaFuncAttributeMaxDynamicSharedMemorySize, 2*GSTAGE);
    cudaFuncSetAttribute(mma_gemm_kernel<1>, cudaFuncAttributeMaxDynamicSharedMemorySize, 2*GSTAGE);
    cudaFuncSetAttribute(bias_mma_kernel, cudaFuncAttributeMaxDynamicSharedMemorySize, BSM_TOT);

    __nv_bfloat16 *xhi, *xlo, *whi, *wlo;
    cudaGetSymbolAddress((void**)&xhi, g_xhi);
    cudaGetSymbolAddress((void**)&xlo, g_xlo);
    cudaGetSymbolAddress((void**)&whi, g_whi);
    cudaGetSymbolAddress((void**)&wlo, g_wlo);

    detect_kernel<<<1, 256>>>((const int*)arc);

    PrepArgs pa;
    const float* srcs[7] = {query, key_, value,
                            (const float*)d_in[5], (const float*)d_in[7],
                            (const float*)d_in[9], (const float*)d_in[11]};
    for (int i = 0; i < 7; i++) {
        pa.src[i] = srcs[i];
        if (i < 3) {
            pa.hi[i] = xhi + (size_t)i*XN;
            pa.lo[i] = xlo + (size_t)i*XN;
            pa.n[i]  = XN;
        } else {
            pa.hi[i] = whi + (size_t)(i-3)*WN;
            pa.lo[i] = wlo + (size_t)(i-3)*WN;
            pa.n[i]  = WN;
        }
    }
    pa.Ek = Ek; pa.Eq = Eq; pa.arc = arc;
    prep_kernel<<<dim3((XN/4 + 255)/256, 9), 256>>>(pa);

    dim3 qkvGrid(D_/BN, (B_*S_)/BM, 3);
    mma_gemm_kernel<0><<<qkvGrid, 256, 2*GSTAGE>>>(bq, bk, bv, nullptr);

    bias_mma_kernel<<<dim3(8, H_, B_), 128, BSM_TOT>>>();
    attn_kernel<<<dim3(S_/QT, H_, B_), 512, SMEM_ATTN>>>(mask, Ev);

    dim3 oGrid(D_/BN, (B_*S_)/BM, 1);
    mma_gemm_kernel<1><<<oGrid, 256, 2*GSTAGE>>>(bo, nullptr, nullptr, out);
}

// round 16
// speedup vs baseline: 1.0627x; 1.0054x over previous
#include <cuda_runtime.h>
#include <cuda_bf16.h>
#include <cstdint>
#include <cstddef>

#define B_    4
#define S_    512
#define D_    768
#define H_    12
#define HD_   64
#define NRELV 101
#define EROWS 112
#define XN    (B_*S_*D_)
#define WN    (D_*D_)

#define BM    128
#define BN    128
#define BK    32
#define GSTAGE 40960       // bytes per gemm pipeline stage

// ---------------- scratch ------------------------------------------------------
__device__ __nv_bfloat16 g_qkhi[(size_t)B_*H_*S_*128], g_qklo[(size_t)B_*H_*S_*128];
__device__ __nv_bfloat16 g_vhi[XN], g_vlo[XN];
__device__ __nv_bfloat16 g_xhi[3*XN], g_xlo[3*XN];
__device__ __nv_bfloat16 g_whi[4*WN], g_wlo[4*WN];
__device__ __nv_bfloat16 g_chi[XN], g_clo[XN];
__device__ __nv_bfloat16 g_ehi[EROWS*128], g_elo[EROWS*128];
__device__ float   g_bias[(size_t)B_*H_*S_*NRELV];
__device__ uint8_t g_rel8[(size_t)B_*S_*S_];
__device__ int     g_arc_is64;

// ---------------- helpers ------------------------------------------------------
__device__ __forceinline__ void split2(float a, float b, uint32_t& hi, uint32_t& lo)
{
    __nv_bfloat16 h0 = __float2bfloat16(a);
    __nv_bfloat16 h1 = __float2bfloat16(b);
    __nv_bfloat16 l0 = __float2bfloat16(a - __bfloat162float(h0));
    __nv_bfloat16 l1 = __float2bfloat16(b - __bfloat162float(h1));
    hi = (uint32_t)*(unsigned short*)&h0 | ((uint32_t)*(unsigned short*)&h1 << 16);
    lo = (uint32_t)*(unsigned short*)&l0 | ((uint32_t)*(unsigned short*)&l1 << 16);
}

__device__ __forceinline__ void ldsm_x4(uint32_t addr, uint32_t& r0, uint32_t& r1,
                                        uint32_t& r2, uint32_t& r3)
{
    asm volatile("ldmatrix.sync.aligned.m8n8.x4.shared.b16 {%0,%1,%2,%3}, [%4];"
                 : "=r"(r0), "=r"(r1), "=r"(r2), "=r"(r3) : "r"(addr));
}

__device__ __forceinline__ void ldsm_x2_trans(uint32_t addr, uint32_t& r0, uint32_t& r1)
{
    asm volatile("ldmatrix.sync.aligned.m8n8.x2.trans.shared.b16 {%0,%1}, [%2];"
                 : "=r"(r0), "=r"(r1) : "r"(addr));
}

__device__ __forceinline__ void mma16816(float* c, const uint32_t* a,
                                         uint32_t b0, uint32_t b1)
{
    asm volatile(
        "mma.sync.aligned.m16n8k16.row.col.f32.bf16.bf16.f32 "
        "{%0,%1,%2,%3}, {%4,%5,%6,%7}, {%8,%9}, {%0,%1,%2,%3};"
        : "+f"(c[0]), "+f"(c[1]), "+f"(c[2]), "+f"(c[3])
        : "r"(a[0]), "r"(a[1]), "r"(a[2]), "r"(a[3]), "r"(b0), "r"(b1));
}

__device__ __forceinline__ void cp16(uint32_t dst, const void* src)
{
    asm volatile("cp.async.ca.shared.global [%0], [%1], 16;" :: "r"(dst), "l"(src));
}

// ---------------- graph_arc dtype detection ------------------------------------
__global__ void detect_kernel(const int* __restrict__ arc32)
{
    __shared__ int cnt;
    if (threadIdx.x == 0) cnt = 0;
    __syncthreads();
    int local = 0;
    for (int i = threadIdx.x; i < 1024; i += blockDim.x)
        if (arc32[2*i + 1] != 0) local++;
    if (local) atomicAdd(&cnt, local);
    __syncthreads();
    if (threadIdx.x == 0) g_arc_is64 = (cnt == 0) ? 1 : 0;
}

// ---------------- merged prepass: splits (y=0..6), ebuild (y=7), rel8 (y=8) -----
struct PrepArgs {
    const float*   src[7];
    __nv_bfloat16* hi[7];
    __nv_bfloat16* lo[7];
    int            n[7];
    const float*   Ek;
    const float*   Eq;
    const void*    arc;
};

__global__ void __launch_bounds__(256)
prep_kernel(PrepArgs a)
{
    const int w = blockIdx.y;
    const int t = blockIdx.x * 256 + threadIdx.x;

    if (w < 7) {
        const int i = t * 4;
        if (i >= a.n[w]) return;
        float4 v = *(const float4*)(a.src[w] + i);
        uint32_t h0, l0, h1, l1;
        split2(v.x, v.y, h0, l0);
        split2(v.z, v.w, h1, l1);
        *(uint2*)(a.hi[w] + i) = make_uint2(h0, h1);
        *(uint2*)(a.lo[w] + i) = make_uint2(l0, l1);
    } else if (w == 7) {
        if (t >= EROWS*128) return;
        int row = t >> 7, col = t & 127;
        float v = 0.f;
        if (row < NRELV) v = (col < 64) ? a.Ek[row*64 + col] : a.Eq[row*64 + col - 64];
        __nv_bfloat16 hv = __float2bfloat16(v);
        __nv_bfloat16 lv = __float2bfloat16(v - __bfloat162float(hv));
        g_ehi[t] = hv;
        g_elo[t] = lv;
    } else {
        const size_t i = (size_t)t * 4;
        if (i >= (size_t)B_*S_*S_) return;
        uchar4 r;
        if (g_arc_is64) {
            const long long* p = (const long long*)a.arc + i;
            r = make_uchar4((uint8_t)p[0], (uint8_t)p[1], (uint8_t)p[2], (uint8_t)p[3]);
        } else {
            const int* p = (const int*)a.arc + i;
            r = make_uchar4((uint8_t)p[0], (uint8_t)p[1], (uint8_t)p[2], (uint8_t)p[3]);
        }
        *(uchar4*)&g_rel8[i] = r;
    }
}

// ---------------- tensor-core GEMM, cp.async 2-stage pipeline -------------------
template<int MODE>
__global__ void __launch_bounds__(256, 2)
mma_gemm_kernel(const float* __restrict__ bias0, const float* __restrict__ bias1,
                const float* __restrict__ bias2, float* __restrict__ out1)
{
    extern __shared__ char gsm[];
    const uint32_t smemBase = (uint32_t)__cvta_generic_to_shared(gsm);

    const int z = (MODE == 0) ? blockIdx.z : 0;
    const __nv_bfloat16 *Xhi, *Xlo, *Whi, *Wlo;
    const float* bias;
    if (MODE == 0) {
        Xhi = g_xhi + (size_t)z*XN;  Xlo = g_xlo + (size_t)z*XN;
        Whi = g_whi + (size_t)z*WN;  Wlo = g_wlo + (size_t)z*WN;
        bias = (z == 0) ? bias0 : (z == 1) ? bias1 : bias2;
    } else {
        Xhi = g_chi;  Xlo = g_clo;
        Whi = g_whi + (size_t)3*WN;  Wlo = g_wlo + (size_t)3*WN;
        bias = bias0;
    }

    const int tid  = threadIdx.x;
    const int lane = tid & 31;
    const int warp = tid >> 5;
    const int wm   = warp & 3;
    const int wn   = warp >> 2;
    const int m0   = blockIdx.y * BM;
    const int n0   = blockIdx.x * BN;

    float acc[2][8][4];
    #pragma unroll
    for (int mt = 0; mt < 2; mt++)
        #pragma unroll
        for (int nt = 0; nt < 8; nt++)
            #pragma unroll
            for (int j = 0; j < 4; j++) acc[mt][nt][j] = 0.f;

    const int mat = lane >> 3, mr = lane & 7;
    const uint32_t aOffHi = (uint32_t)((wm*32 + (mat & 1)*8 + mr)*80 + ((mat >> 1)*8)*2);
    const uint32_t bOffHi = 20480u + (uint32_t)((wn*64 + (mat >> 1)*8 + mr)*80 + ((mat & 1)*8)*2);

    const int ldrow = tid >> 1;
    const int ldq   = (tid & 1) * 2;
    const uint32_t xDst = (uint32_t)(ldrow*80 + ldq*16);
    const uint32_t wDst = 20480u + xDst;

    #pragma unroll
    for (int u = 0; u < 2; u++) {
        const size_t xo = (size_t)(m0 + ldrow)*D_ + (ldq + u)*8;
        const size_t wo = (size_t)(n0 + ldrow)*D_ + (ldq + u)*8;
        cp16(smemBase + xDst + u*16,          Xhi + xo);
        cp16(smemBase + 10240 + xDst + u*16,  Xlo + xo);
        cp16(smemBase + wDst + u*16,          Whi + wo);
        cp16(smemBase + 10240 + wDst + u*16,  Wlo + wo);
    }
    asm volatile("cp.async.commit_group;");

    const int NK = D_ / BK;
    for (int kt = 0; kt < NK; kt++) {
        asm volatile("cp.async.wait_group 0;");
        __syncthreads();

        if (kt + 1 < NK) {
            const uint32_t sb2 = smemBase + (uint32_t)(((kt + 1) & 1) * GSTAGE);
            const int k0 = (kt + 1) * BK;
            #pragma unroll
            for (int u = 0; u < 2; u++) {
                const size_t xo = (size_t)(m0 + ldrow)*D_ + k0 + (ldq + u)*8;
                const size_t wo = (size_t)(n0 + ldrow)*D_ + k0 + (ldq + u)*8;
                cp16(sb2 + xDst + u*16,          Xhi + xo);
                cp16(sb2 + 10240 + xDst + u*16,  Xlo + xo);
                cp16(sb2 + wDst + u*16,          Whi + wo);
                cp16(sb2 + 10240 + wDst + u*16,  Wlo + wo);
            }
        }
        asm volatile("cp.async.commit_group;");

        const uint32_t sb = smemBase + (uint32_t)((kt & 1) * GSTAGE);
        #pragma unroll
        for (int ks = 0; ks < 2; ks++) {
            const uint32_t ko = ks * 32;
            uint32_t ah[2][4], al[2][4];
            #pragma unroll
            for (int mt = 0; mt < 2; mt++) {
                const uint32_t mo = mt * 1280;
                ldsm_x4(sb + aOffHi + mo + ko,          ah[mt][0], ah[mt][1], ah[mt][2], ah[mt][3]);
                ldsm_x4(sb + aOffHi + 10240 + mo + ko,  al[mt][0], al[mt][1], al[mt][2], al[mt][3]);
            }
            #pragma unroll
            for (int pr = 0; pr < 4; pr++) {
                const uint32_t po = pr * 1280;
                uint32_t bh[4], bl[4];
                ldsm_x4(sb + bOffHi + po + ko,          bh[0], bh[1], bh[2], bh[3]);
                ldsm_x4(sb + bOffHi + 10240 + po + ko,  bl[0], bl[1], bl[2], bl[3]);
                #pragma unroll
                for (int h2 = 0; h2 < 2; h2++) {
                    const int nt = pr*2 + h2;
                    #pragma unroll
                    for (int mt = 0; mt < 2; mt++) {
                        mma16816(acc[mt][nt], ah[mt], bh[h2*2], bh[h2*2+1]);
                        mma16816(acc[mt][nt], ah[mt], bl[h2*2], bl[h2*2+1]);
                        mma16816(acc[mt][nt], al[mt], bh[h2*2], bh[h2*2+1]);
                    }
                }
            }
        }
    }

    const int gid = lane >> 2, tig = lane & 3;
    #pragma unroll
    for (int mt = 0; mt < 2; mt++) {
        const int rbase = m0 + wm*32 + mt*16 + gid;
        #pragma unroll
        for (int nt = 0; nt < 8; nt++) {
            const int col = n0 + wn*64 + nt*8 + tig*2;
            const float b0v = bias[col], b1v = bias[col+1];
            float v00 = acc[mt][nt][0] + b0v;
            float v01 = acc[mt][nt][1] + b1v;
            float v10 = acc[mt][nt][2] + b0v;
            float v11 = acc[mt][nt][3] + b1v;
            if (MODE == 0) {
                const int hh = col >> 6, e = col & 63;
                #pragma unroll
                for (int half = 0; half < 2; half++) {
                    const int r = rbase + half*8;
                    const int b = r >> 9, s = r & (S_-1);
                    const size_t rowb = (size_t)(b*H_ + hh)*S_ + s;
                    const float va = half ? v10 : v00;
                    const float vb = half ? v11 : v01;
                    uint32_t hi, lo; split2(va, vb, hi, lo);
                    if (z == 0) {
                        *(uint32_t*)&g_qkhi[rowb*128 + e] = hi;
                        *(uint32_t*)&g_qklo[rowb*128 + e] = lo;
                    } else if (z == 1) {
                        *(uint32_t*)&g_qkhi[rowb*128 + 64 + e] = hi;
                        *(uint32_t*)&g_qklo[rowb*128 + 64 + e] = lo;
                    } else {
                        *(uint32_t*)&g_vhi[rowb*64 + e] = hi;
                        *(uint32_t*)&g_vlo[rowb*64 + e] = lo;
                    }
                }
            } else {
                out1[(size_t)rbase*D_ + col]       = v00;
                out1[(size_t)rbase*D_ + col + 1]   = v01;
                out1[(size_t)(rbase+8)*D_ + col]   = v10;
                out1[(size_t)(rbase+8)*D_ + col+1] = v11;
            }
        }
    }
}

// ---------------- bias table: 64-row CTAs, 256 thr (4m x 2n warps), 2 CTAs/SM ---
// smem (bytes): Ahi@0 (64x272)=17408, Alo@17408, Bhi@34816 (112x272)=30464,
//               Blo@65280 ; total 95744
#define BSM_AHI 0u
#define BSM_ALO 17408u
#define BSM_BHI 34816u
#define BSM_BLO 65280u
#define BSM_TOT 95744

__global__ void __launch_bounds__(256, 2)
bias_mma_kernel()
{
    extern __shared__ char bsm[];
    const uint32_t sb = (uint32_t)__cvta_generic_to_shared(bsm);

    const int rt = blockIdx.x;            // 0..7 (64-row tile)
    const int h  = blockIdx.y, b = blockIdx.z;
    const size_t bh = (size_t)b*H_ + h;
    const size_t abase = (bh*S_ + rt*64) * 128;

    const int tid  = threadIdx.x;
    const int lane = tid & 31;
    const int warp = tid >> 5;            // 0..7
    const int wm   = warp & 3;            // 4 m-warps (16 rows each)
    const int wn   = warp >> 2;           // 2 n-halves
    const int pr0  = wn ? 4 : 0;          // n16-tile range [pr0, pr0+NPR)
    const int NPR  = wn ? 3 : 4;          // 7 n16-tiles split 4/3

    // ---- one-shot cp.async load: A (64x128) + B (112x128), hi+lo ----
    {
        const int row = tid >> 2;             // 0..63
        const int q   = (tid & 3) * 32;       // 32-elem quarter
        const uint32_t dA = (uint32_t)(row*272 + q*2);
        const size_t  sA = abase + (size_t)row*128 + q;
        #pragma unroll
        for (int u = 0; u < 4; u++) {
            cp16(sb + BSM_AHI + dA + u*16, g_qkhi + sA + u*8);
            cp16(sb + BSM_ALO + dA + u*16, g_qklo + sA + u*8);
        }
        if (tid < EROWS*2) {
            const int brow  = tid >> 1;
            const int bhalf = (tid & 1) * 64;
            const uint32_t dB = (uint32_t)(brow*272 + bhalf*2);
            const size_t  sB = (size_t)brow*128 + bhalf;
            #pragma unroll
            for (int u = 0; u < 8; u++) {
                cp16(sb + BSM_BHI + dB + u*16, g_ehi + sB + u*8);
                cp16(sb + BSM_BLO + dB + u*16, g_elo + sB + u*8);
            }
        }
    }
    asm volatile("cp.async.commit_group;");
    asm volatile("cp.async.wait_group 0;");
    __syncthreads();

    float acc[4][2][4];
    #pragma unroll
    for (int p = 0; p < 4; p++)
        #pragma unroll
        for (int h2 = 0; h2 < 2; h2++)
            #pragma unroll
            for (int j = 0; j < 4; j++) acc[p][h2][j] = 0.f;

    const int mat = lane >> 3, mr = lane & 7;
    const uint32_t aOff = (uint32_t)((wm*16 + (mat & 1)*8 + mr)*272 + ((mat >> 1)*8)*2);
    const uint32_t bOff = (uint32_t)(((mat >> 1)*8 + mr)*272 + ((mat & 1)*8)*2);

    #pragma unroll
    for (int kk = 0; kk < 8; kk++) {
        const uint32_t ko = kk * 32;
        uint32_t ah[4], al[4];
        ldsm_x4(sb + BSM_AHI + aOff + ko, ah[0], ah[1], ah[2], ah[3]);
        ldsm_x4(sb + BSM_ALO + aOff + ko, al[0], al[1], al[2], al[3]);
        #pragma unroll
        for (int p = 0; p < 4; p++) {
            if (p < NPR) {
                const uint32_t po = (uint32_t)(pr0 + p) * (16*272);
                uint32_t bhf[4], blf[4];
                ldsm_x4(sb + BSM_BHI + bOff + po + ko, bhf[0], bhf[1], bhf[2], bhf[3]);
                ldsm_x4(sb + BSM_BLO + bOff + po + ko, blf[0], blf[1], blf[2], blf[3]);
                #pragma unroll
                for (int h2 = 0; h2 < 2; h2++) {
                    mma16816(acc[p][h2], ah, bhf[h2*2], bhf[h2*2+1]);
                    mma16816(acc[p][h2], ah, blf[h2*2], blf[h2*2+1]);
                    mma16816(acc[p][h2], al, bhf[h2*2], bhf[h2*2+1]);
                }
            }
        }
    }

    const int gid = lane >> 2, tig = lane & 3;
    const int row0 = rt*64 + wm*16 + gid;
    #pragma unroll
    for (int p = 0; p < 4; p++) {
        if (p < NPR) {
            #pragma unroll
            for (int h2 = 0; h2 < 2; h2++) {
                const int nt = (pr0 + p)*2 + h2;
                const int col = nt*8 + tig*2;
                #pragma unroll
                for (int half = 0; half < 2; half++) {
                    const int row = row0 + half*8;
                    const size_t o = (bh*S_ + row)*NRELV;
                    const float v0 = acc[p][h2][half*2];
                    const float v1 = acc[p][h2][half*2+1];
                    if (col < NRELV)     g_bias[o + col]     = v0;
                    if (col + 1 < NRELV) g_bias[o + col + 1] = v1;
                }
            }
        }
    }
}

// ---------------- fused attention: QT=32, cp.async KV, fused scalar phases ------
#define QT    32
#define SSTR  520
#define OFF_SS    0
#define KVHI(bf)  (66560u + (uint32_t)(bf)*36864u)
#define KVLO(bf)  (84992u + (uint32_t)(bf)*36864u)
#define OFF_SB    140288
#define OFF_SW    153216
#define OFF_SZ    166144
#define OFF_MASK  166272
#define OFF_EV    168320
#define SMEM_ATTN 194176

__global__ void __launch_bounds__(512, 1)
attn_kernel(const int* __restrict__ mask, const float* __restrict__ Ev)
{
    extern __shared__ char smraw[];
    const uint32_t sbase = (uint32_t)__cvta_generic_to_shared(smraw);
    float* sS    = (float*)(smraw + OFF_SS);
    float* sEv   = (float*)(smraw + OFF_EV);
    float* sB    = (float*)(smraw + OFF_SB);
    float* sW    = (float*)(smraw + OFF_SW);
    float* sZ    = (float*)(smraw + OFF_SZ);
    int*   sMask = (int*)  (smraw + OFF_MASK);

    const int qt = blockIdx.x, h = blockIdx.y, b = blockIdx.z;
    const int i0 = qt * QT;
    const int tid  = threadIdx.x;
    const int lane = tid & 31;
    const int warp = tid >> 5;
    const int mt   = warp >> 3;
    const int wj   = warp & 7;
    const size_t bh    = (size_t)b*H_ + h;
    const size_t qrow0 = bh*S_ + i0;
    const size_t krow0 = bh*S_;
    const size_t vbase = bh*S_*HD_;

    const int copyrow = tid >> 2;
    const int cq      = (tid & 3) * 16;
    const uint32_t dOff = (uint32_t)(copyrow*144 + cq*2);

    {
        const size_t src = (krow0 + copyrow)*128 + 64 + cq;
        cp16(sbase + KVHI(0) + dOff,      g_qkhi + src);
        cp16(sbase + KVHI(0) + dOff + 16, g_qkhi + src + 8);
        cp16(sbase + KVLO(0) + dOff,      g_qklo + src);
        cp16(sbase + KVLO(0) + dOff + 16, g_qklo + src + 8);
    }
    asm volatile("cp.async.commit_group;");

    for (int i = tid; i < QT*NRELV; i += 512) {
        sB[i] = g_bias[qrow0*NRELV + i];
        sW[i] = 0.f;
    }
    for (int i = tid; i < S_; i += 512) sMask[i] = mask[b*S_ + i];

    uint32_t qah[4][4], qal[4][4];
    {
        const int qr = lane >> 2;
        const int qc = (lane & 3) * 2;
        const size_t qm = qrow0 + mt*16;
        #pragma unroll
        for (int kk = 0; kk < 4; kk++) {
            const size_t r0o = (qm + qr)*128     + kk*16 + qc;
            const size_t r1o = (qm + qr + 8)*128 + kk*16 + qc;
            qah[kk][0] = *(const uint32_t*)&g_qkhi[r0o];
            qah[kk][1] = *(const uint32_t*)&g_qkhi[r1o];
            qah[kk][2] = *(const uint32_t*)&g_qkhi[r0o + 8];
            qah[kk][3] = *(const uint32_t*)&g_qkhi[r1o + 8];
            qal[kk][0] = *(const uint32_t*)&g_qklo[r0o];
            qal[kk][1] = *(const uint32_t*)&g_qklo[r1o];
            qal[kk][2] = *(const uint32_t*)&g_qklo[r0o + 8];
            qal[kk][3] = *(const uint32_t*)&g_qklo[r1o + 8];
        }
    }
    __syncthreads();

    const uint32_t bfragOff =
        (uint32_t)((wj*16 + ((lane >> 4) & 1)*8 + (lane & 7))*144 + ((lane >> 3) & 1)*16);

    for (int jt = 0; jt < 4; jt++) {
        if (jt < 3) {
            const int nb = (jt + 1) & 1;
            const size_t src = (krow0 + (jt+1)*128 + copyrow)*128 + 64 + cq;
            cp16(sbase + KVHI(nb) + dOff,      g_qkhi + src);
            cp16(sbase + KVHI(nb) + dOff + 16, g_qkhi + src + 8);
            cp16(sbase + KVLO(nb) + dOff,      g_qklo + src);
            cp16(sbase + KVLO(nb) + dOff + 16, g_qklo + src + 8);
        } else {
            const size_t src = vbase + (size_t)copyrow*HD_ + cq;
            cp16(sbase + KVHI(0) + dOff,      g_vhi + src);
            cp16(sbase + KVHI(0) + dOff + 16, g_vhi + src + 8);
            cp16(sbase + KVLO(0) + dOff,      g_vlo + src);
            cp16(sbase + KVLO(0) + dOff + 16, g_vlo + src + 8);
        }
        asm volatile("cp.async.commit_group;");
        asm volatile("cp.async.wait_group 1;");
        __syncthreads();

        const uint32_t khA = sbase + KVHI(jt & 1) + bfragOff;
        const uint32_t klA = sbase + KVLO(jt & 1) + bfragOff;
        const int j0 = jt * 128;

        float c[2][4] = {{0,0,0,0},{0,0,0,0}};
        #pragma unroll
        for (int kk = 0; kk < 4; kk++) {
            uint32_t bhf[4], blf[4];
            ldsm_x4(khA + kk*32, bhf[0], bhf[1], bhf[2], bhf[3]);
            ldsm_x4(klA + kk*32, blf[0], blf[1], blf[2], blf[3]);
            mma16816(c[0], qah[kk], bhf[0], bhf[1]);
            mma16816(c[0], qah[kk], blf[0], blf[1]);
            mma16816(c[0], qal[kk], bhf[0], bhf[1]);
            mma16816(c[1], qah[kk], bhf[2], bhf[3]);
            mma16816(c[1], qah[kk], blf[2], blf[3]);
            mma16816(c[1], qal[kk], bhf[2], bhf[3]);
        }
        #pragma unroll
        for (int nt = 0; nt < 2; nt++) {
            const int col = j0 + wj*16 + nt*8 + 2*(lane & 3);
            const int r   = mt*16 + (lane >> 2);
            *(float2*)&sS[r*SSTR + col]     = make_float2(c[nt][0], c[nt][1]);
            *(float2*)&sS[(r+8)*SSTR + col] = make_float2(c[nt][2], c[nt][3]);
        }
        __syncthreads();
    }

    {
        const size_t src = vbase + (size_t)(128 + copyrow)*HD_ + cq;
        cp16(sbase + KVHI(1) + dOff,      g_vhi + src);
        cp16(sbase + KVHI(1) + dOff + 16, g_vhi + src + 8);
        cp16(sbase + KVLO(1) + dOff,      g_vlo + src);
        cp16(sbase + KVLO(1) + dOff + 16, g_vlo + src + 8);
    }
    asm volatile("cp.async.commit_group;");

    for (int i = tid; i < NRELV*HD_; i += 512) sEv[i] = Ev[i];

    const size_t arcbase = ((size_t)b*S_ + i0)*S_;
    {
        uchar4 relreg[2][4];
        #pragma unroll
        for (int rr = 0; rr < 2; rr++) {
            const int row = warp*2 + rr;
            const float* brow = &sB[row*NRELV];
            float m = -3.4e38f;
            #pragma unroll
            for (int it = 0; it < 4; it++) {
                const int j = it*128 + lane*4;
                uchar4 r4 = *(const uchar4*)&g_rel8[arcbase + (size_t)row*S_ + j];
                relreg[rr][it] = r4;
                float4 s4 = *(float4*)&sS[row*SSTR + j];
                s4.x = (s4.x + brow[r4.x]) * 0.125f; if (sMask[j]     == 0) s4.x = -1e30f;
                s4.y = (s4.y + brow[r4.y]) * 0.125f; if (sMask[j + 1] == 0) s4.y = -1e30f;
                s4.z = (s4.z + brow[r4.z]) * 0.125f; if (sMask[j + 2] == 0) s4.z = -1e30f;
                s4.w = (s4.w + brow[r4.w]) * 0.125f; if (sMask[j + 3] == 0) s4.w = -1e30f;
                *(float4*)&sS[row*SSTR + j] = s4;
                m = fmaxf(m, fmaxf(fmaxf(s4.x, s4.y), fmaxf(s4.z, s4.w)));
            }
            #pragma unroll
            for (int o = 16; o; o >>= 1) m = fmaxf(m, __shfl_xor_sync(0xffffffffu, m, o));

            float z = 0.f;
            float* wrow = &sW[row*NRELV];
            #pragma unroll
            for (int it = 0; it < 4; it++) {
                const int j = it*128 + lane*4;
                float4 s4 = *(float4*)&sS[row*SSTR + j];
                float4 p4;
                p4.x = __expf(s4.x - m);
                p4.y = __expf(s4.y - m);
                p4.z = __expf(s4.z - m);
                p4.w = __expf(s4.w - m);
                *(float4*)&sS[row*SSTR + j] = p4;
                z += p4.x + p4.y + p4.z + p4.w;
                uchar4 r4 = relreg[rr][it];
                atomicAdd(&wrow[r4.x], p4.x);
                atomicAdd(&wrow[r4.y], p4.y);
                atomicAdd(&wrow[r4.z], p4.z);
                atomicAdd(&wrow[r4.w], p4.w);
            }
            #pragma unroll
            for (int o = 16; o; o >>= 1) z += __shfl_xor_sync(0xffffffffu, z, o);
            if (lane == 0) sZ[row] = z;
        }
    }
    __syncthreads();

    float c2[8][4];
    #pragma unroll
    for (int nt = 0; nt < 8; nt++)
        #pragma unroll
        for (int j = 0; j < 4; j++) c2[nt][j] = 0.f;

    for (int jt = 0; jt < 4; jt++) {
        if (jt < 3) { asm volatile("cp.async.wait_group 1;"); }
        else        { asm volatile("cp.async.wait_group 0;"); }
        __syncthreads();

        const uint32_t vh = sbase + KVHI(jt & 1);
        const uint32_t vl = sbase + KVLO(jt & 1);
        const int jb = jt*128 + wj*16;
        uint32_t pah[4], pal[4];
        {
            const int pr = mt*16 + (lane >> 2);
            const int pc = (lane & 3) * 2;
            float2 x0 = *(float2*)&sS[pr*SSTR     + jb + pc];
            float2 x1 = *(float2*)&sS[(pr+8)*SSTR + jb + pc];
            float2 x2 = *(float2*)&sS[pr*SSTR     + jb + pc + 8];
            float2 x3 = *(float2*)&sS[(pr+8)*SSTR + jb + pc + 8];
            split2(x0.x, x0.y, pah[0], pal[0]);
            split2(x1.x, x1.y, pah[1], pal[1]);
            split2(x2.x, x2.y, pah[2], pal[2]);
            split2(x3.x, x3.y, pah[3], pal[3]);
        }
        const uint32_t rowoff = (uint32_t)(wj*16 + (lane & 15)) * 144;
        #pragma unroll
        for (int nt = 0; nt < 8; nt++) {
            uint32_t bh0, bh1, bl0, bl1;
            ldsm_x2_trans(vh + rowoff + nt*16, bh0, bh1);
            ldsm_x2_trans(vl + rowoff + nt*16, bl0, bl1);
            mma16816(c2[nt], pah, bh0, bh1);
            mma16816(c2[nt], pah, bl0, bl1);
            mma16816(c2[nt], pal, bh0, bh1);
        }
        __syncthreads();

        if (jt + 2 < 4) {
            const int nb = jt & 1;
            const size_t src = vbase + (size_t)((jt+2)*128 + copyrow)*HD_ + cq;
            cp16(sbase + KVHI(nb) + dOff,      g_vhi + src);
            cp16(sbase + KVHI(nb) + dOff + 16, g_vhi + src + 8);
            cp16(sbase + KVLO(nb) + dOff,      g_vlo + src);
            cp16(sbase + KVLO(nb) + dOff + 16, g_vlo + src + 8);
            asm volatile("cp.async.commit_group;");
        }
    }

    {
        float* red = sS;
        const int r = lane >> 2;
        #pragma unroll
        for (int nt = 0; nt < 8; nt++) {
            const int col = nt*8 + 2*(lane & 3);
            red[warp*1024 + r*64 + col]       = c2[nt][0];
            red[warp*1024 + r*64 + col + 1]   = c2[nt][1];
            red[warp*1024 + (r+8)*64 + col]   = c2[nt][2];
            red[warp*1024 + (r+8)*64 + col+1] = c2[nt][3];
        }
    }
    __syncthreads();

    {
        const int row = tid >> 4;
        const int e0  = (tid & 15) * 4;
        const int rmt = row >> 4, rl = row & 15;
        float4 acc = make_float4(0,0,0,0);
        #pragma unroll
        for (int w = 0; w < 8; w++) {
            float4 p = *(float4*)&sS[(rmt*8 + w)*1024 + rl*64 + e0];
            acc.x += p.x; acc.y += p.y; acc.z += p.z; acc.w += p.w;
        }
        const float* wrow = &sW[row*NRELV];
        for (int rel = 0; rel < NRELV; rel++) {
            float wv = wrow[rel];
            float4 ev = *(float4*)&sEv[rel*64 + e0];
            acc.x += wv*ev.x; acc.y += wv*ev.y; acc.z += wv*ev.z; acc.w += wv*ev.w;
        }
        const float rz = 1.f / sZ[row];
        acc.x *= rz; acc.y *= rz; acc.z *= rz; acc.w *= rz;

        uint32_t h0, l0, h1, l1;
        split2(acc.x, acc.y, h0, l0);
        split2(acc.z, acc.w, h1, l1);
        const size_t o = ((size_t)(b*S_ + i0 + row))*D_ + h*HD_ + e0;
        *(uint2*)&g_chi[o] = make_uint2(h0, h1);
        *(uint2*)&g_clo[o] = make_uint2(l0, l1);
    }
}

// ---------------- launch --------------------------------------------------------
extern "C" void kernel_launch(void* const* d_in, const int* in_sizes, int n_in,
                              void* d_out, int out_size)
{
    (void)in_sizes; (void)n_in; (void)out_size;
    const float* query = (const float*)d_in[0];
    const float* key_  = (const float*)d_in[1];
    const float* value = (const float*)d_in[2];
    const int*   mask  = (const int*)d_in[3];
    const void*  arc   = d_in[4];
    const float* bq = (const float*)d_in[6];
    const float* bk = (const float*)d_in[8];
    const float* bv = (const float*)d_in[10];
    const float* bo = (const float*)d_in[12];
    const float* Ek = (const float*)d_in[13];
    const float* Eq = (const float*)d_in[14];
    const float* Ev = (const float*)d_in[15];
    float* out = (float*)d_out;

    cudaFuncSetAttribute(attn_kernel, cudaFuncAttributeMaxDynamicSharedMemorySize, SMEM_ATTN);
    cudaFuncSetAttribute(mma_gemm_kernel<0>, cudaFuncAttributeMaxDynamicSharedMemorySize, 2*GSTAGE);
    cudaFuncSetAttribute(mma_gemm_kernel<1>, cudaFuncAttributeMaxDynamicSharedMemorySize, 2*GSTAGE);
    cudaFuncSetAttribute(bias_mma_kernel, cudaFuncAttributeMaxDynamicSharedMemorySize, BSM_TOT);

    __nv_bfloat16 *xhi, *xlo, *whi, *wlo;
    cudaGetSymbolAddress((void**)&xhi, g_xhi);
    cudaGetSymbolAddress((void**)&xlo, g_xlo);
    cudaGetSymbolAddress((void**)&whi, g_whi);
    cudaGetSymbolAddress((void**)&wlo, g_wlo);

    detect_kernel<<<1, 256>>>((const int*)arc);

    PrepArgs pa;
    const float* srcs[7] = {query, key_, value,
                            (const float*)d_in[5], (const float*)d_in[7],
                            (const float*)d_in[9], (const float*)d_in[11]};
    for (int i = 0; i < 7; i++) {
        pa.src[i] = srcs[i];
        if (i < 3) {
            pa.hi[i] = xhi + (size_t)i*XN;
            pa.lo[i] = xlo + (size_t)i*XN;
            pa.n[i]  = XN;
        } else {
            pa.hi[i] = whi + (size_t)(i-3)*WN;
            pa.lo[i] = wlo + (size_t)(i-3)*WN;
            pa.n[i]  = WN;
        }
    }
    pa.Ek = Ek; pa.Eq = Eq; pa.arc = arc;
    prep_kernel<<<dim3((XN/4 + 255)/256, 9), 256>>>(pa);

    dim3 qkvGrid(D_/BN, (B_*S_)/BM, 3);
    mma_gemm_kernel<0><<<qkvGrid, 256, 2*GSTAGE>>>(bq, bk, bv, nullptr);

    bias_mma_kernel<<<dim3(8, H_, B_), 256, BSM_TOT>>>();
    attn_kernel<<<dim3(S_/QT, H_, B_), 512, SMEM_ATTN>>>(mask, Ev);

    dim3 oGrid(D_/BN, (B_*S_)/BM, 1);
    mma_gemm_kernel<1><<<oGrid, 256, 2*GSTAGE>>>(bo, nullptr, nullptr, out);
}

// round 17
// speedup vs baseline: 1.1003x; 1.0353x over previous
#include <cuda_runtime.h>
#include <cuda_bf16.h>
#include <cstdint>
#include <cstddef>

#define B_    4
#define S_    512
#define D_    768
#define H_    12
#define HD_   64
#define NRELV 101
#define EROWS 112
#define XN    (B_*S_*D_)
#define WN    (D_*D_)

#define BM    128
#define BN    128
#define BK    32
#define GSTAGE 40960       // bytes per gemm pipeline stage

// ---------------- scratch ------------------------------------------------------
__device__ __nv_bfloat16 g_qkhi[(size_t)B_*H_*S_*128], g_qklo[(size_t)B_*H_*S_*128];
__device__ __nv_bfloat16 g_vhi[XN], g_vlo[XN];
__device__ __nv_bfloat16 g_xhi[3*XN], g_xlo[3*XN];
__device__ __nv_bfloat16 g_whi[4*WN], g_wlo[4*WN];
__device__ __nv_bfloat16 g_chi[XN], g_clo[XN];
__device__ __nv_bfloat16 g_ehi[EROWS*128], g_elo[EROWS*128];
__device__ uint8_t g_rel8[(size_t)B_*S_*S_];
__device__ int     g_arc_is64;

// ---------------- helpers ------------------------------------------------------
__device__ __forceinline__ void split2(float a, float b, uint32_t& hi, uint32_t& lo)
{
    __nv_bfloat16 h0 = __float2bfloat16(a);
    __nv_bfloat16 h1 = __float2bfloat16(b);
    __nv_bfloat16 l0 = __float2bfloat16(a - __bfloat162float(h0));
    __nv_bfloat16 l1 = __float2bfloat16(b - __bfloat162float(h1));
    hi = (uint32_t)*(unsigned short*)&h0 | ((uint32_t)*(unsigned short*)&h1 << 16);
    lo = (uint32_t)*(unsigned short*)&l0 | ((uint32_t)*(unsigned short*)&l1 << 16);
}

__device__ __forceinline__ void ldsm_x4(uint32_t addr, uint32_t& r0, uint32_t& r1,
                                        uint32_t& r2, uint32_t& r3)
{
    asm volatile("ldmatrix.sync.aligned.m8n8.x4.shared.b16 {%0,%1,%2,%3}, [%4];"
                 : "=r"(r0), "=r"(r1), "=r"(r2), "=r"(r3) : "r"(addr));
}

__device__ __forceinline__ void ldsm_x2_trans(uint32_t addr, uint32_t& r0, uint32_t& r1)
{
    asm volatile("ldmatrix.sync.aligned.m8n8.x2.trans.shared.b16 {%0,%1}, [%2];"
                 : "=r"(r0), "=r"(r1) : "r"(addr));
}

__device__ __forceinline__ void mma16816(float* c, const uint32_t* a,
                                         uint32_t b0, uint32_t b1)
{
    asm volatile(
        "mma.sync.aligned.m16n8k16.row.col.f32.bf16.bf16.f32 "
        "{%0,%1,%2,%3}, {%4,%5,%6,%7}, {%8,%9}, {%0,%1,%2,%3};"
        : "+f"(c[0]), "+f"(c[1]), "+f"(c[2]), "+f"(c[3])
        : "r"(a[0]), "r"(a[1]), "r"(a[2]), "r"(a[3]), "r"(b0), "r"(b1));
}

__device__ __forceinline__ void cp16(uint32_t dst, const void* src)
{
    asm volatile("cp.async.ca.shared.global [%0], [%1], 16;" :: "r"(dst), "l"(src));
}

// ---------------- graph_arc dtype detection ------------------------------------
__global__ void detect_kernel(const int* __restrict__ arc32)
{
    __shared__ int cnt;
    if (threadIdx.x == 0) cnt = 0;
    __syncthreads();
    int local = 0;
    for (int i = threadIdx.x; i < 1024; i += blockDim.x)
        if (arc32[2*i + 1] != 0) local++;
    if (local) atomicAdd(&cnt, local);
    __syncthreads();
    if (threadIdx.x == 0) g_arc_is64 = (cnt == 0) ? 1 : 0;
}

// ---------------- merged prepass: splits (y=0..6), ebuild (y=7), rel8 (y=8) -----
struct PrepArgs {
    const float*   src[7];
    __nv_bfloat16* hi[7];
    __nv_bfloat16* lo[7];
    int            n[7];
    const float*   Ek;
    const float*   Eq;
    const void*    arc;
};

__global__ void __launch_bounds__(256)
prep_kernel(PrepArgs a)
{
    const int w = blockIdx.y;
    const int t = blockIdx.x * 256 + threadIdx.x;

    if (w < 7) {
        const int i = t * 4;
        if (i >= a.n[w]) return;
        float4 v = *(const float4*)(a.src[w] + i);
        uint32_t h0, l0, h1, l1;
        split2(v.x, v.y, h0, l0);
        split2(v.z, v.w, h1, l1);
        *(uint2*)(a.hi[w] + i) = make_uint2(h0, h1);
        *(uint2*)(a.lo[w] + i) = make_uint2(l0, l1);
    } else if (w == 7) {
        if (t >= EROWS*128) return;
        int row = t >> 7, col = t & 127;
        float v = 0.f;
        if (row < NRELV) v = (col < 64) ? a.Ek[row*64 + col] : a.Eq[row*64 + col - 64];
        __nv_bfloat16 hv = __float2bfloat16(v);
        __nv_bfloat16 lv = __float2bfloat16(v - __bfloat162float(hv));
        g_ehi[t] = hv;
        g_elo[t] = lv;
    } else {
        const size_t i = (size_t)t * 4;
        if (i >= (size_t)B_*S_*S_) return;
        uchar4 r;
        if (g_arc_is64) {
            const long long* p = (const long long*)a.arc + i;
            r = make_uchar4((uint8_t)p[0], (uint8_t)p[1], (uint8_t)p[2], (uint8_t)p[3]);
        } else {
            const int* p = (const int*)a.arc + i;
            r = make_uchar4((uint8_t)p[0], (uint8_t)p[1], (uint8_t)p[2], (uint8_t)p[3]);
        }
        *(uchar4*)&g_rel8[i] = r;
    }
}

// ---------------- tensor-core GEMM, cp.async 2-stage pipeline -------------------
template<int MODE>
__global__ void __launch_bounds__(256, 2)
mma_gemm_kernel(const float* __restrict__ bias0, const float* __restrict__ bias1,
                const float* __restrict__ bias2, float* __restrict__ out1)
{
    extern __shared__ char gsm[];
    const uint32_t smemBase = (uint32_t)__cvta_generic_to_shared(gsm);

    const int z = (MODE == 0) ? blockIdx.z : 0;
    const __nv_bfloat16 *Xhi, *Xlo, *Whi, *Wlo;
    const float* bias;
    if (MODE == 0) {
        Xhi = g_xhi + (size_t)z*XN;  Xlo = g_xlo + (size_t)z*XN;
        Whi = g_whi + (size_t)z*WN;  Wlo = g_wlo + (size_t)z*WN;
        bias = (z == 0) ? bias0 : (z == 1) ? bias1 : bias2;
    } else {
        Xhi = g_chi;  Xlo = g_clo;
        Whi = g_whi + (size_t)3*WN;  Wlo = g_wlo + (size_t)3*WN;
        bias = bias0;
    }

    const int tid  = threadIdx.x;
    const int lane = tid & 31;
    const int warp = tid >> 5;
    const int wm   = warp & 3;
    const int wn   = warp >> 2;
    const int m0   = blockIdx.y * BM;
    const int n0   = blockIdx.x * BN;

    float acc[2][8][4];
    #pragma unroll
    for (int mt = 0; mt < 2; mt++)
        #pragma unroll
        for (int nt = 0; nt < 8; nt++)
            #pragma unroll
            for (int j = 0; j < 4; j++) acc[mt][nt][j] = 0.f;

    const int mat = lane >> 3, mr = lane & 7;
    const uint32_t aOffHi = (uint32_t)((wm*32 + (mat & 1)*8 + mr)*80 + ((mat >> 1)*8)*2);
    const uint32_t bOffHi = 20480u + (uint32_t)((wn*64 + (mat >> 1)*8 + mr)*80 + ((mat & 1)*8)*2);

    const int ldrow = tid >> 1;
    const int ldq   = (tid & 1) * 2;
    const uint32_t xDst = (uint32_t)(ldrow*80 + ldq*16);
    const uint32_t wDst = 20480u + xDst;

    #pragma unroll
    for (int u = 0; u < 2; u++) {
        const size_t xo = (size_t)(m0 + ldrow)*D_ + (ldq + u)*8;
        const size_t wo = (size_t)(n0 + ldrow)*D_ + (ldq + u)*8;
        cp16(smemBase + xDst + u*16,          Xhi + xo);
        cp16(smemBase + 10240 + xDst + u*16,  Xlo + xo);
        cp16(smemBase + wDst + u*16,          Whi + wo);
        cp16(smemBase + 10240 + wDst + u*16,  Wlo + wo);
    }
    asm volatile("cp.async.commit_group;");

    const int NK = D_ / BK;
    for (int kt = 0; kt < NK; kt++) {
        asm volatile("cp.async.wait_group 0;");
        __syncthreads();

        if (kt + 1 < NK) {
            const uint32_t sb2 = smemBase + (uint32_t)(((kt + 1) & 1) * GSTAGE);
            const int k0 = (kt + 1) * BK;
            #pragma unroll
            for (int u = 0; u < 2; u++) {
                const size_t xo = (size_t)(m0 + ldrow)*D_ + k0 + (ldq + u)*8;
                const size_t wo = (size_t)(n0 + ldrow)*D_ + k0 + (ldq + u)*8;
                cp16(sb2 + xDst + u*16,          Xhi + xo);
                cp16(sb2 + 10240 + xDst + u*16,  Xlo + xo);
                cp16(sb2 + wDst + u*16,          Whi + wo);
                cp16(sb2 + 10240 + wDst + u*16,  Wlo + wo);
            }
        }
        asm volatile("cp.async.commit_group;");

        const uint32_t sb = smemBase + (uint32_t)((kt & 1) * GSTAGE);
        #pragma unroll
        for (int ks = 0; ks < 2; ks++) {
            const uint32_t ko = ks * 32;
            uint32_t ah[2][4], al[2][4];
            #pragma unroll
            for (int mt = 0; mt < 2; mt++) {
                const uint32_t mo = mt * 1280;
                ldsm_x4(sb + aOffHi + mo + ko,          ah[mt][0], ah[mt][1], ah[mt][2], ah[mt][3]);
                ldsm_x4(sb + aOffHi + 10240 + mo + ko,  al[mt][0], al[mt][1], al[mt][2], al[mt][3]);
            }
            #pragma unroll
            for (int pr = 0; pr < 4; pr++) {
                const uint32_t po = pr * 1280;
                uint32_t bh[4], bl[4];
                ldsm_x4(sb + bOffHi + po + ko,          bh[0], bh[1], bh[2], bh[3]);
                ldsm_x4(sb + bOffHi + 10240 + po + ko,  bl[0], bl[1], bl[2], bl[3]);
                #pragma unroll
                for (int h2 = 0; h2 < 2; h2++) {
                    const int nt = pr*2 + h2;
                    #pragma unroll
                    for (int mt = 0; mt < 2; mt++) {
                        mma16816(acc[mt][nt], ah[mt], bh[h2*2], bh[h2*2+1]);
                        mma16816(acc[mt][nt], ah[mt], bl[h2*2], bl[h2*2+1]);
                        mma16816(acc[mt][nt], al[mt], bh[h2*2], bh[h2*2+1]);
                    }
                }
            }
        }
    }

    const int gid = lane >> 2, tig = lane & 3;
    #pragma unroll
    for (int mt = 0; mt < 2; mt++) {
        const int rbase = m0 + wm*32 + mt*16 + gid;
        #pragma unroll
        for (int nt = 0; nt < 8; nt++) {
            const int col = n0 + wn*64 + nt*8 + tig*2;
            const float b0v = bias[col], b1v = bias[col+1];
            float v00 = acc[mt][nt][0] + b0v;
            float v01 = acc[mt][nt][1] + b1v;
            float v10 = acc[mt][nt][2] + b0v;
            float v11 = acc[mt][nt][3] + b1v;
            if (MODE == 0) {
                const int hh = col >> 6, e = col & 63;
                #pragma unroll
                for (int half = 0; half < 2; half++) {
                    const int r = rbase + half*8;
                    const int b = r >> 9, s = r & (S_-1);
                    const size_t rowb = (size_t)(b*H_ + hh)*S_ + s;
                    const float va = half ? v10 : v00;
                    const float vb = half ? v11 : v01;
                    uint32_t hi, lo; split2(va, vb, hi, lo);
                    if (z == 0) {
                        *(uint32_t*)&g_qkhi[rowb*128 + e] = hi;
                        *(uint32_t*)&g_qklo[rowb*128 + e] = lo;
                    } else if (z == 1) {
                        *(uint32_t*)&g_qkhi[rowb*128 + 64 + e] = hi;
                        *(uint32_t*)&g_qklo[rowb*128 + 64 + e] = lo;
                    } else {
                        *(uint32_t*)&g_vhi[rowb*64 + e] = hi;
                        *(uint32_t*)&g_vlo[rowb*64 + e] = lo;
                    }
                }
            } else {
                out1[(size_t)rbase*D_ + col]       = v00;
                out1[(size_t)rbase*D_ + col + 1]   = v01;
                out1[(size_t)(rbase+8)*D_ + col]   = v10;
                out1[(size_t)(rbase+8)*D_ + col+1] = v11;
            }
        }
    }
}

// ---------------- fused attention: QT=32, fused bias GEMM + scalar phases -------
#define QT    32
#define SSTR  520
#define OFF_SS    0
#define OFF_EHI   0                        // E hi (112x272) reuses sS region
#define OFF_ELO   30464                    // E lo -> ends 60928 < 66560
#define KVHI(bf)  (66560u + (uint32_t)(bf)*36864u)
#define KVLO(bf)  (84992u + (uint32_t)(bf)*36864u)
#define OFF_AHI   KVHI(1)                  // A qk rows (32x272) hi, reuses buf1
#define OFF_ALO   (KVHI(1) + 17408u)       // A lo -> ends 138240 < 140288
#define OFF_SB    140288
#define OFF_SW    153216
#define OFF_SZ    166144
#define OFF_MASK  166272
#define OFF_EV    168320
#define SMEM_ATTN 194176

__global__ void __launch_bounds__(512, 1)
attn_kernel(const int* __restrict__ mask, const float* __restrict__ Ev)
{
    extern __shared__ char smraw[];
    const uint32_t sbase = (uint32_t)__cvta_generic_to_shared(smraw);
    float* sS    = (float*)(smraw + OFF_SS);
    float* sEv   = (float*)(smraw + OFF_EV);
    float* sB    = (float*)(smraw + OFF_SB);
    float* sW    = (float*)(smraw + OFF_SW);
    float* sZ    = (float*)(smraw + OFF_SZ);
    int*   sMask = (int*)  (smraw + OFF_MASK);

    const int qt = blockIdx.x, h = blockIdx.y, b = blockIdx.z;
    const int i0 = qt * QT;
    const int tid  = threadIdx.x;
    const int lane = tid & 31;
    const int warp = tid >> 5;
    const int mt   = warp >> 3;
    const int wj   = warp & 7;
    const size_t bh    = (size_t)b*H_ + h;
    const size_t qrow0 = bh*S_ + i0;
    const size_t krow0 = bh*S_;
    const size_t vbase = bh*S_*HD_;

    const int copyrow = tid >> 2;
    const int cq      = (tid & 3) * 16;
    const uint32_t dOff = (uint32_t)(copyrow*144 + cq*2);

    // ---- K tile 0 into buf0 (group 0) ----
    {
        const size_t src = (krow0 + copyrow)*128 + 64 + cq;
        cp16(sbase + KVHI(0) + dOff,      g_qkhi + src);
        cp16(sbase + KVHI(0) + dOff + 16, g_qkhi + src + 8);
        cp16(sbase + KVLO(0) + dOff,      g_qklo + src);
        cp16(sbase + KVLO(0) + dOff + 16, g_qklo + src + 8);
    }
    asm volatile("cp.async.commit_group;");

    // ---- E (112x128 hi/lo) into sS region + A qk rows (32x128 hi/lo) into buf1 ----
    {
        const int i = tid;                  // 448 slots for E
        if (i < EROWS*4) {
            const int row = i >> 2;
            const int q   = (i & 3) * 32;
            const uint32_t d = (uint32_t)(row*272 + q*2);
            const size_t  s = (size_t)row*128 + q;
            #pragma unroll
            for (int u = 0; u < 4; u++) {
                cp16(sbase + OFF_EHI + d + u*16, g_ehi + s + u*8);
                cp16(sbase + OFF_ELO + d + u*16, g_elo + s + u*8);
            }
        }
        if (tid < 32*4) {                   // 128 slots for A
            const int row = tid >> 2;
            const int q   = (tid & 3) * 32;
            const uint32_t d = (uint32_t)(row*272 + q*2);
            const size_t  s = (qrow0 + row)*128 + q;
            #pragma unroll
            for (int u = 0; u < 4; u++) {
                cp16(sbase + OFF_AHI + d + u*16, g_qkhi + s + u*8);
                cp16(sbase + OFF_ALO + d + u*16, g_qklo + s + u*8);
            }
        }
    }
    asm volatile("cp.async.commit_group;");

    for (int i = tid; i < QT*NRELV; i += 512) sW[i] = 0.f;
    for (int i = tid; i < S_; i += 512) sMask[i] = mask[b*S_ + i];

    // ---- Q A-fragments from global (overlaps cp.async) ----
    uint32_t qah[4][4], qal[4][4];
    {
        const int qr = lane >> 2;
        const int qc = (lane & 3) * 2;
        const size_t qm = qrow0 + mt*16;
        #pragma unroll
        for (int kk = 0; kk < 4; kk++) {
            const size_t r0o = (qm + qr)*128     + kk*16 + qc;
            const size_t r1o = (qm + qr + 8)*128 + kk*16 + qc;
            qah[kk][0] = *(const uint32_t*)&g_qkhi[r0o];
            qah[kk][1] = *(const uint32_t*)&g_qkhi[r1o];
            qah[kk][2] = *(const uint32_t*)&g_qkhi[r0o + 8];
            qah[kk][3] = *(const uint32_t*)&g_qkhi[r1o + 8];
            qal[kk][0] = *(const uint32_t*)&g_qklo[r0o];
            qal[kk][1] = *(const uint32_t*)&g_qklo[r1o];
            qal[kk][2] = *(const uint32_t*)&g_qklo[r0o + 8];
            qal[kk][3] = *(const uint32_t*)&g_qklo[r1o + 8];
        }
    }

    asm volatile("cp.async.wait_group 0;");
    __syncthreads();

    // ---- fused bias GEMM: sB[row, rel] = A(32x128) . E(112x128)^T ----
    {
        const int mt2 = warp & 1;           // 2 m16-tiles
        const int pr  = warp >> 1;          // 7 n16-tiles (warps 14,15 idle)
        if (pr < 7) {
            float bacc[2][4];
            #pragma unroll
            for (int h2 = 0; h2 < 2; h2++)
                #pragma unroll
                for (int j = 0; j < 4; j++) bacc[h2][j] = 0.f;

            const int bmat = lane >> 3, bmr = lane & 7;
            const uint32_t aOff = (uint32_t)((mt2*16 + (bmat & 1)*8 + bmr)*272
                                             + ((bmat >> 1)*8)*2);
            const uint32_t bOff = (uint32_t)(((bmat >> 1)*8 + bmr)*272
                                             + ((bmat & 1)*8)*2)
                                + (uint32_t)pr * (16*272);
            #pragma unroll
            for (int kk = 0; kk < 8; kk++) {
                const uint32_t ko = kk * 32;
                uint32_t ah[4], al[4], bhf[4], blf[4];
                ldsm_x4(sbase + OFF_AHI + aOff + ko, ah[0], ah[1], ah[2], ah[3]);
                ldsm_x4(sbase + OFF_ALO + aOff + ko, al[0], al[1], al[2], al[3]);
                ldsm_x4(sbase + OFF_EHI + bOff + ko, bhf[0], bhf[1], bhf[2], bhf[3]);
                ldsm_x4(sbase + OFF_ELO + bOff + ko, blf[0], blf[1], blf[2], blf[3]);
                #pragma unroll
                for (int h2 = 0; h2 < 2; h2++) {
                    mma16816(bacc[h2], ah, bhf[h2*2], bhf[h2*2+1]);
                    mma16816(bacc[h2], ah, blf[h2*2], blf[h2*2+1]);
                    mma16816(bacc[h2], al, bhf[h2*2], bhf[h2*2+1]);
                }
            }
            const int gid = lane >> 2, tig = lane & 3;
            #pragma unroll
            for (int h2 = 0; h2 < 2; h2++) {
                const int col = pr*16 + h2*8 + tig*2;
                #pragma unroll
                for (int half = 0; half < 2; half++) {
                    const int row = mt2*16 + half*8 + gid;
                    if (col < NRELV)     sB[row*NRELV + col]     = bacc[h2][half*2];
                    if (col + 1 < NRELV) sB[row*NRELV + col + 1] = bacc[h2][half*2+1];
                }
            }
        }
    }
    __syncthreads();

    const uint32_t bfragOff =
        (uint32_t)((wj*16 + ((lane >> 4) & 1)*8 + (lane & 7))*144 + ((lane >> 3) & 1)*16);

    // ---- pass 1: S = Q K^T, double-buffered ----
    for (int jt = 0; jt < 4; jt++) {
        if (jt < 3) {
            const int nb = (jt + 1) & 1;
            const size_t src = (krow0 + (jt+1)*128 + copyrow)*128 + 64 + cq;
            cp16(sbase + KVHI(nb) + dOff,      g_qkhi + src);
            cp16(sbase + KVHI(nb) + dOff + 16, g_qkhi + src + 8);
            cp16(sbase + KVLO(nb) + dOff,      g_qklo + src);
            cp16(sbase + KVLO(nb) + dOff + 16, g_qklo + src + 8);
        } else {
            const size_t src = vbase + (size_t)copyrow*HD_ + cq;
            cp16(sbase + KVHI(0) + dOff,      g_vhi + src);
            cp16(sbase + KVHI(0) + dOff + 16, g_vhi + src + 8);
            cp16(sbase + KVLO(0) + dOff,      g_vlo + src);
            cp16(sbase + KVLO(0) + dOff + 16, g_vlo + src + 8);
        }
        asm volatile("cp.async.commit_group;");
        asm volatile("cp.async.wait_group 1;");
        __syncthreads();

        const uint32_t khA = sbase + KVHI(jt & 1) + bfragOff;
        const uint32_t klA = sbase + KVLO(jt & 1) + bfragOff;
        const int j0 = jt * 128;

        float c[2][4] = {{0,0,0,0},{0,0,0,0}};
        #pragma unroll
        for (int kk = 0; kk < 4; kk++) {
            uint32_t bhf[4], blf[4];
            ldsm_x4(khA + kk*32, bhf[0], bhf[1], bhf[2], bhf[3]);
            ldsm_x4(klA + kk*32, blf[0], blf[1], blf[2], blf[3]);
            mma16816(c[0], qah[kk], bhf[0], bhf[1]);
            mma16816(c[0], qah[kk], blf[0], blf[1]);
            mma16816(c[0], qal[kk], bhf[0], bhf[1]);
            mma16816(c[1], qah[kk], bhf[2], bhf[3]);
            mma16816(c[1], qah[kk], blf[2], blf[3]);
            mma16816(c[1], qal[kk], bhf[2], bhf[3]);
        }
        #pragma unroll
        for (int nt = 0; nt < 2; nt++) {
            const int col = j0 + wj*16 + nt*8 + 2*(lane & 3);
            const int r   = mt*16 + (lane >> 2);
            *(float2*)&sS[r*SSTR + col]     = make_float2(c[nt][0], c[nt][1]);
            *(float2*)&sS[(r+8)*SSTR + col] = make_float2(c[nt][2], c[nt][3]);
        }
        __syncthreads();
    }

    // prefetch V tile 1 into buf1
    {
        const size_t src = vbase + (size_t)(128 + copyrow)*HD_ + cq;
        cp16(sbase + KVHI(1) + dOff,      g_vhi + src);
        cp16(sbase + KVHI(1) + dOff + 16, g_vhi + src + 8);
        cp16(sbase + KVLO(1) + dOff,      g_vlo + src);
        cp16(sbase + KVLO(1) + dOff + 16, g_vlo + src + 8);
    }
    asm volatile("cp.async.commit_group;");

    for (int i = tid; i < NRELV*HD_; i += 512) sEv[i] = Ev[i];

    const size_t arcbase = ((size_t)b*S_ + i0)*S_;
    {
        uchar4 relreg[2][4];
        #pragma unroll
        for (int rr = 0; rr < 2; rr++) {
            const int row = warp*2 + rr;
            const float* brow = &sB[row*NRELV];
            float m = -3.4e38f;
            #pragma unroll
            for (int it = 0; it < 4; it++) {
                const int j = it*128 + lane*4;
                uchar4 r4 = *(const uchar4*)&g_rel8[arcbase + (size_t)row*S_ + j];
                relreg[rr][it] = r4;
                float4 s4 = *(float4*)&sS[row*SSTR + j];
                s4.x = (s4.x + brow[r4.x]) * 0.125f; if (sMask[j]     == 0) s4.x = -1e30f;
                s4.y = (s4.y + brow[r4.y]) * 0.125f; if (sMask[j + 1] == 0) s4.y = -1e30f;
                s4.z = (s4.z + brow[r4.z]) * 0.125f; if (sMask[j + 2] == 0) s4.z = -1e30f;
                s4.w = (s4.w + brow[r4.w]) * 0.125f; if (sMask[j + 3] == 0) s4.w = -1e30f;
                *(float4*)&sS[row*SSTR + j] = s4;
                m = fmaxf(m, fmaxf(fmaxf(s4.x, s4.y), fmaxf(s4.z, s4.w)));
            }
            #pragma unroll
            for (int o = 16; o; o >>= 1) m = fmaxf(m, __shfl_xor_sync(0xffffffffu, m, o));

            float z = 0.f;
            float* wrow = &sW[row*NRELV];
            #pragma unroll
            for (int it = 0; it < 4; it++) {
                const int j = it*128 + lane*4;
                float4 s4 = *(float4*)&sS[row*SSTR + j];
                float4 p4;
                p4.x = __expf(s4.x - m);
                p4.y = __expf(s4.y - m);
                p4.z = __expf(s4.z - m);
                p4.w = __expf(s4.w - m);
                *(float4*)&sS[row*SSTR + j] = p4;
                z += p4.x + p4.y + p4.z + p4.w;
                uchar4 r4 = relreg[rr][it];
                atomicAdd(&wrow[r4.x], p4.x);
                atomicAdd(&wrow[r4.y], p4.y);
                atomicAdd(&wrow[r4.z], p4.z);
                atomicAdd(&wrow[r4.w], p4.w);
            }
            #pragma unroll
            for (int o = 16; o; o >>= 1) z += __shfl_xor_sync(0xffffffffu, z, o);
            if (lane == 0) sZ[row] = z;
        }
    }
    __syncthreads();

    float c2[8][4];
    #pragma unroll
    for (int nt = 0; nt < 8; nt++)
        #pragma unroll
        for (int j = 0; j < 4; j++) c2[nt][j] = 0.f;

    for (int jt = 0; jt < 4; jt++) {
        if (jt < 3) { asm volatile("cp.async.wait_group 1;"); }
        else        { asm volatile("cp.async.wait_group 0;"); }
        __syncthreads();

        const uint32_t vh = sbase + KVHI(jt & 1);
        const uint32_t vl = sbase + KVLO(jt & 1);
        const int jb = jt*128 + wj*16;
        uint32_t pah[4], pal[4];
        {
            const int pr = mt*16 + (lane >> 2);
            const int pc = (lane & 3) * 2;
            float2 x0 = *(float2*)&sS[pr*SSTR     + jb + pc];
            float2 x1 = *(float2*)&sS[(pr+8)*SSTR + jb + pc];
            float2 x2 = *(float2*)&sS[pr*SSTR     + jb + pc + 8];
            float2 x3 = *(float2*)&sS[(pr+8)*SSTR + jb + pc + 8];
            split2(x0.x, x0.y, pah[0], pal[0]);
            split2(x1.x, x1.y, pah[1], pal[1]);
            split2(x2.x, x2.y, pah[2], pal[2]);
            split2(x3.x, x3.y, pah[3], pal[3]);
        }
        const uint32_t rowoff = (uint32_t)(wj*16 + (lane & 15)) * 144;
        #pragma unroll
        for (int nt = 0; nt < 8; nt++) {
            uint32_t bh0, bh1, bl0, bl1;
            ldsm_x2_trans(vh + rowoff + nt*16, bh0, bh1);
            ldsm_x2_trans(vl + rowoff + nt*16, bl0, bl1);
            mma16816(c2[nt], pah, bh0, bh1);
            mma16816(c2[nt], pah, bl0, bl1);
            mma16816(c2[nt], pal, bh0, bh1);
        }
        __syncthreads();

        if (jt + 2 < 4) {
            const int nb = jt & 1;
            const size_t src = vbase + (size_t)((jt+2)*128 + copyrow)*HD_ + cq;
            cp16(sbase + KVHI(nb) + dOff,      g_vhi + src);
            cp16(sbase + KVHI(nb) + dOff + 16, g_vhi + src + 8);
            cp16(sbase + KVLO(nb) + dOff,      g_vlo + src);
            cp16(sbase + KVLO(nb) + dOff + 16, g_vlo + src + 8);
            asm volatile("cp.async.commit_group;");
        }
    }

    {
        float* red = sS;
        const int r = lane >> 2;
        #pragma unroll
        for (int nt = 0; nt < 8; nt++) {
            const int col = nt*8 + 2*(lane & 3);
            red[warp*1024 + r*64 + col]       = c2[nt][0];
            red[warp*1024 + r*64 + col + 1]   = c2[nt][1];
            red[warp*1024 + (r+8)*64 + col]   = c2[nt][2];
            red[warp*1024 + (r+8)*64 + col+1] = c2[nt][3];
        }
    }
    __syncthreads();

    {
        const int row = tid >> 4;
        const int e0  = (tid & 15) * 4;
        const int rmt = row >> 4, rl = row & 15;
        float4 acc = make_float4(0,0,0,0);
        #pragma unroll
        for (int w = 0; w < 8; w++) {
            float4 p = *(float4*)&sS[(rmt*8 + w)*1024 + rl*64 + e0];
            acc.x += p.x; acc.y += p.y; acc.z += p.z; acc.w += p.w;
        }
        const float* wrow = &sW[row*NRELV];
        for (int rel = 0; rel < NRELV; rel++) {
            float wv = wrow[rel];
            float4 ev = *(float4*)&sEv[rel*64 + e0];
            acc.x += wv*ev.x; acc.y += wv*ev.y; acc.z += wv*ev.z; acc.w += wv*ev.w;
        }
        const float rz = 1.f / sZ[row];
        acc.x *= rz; acc.y *= rz; acc.z *= rz; acc.w *= rz;

        uint32_t h0, l0, h1, l1;
        split2(acc.x, acc.y, h0, l0);
        split2(acc.z, acc.w, h1, l1);
        const size_t o = ((size_t)(b*S_ + i0 + row))*D_ + h*HD_ + e0;
        *(uint2*)&g_chi[o] = make_uint2(h0, h1);
        *(uint2*)&g_clo[o] = make_uint2(l0, l1);
    }
}

// ---------------- launch --------------------------------------------------------
extern "C" void kernel_launch(void* const* d_in, const int* in_sizes, int n_in,
                              void* d_out, int out_size)
{
    (void)in_sizes; (void)n_in; (void)out_size;
    const float* query = (const float*)d_in[0];
    const float* key_  = (const float*)d_in[1];
    const float* value = (const float*)d_in[2];
    const int*   mask  = (const int*)d_in[3];
    const void*  arc   = d_in[4];
    const float* bq = (const float*)d_in[6];
    const float* bk = (const float*)d_in[8];
    const float* bv = (const float*)d_in[10];
    const float* bo = (const float*)d_in[12];
    const float* Ek = (const float*)d_in[13];
    const float* Eq = (const float*)d_in[14];
    const float* Ev = (const float*)d_in[15];
    float* out = (float*)d_out;

    cudaFuncSetAttribute(attn_kernel, cudaFuncAttributeMaxDynamicSharedMemorySize, SMEM_ATTN);
    cudaFuncSetAttribute(mma_gemm_kernel<0>, cudaFuncAttributeMaxDynamicSharedMemorySize, 2*GSTAGE);
    cudaFuncSetAttribute(mma_gemm_kernel<1>, cudaFuncAttributeMaxDynamicSharedMemorySize, 2*GSTAGE);

    __nv_bfloat16 *xhi, *xlo, *whi, *wlo;
    cudaGetSymbolAddress((void**)&xhi, g_xhi);
    cudaGetSymbolAddress((void**)&xlo, g_xlo);
    cudaGetSymbolAddress((void**)&whi, g_whi);
    cudaGetSymbolAddress((void**)&wlo, g_wlo);

    detect_kernel<<<1, 256>>>((const int*)arc);

    PrepArgs pa;
    const float* srcs[7] = {query, key_, value,
                            (const float*)d_in[5], (const float*)d_in[7],
                            (const float*)d_in[9], (const float*)d_in[11]};
    for (int i = 0; i < 7; i++) {
        pa.src[i] = srcs[i];
        if (i < 3) {
            pa.hi[i] = xhi + (size_t)i*XN;
            pa.lo[i] = xlo + (size_t)i*XN;
            pa.n[i]  = XN;
        } else {
            pa.hi[i] = whi + (size_t)(i-3)*WN;
            pa.lo[i] = wlo + (size_t)(i-3)*WN;
            pa.n[i]  = WN;
        }
    }
    pa.Ek = Ek; pa.Eq = Eq; pa.arc = arc;
    prep_kernel<<<dim3((XN/4 + 255)/256, 9), 256>>>(pa);

    dim3 qkvGrid(D_/BN, (B_*S_)/BM, 3);
    mma_gemm_kernel<0><<<qkvGrid, 256, 2*GSTAGE>>>(bq, bk, bv, nullptr);

    attn_kernel<<<dim3(S_/QT, H_, B_), 512, SMEM_ATTN>>>(mask, Ev);

    dim3 oGrid(D_/BN, (B_*S_)/BM, 1);
    mma_gemm_kernel<1><<<oGrid, 256, 2*GSTAGE>>>(bo, nullptr, nullptr, out);
}